// round 13
// baseline (speedup 1.0000x reference)
#include <cuda_runtime.h>
#include <cuda_bf16.h>
#include <cstdint>

typedef long long LL;

// ------------------------------- scratch ------------------------------------
__device__ float g_xb[7864320];   // [kb=k*4+b][t][n]   (reused as vg)
__device__ float g_q [7864320];   // [kb][t][128]       (reused as qg)
__device__ float g_k [7864320];   // [kb][t][128]       (reused as kg)
__device__ float g_v [3932160];   // [kb][t][64]
__device__ float g_S [62914560];  // o1 / o2 flash outputs (reuse)
__device__ float g_rs[491520];
__device__ float g_st[960];
__device__ float g_lam[120];
__device__ float g_ob[3932160];   // [kb][t][64]
__device__ float g_xm[7864320];   // [b][k][n][t]       (reused as og)
__device__ uint32_t g_wch[3735552]; // packed bf16-hi pairs, step-major per band
__device__ uint32_t g_wcl[3735552]; // packed bf16-lo pairs
__device__ uint32_t g_xp2[7864320]; // xm as (hi | lo<<16) packed bf16
__device__ float g_bc[3840];
__device__ float g_xg[7864320];   // [(b*512+t)*30+k][n]
__device__ float g_adj[900];

__device__ __forceinline__ void band_cfg(int k, int& taps, int& shift, LL& woff){
    if (k <= 5)      { taps=32; shift=5; woff = (LL)k*(16384*32); }
    else if (k <= 14){ taps=16; shift=4; woff = 6LL*(16384*32) + (LL)(k-6)*(16384*16); }
    else             { taps=8;  shift=3; woff = 6LL*(16384*32) + 9LL*(16384*16) + (LL)(k-15)*(16384*8); }
}

__device__ __forceinline__ void split2(float v0, float v1, uint32_t& hi, uint32_t& lo){
    __nv_bfloat16 h0 = __float2bfloat16_rn(v0);
    __nv_bfloat16 h1 = __float2bfloat16_rn(v1);
    float l0 = v0 - __bfloat162float(h0);
    float l1 = v1 - __bfloat162float(h1);
    hi = (uint32_t)__bfloat16_as_ushort(h0) | ((uint32_t)__bfloat16_as_ushort(h1) << 16);
    lo = (uint32_t)__bfloat16_as_ushort(__float2bfloat16_rn(l0))
       | ((uint32_t)__bfloat16_as_ushort(__float2bfloat16_rn(l1)) << 16);
}

#define MMA_BF16(d, a0,a1,a2,a3, b0,b1) \
    asm volatile("mma.sync.aligned.m16n8k16.row.col.f32.bf16.bf16.f32 " \
        "{%0,%1,%2,%3}, {%4,%5,%6,%7}, {%8,%9}, {%0,%1,%2,%3};" \
        : "+f"((d)[0]), "+f"((d)[1]), "+f"((d)[2]), "+f"((d)[3]) \
        : "r"(a0), "r"(a1), "r"(a2), "r"(a3), "r"(b0), "r"(b1))

// ------------------------- block reduce (128 thr) ---------------------------
__device__ __forceinline__ float bred(float v, float* sred, int op){
    #pragma unroll
    for (int o = 16; o; o >>= 1){
        float t = __shfl_xor_sync(0xffffffffu, v, o);
        v = (op==0) ? v+t : (op==1) ? fmaxf(v,t) : fminf(v,t);
    }
    if ((threadIdx.x & 31) == 0) sred[threadIdx.x >> 5] = v;
    __syncthreads();
    float r = (op==0) ? (sred[0]+sred[1])+(sred[2]+sred[3])
            : (op==1) ? fmaxf(fmaxf(sred[0],sred[1]),fmaxf(sred[2],sred[3]))
            :           fminf(fminf(sred[0],sred[1]),fminf(sred[2],sred[3]));
    __syncthreads();
    return r;
}

// ------------------------------ transpose x ---------------------------------
__global__ void transpose_x_kernel(const float* __restrict__ x, float* __restrict__ xb){
    __shared__ float s[128*31 + 32];
    int t = blockIdx.x, b = blockIdx.y;
    const float* src = x + (LL)b*1966080 + (LL)t*30;
    for (int i = threadIdx.x; i < 3840; i += 256){
        int n = i / 30, k = i - n*30;
        s[n*31 + k] = src[(LL)n*15360 + k];
    }
    __syncthreads();
    for (int i = threadIdx.x; i < 3840; i += 256){
        int k = i >> 7, n = i & 127;
        xb[((LL)(k*4 + b)*512 + t)*128 + n] = s[n*31 + k];
    }
}

// ---------- pipelined bf16-split tensor-core GEMM (128x128, B row-major) -----
__global__ void __launch_bounds__(256)
mgemm_p(const float* __restrict__ A, const float* __restrict__ Bm,
        const float* __restrict__ bias, float* __restrict__ C, int Kd, int inner,
        LL a_o, LL a_i, int lda,
        LL b_o, LL b_i, int ldb,
        LL c_o, LL c_i, int c_m, int c_n,
        int bias_stride, float alpha)
{
    extern __shared__ uint32_t smm[];
    uint32_t* Ah = smm;            // [2][1536]
    uint32_t* Al = smm + 3072;
    uint32_t* Bh = smm + 6144;
    uint32_t* Bl = smm + 9216;
    int z = blockIdx.z;
    int ko = z / inner, bi = z - ko*inner;
    const float* Ab = A + (LL)ko*a_o + (LL)bi*a_i;
    const float* Bb = Bm + (LL)ko*b_o + (LL)bi*b_i;
    float* Cb = C + (LL)ko*c_o + (LL)bi*c_i;
    int m0 = blockIdx.y * 128, n0 = blockIdx.x * 128;
    int tid = threadIdx.x, lane = tid & 31, wid = tid >> 5;
    int m0w = (wid >> 2) * 64, n0w = (wid & 3) * 32;
    int lr = lane >> 2, lc = lane & 3;

    float acc[4][4][4];
    #pragma unroll
    for (int i=0;i<4;i++)
        #pragma unroll
        for (int j=0;j<4;j++)
            #pragma unroll
            for (int q=0;q<4;q++) acc[i][j][q]=0.f;

    int am = tid >> 1, ak8 = (tid & 1) * 8;
    int n4 = (tid & 31) * 4, kp = tid >> 5;
    const int NSTEP = Kd >> 4;

    float va[8];
    float4 rb0, rb1;
    {   // prologue (st = 0)
        const float* ap = Ab + (LL)(m0 + am)*lda + ak8;
        *(float4*)&va[0] = *(const float4*)(ap);
        *(float4*)&va[4] = *(const float4*)(ap + 4);
        const float* bp = Bb + (LL)(kp*2)*ldb + n0 + n4;
        rb0 = *(const float4*)bp;
        rb1 = *(const float4*)(bp + ldb);
    }
    for (int st = 0; st < NSTEP; ++st){
        int buf = (st & 1) * 1536;
        int basea = buf + am*12 + (tid & 1)*4;
        #pragma unroll
        for (int j=0;j<4;j++){
            uint32_t hi, lo;
            split2(va[2*j], va[2*j+1], hi, lo);
            Ah[basea + j] = hi; Al[basea + j] = lo;
        }
        {
            float e0[4] = {rb0.x, rb0.y, rb0.z, rb0.w};
            float e1[4] = {rb1.x, rb1.y, rb1.z, rb1.w};
            #pragma unroll
            for (int j=0;j<4;j++){
                uint32_t hi, lo;
                split2(e0[j], e1[j], hi, lo);
                Bh[buf + (n4+j)*12 + kp] = hi;
                Bl[buf + (n4+j)*12 + kp] = lo;
            }
        }
        __syncthreads();
        if (st + 1 < NSTEP){
            int c = (st + 1) << 4;
            const float* ap = Ab + (LL)(m0 + am)*lda + c + ak8;
            *(float4*)&va[0] = *(const float4*)(ap);
            *(float4*)&va[4] = *(const float4*)(ap + 4);
            const float* bp = Bb + (LL)(c + kp*2)*ldb + n0 + n4;
            rb0 = *(const float4*)bp;
            rb1 = *(const float4*)(bp + ldb);
        }
        uint32_t bh[4][2], bl[4][2];
        #pragma unroll
        for (int nf = 0; nf < 4; ++nf){
            int r = buf + (n0w + nf*8 + lr) * 12 + lc;
            bh[nf][0] = Bh[r]; bh[nf][1] = Bh[r + 4];
            bl[nf][0] = Bl[r]; bl[nf][1] = Bl[r + 4];
        }
        #pragma unroll
        for (int mf = 0; mf < 4; ++mf){
            int r0 = buf + (m0w + mf*16 + lr) * 12 + lc;
            int r1 = r0 + 96;
            uint32_t ah0 = Ah[r0], ah1 = Ah[r1], ah2 = Ah[r0+4], ah3 = Ah[r1+4];
            uint32_t al0 = Al[r0], al1 = Al[r1], al2 = Al[r0+4], al3 = Al[r1+4];
            #pragma unroll
            for (int nf = 0; nf < 4; ++nf){
                MMA_BF16(acc[mf][nf], ah0,ah1,ah2,ah3, bh[nf][0], bh[nf][1]);
                MMA_BF16(acc[mf][nf], ah0,ah1,ah2,ah3, bl[nf][0], bl[nf][1]);
                MMA_BF16(acc[mf][nf], al0,al1,al2,al3, bh[nf][0], bh[nf][1]);
            }
        }
    }
    #pragma unroll
    for (int mf = 0; mf < 4; ++mf){
        int m = m0 + m0w + mf*16 + lr;
        #pragma unroll
        for (int nf = 0; nf < 4; ++nf){
            int n = n0 + n0w + nf*8 + lc*2;
            float b0 = bias ? bias[bias_stride*ko + n]   : 0.f;
            float b1 = bias ? bias[bias_stride*ko + n+1] : 0.f;
            Cb[(LL)m*c_m + (LL)n*c_n]         = fmaf(alpha, acc[mf][nf][0], b0);
            Cb[(LL)m*c_m + (LL)(n+1)*c_n]     = fmaf(alpha, acc[mf][nf][1], b1);
            Cb[(LL)(m+8)*c_m + (LL)n*c_n]     = fmaf(alpha, acc[mf][nf][2], b0);
            Cb[(LL)(m+8)*c_m + (LL)(n+1)*c_n] = fmaf(alpha, acc[mf][nf][3], b1);
        }
    }
}

// ------- fused triple projection, pipelined B: A split once, 3 weights -------
__global__ void __launch_bounds__(256)
proj3_kernel(const float* __restrict__ A, LL a_z,
             const float* __restrict__ W0, LL wz0,
             const float* __restrict__ W1, LL wz1,
             const float* __restrict__ W2, LL wz2,
             int kodiv,
             const float* __restrict__ b0, const float* __restrict__ b1,
             const float* __restrict__ b2,
             float* __restrict__ C0, LL cz0,
             float* __restrict__ C1, LL cz1,
             float* __restrict__ C2, LL cz2,
             int N2)
{
    extern __shared__ uint32_t smp[];
    uint32_t* Ah = smp;                 // [128][68]
    uint32_t* Al = Ah + 128*68;
    uint32_t* Bh = Al + 128*68;         // [2][1536]
    uint32_t* Bl = Bh + 3072;

    int z = blockIdx.y;
    int ko = z / kodiv;
    int tile = blockIdx.x;
    const float* Ab = A + (LL)z*a_z + (LL)tile*16384;
    int tid = threadIdx.x, lane = tid & 31, wid = tid >> 5;
    int m0w = (wid >> 2) * 64, n0w = (wid & 3) * 32;
    int lr = lane >> 2, lc = lane & 3;

    // ---- stage full A tile (split once): 2 threads/row, 64 floats each ----
    {
        int am = tid >> 1, koff = (tid & 1) * 64;
        const float* ap = Ab + (LL)am*128 + koff;
        int base = am*68 + (tid & 1)*32;
        #pragma unroll
        for (int g = 0; g < 8; ++g){
            float4 f0 = *(const float4*)(ap + g*8);
            float4 f1 = *(const float4*)(ap + g*8 + 4);
            float v[8] = {f0.x,f0.y,f0.z,f0.w,f1.x,f1.y,f1.z,f1.w};
            #pragma unroll
            for (int j = 0; j < 4; ++j){
                uint32_t hi, lo;
                split2(v[2*j], v[2*j+1], hi, lo);
                Ah[base + g*4 + j] = hi;
                Al[base + g*4 + j] = lo;
            }
        }
    }
    __syncthreads();

    const float* Ws[3] = {W0 + (LL)ko*wz0, W1 + (LL)ko*wz1, W2 + (LL)ko*wz2};
    const float* bs[3] = {b0, b1, b2};
    float* Cs[3];
    Cs[0] = C0 + (LL)z*cz0 + (LL)tile*16384;
    Cs[1] = C1 + (LL)z*cz1 + (LL)tile*16384;
    Cs[2] = C2 + (LL)z*cz2 + (LL)tile*128*N2;
    int Ns[3] = {128, 128, N2};
    int n4 = (tid & 31) * 4, kp = tid >> 5;

    for (int w = 0; w < 3; ++w){
        const float* Wb = Ws[w];
        int Nw = Ns[w];
        bool act = n4 < Nw;
        float acc[4][4][4];
        #pragma unroll
        for (int i=0;i<4;i++)
            #pragma unroll
            for (int j=0;j<4;j++)
                #pragma unroll
                for (int q=0;q<4;q++) acc[i][j][q]=0.f;

        float4 r0, r1;
        if (act){
            const float* bp0 = Wb + (LL)(kp*2)*Nw + n4;
            r0 = *(const float4*)bp0;
            r1 = *(const float4*)(bp0 + Nw);
        }
        for (int st = 0; st < 8; ++st){
            int buf = (st & 1) * 1536;
            if (act){
                float e0[4] = {r0.x, r0.y, r0.z, r0.w};
                float e1[4] = {r1.x, r1.y, r1.z, r1.w};
                #pragma unroll
                for (int j = 0; j < 4; ++j){
                    uint32_t hi, lo;
                    split2(e0[j], e1[j], hi, lo);
                    Bh[buf + (n4+j)*12 + kp] = hi;
                    Bl[buf + (n4+j)*12 + kp] = lo;
                }
            }
            __syncthreads();
            if (st < 7 && act){
                int c = (st + 1) << 4;
                const float* bp0 = Wb + (LL)(c + kp*2)*Nw + n4;
                r0 = *(const float4*)bp0;
                r1 = *(const float4*)(bp0 + Nw);
            }
            uint32_t bh[4][2], bl[4][2];
            #pragma unroll
            for (int nf = 0; nf < 4; ++nf){
                int r = buf + (n0w + nf*8 + lr) * 12 + lc;
                bh[nf][0] = Bh[r]; bh[nf][1] = Bh[r + 4];
                bl[nf][0] = Bl[r]; bl[nf][1] = Bl[r + 4];
            }
            #pragma unroll
            for (int mf = 0; mf < 4; ++mf){
                int ra = (m0w + mf*16 + lr)*68 + st*8 + lc;
                uint32_t ah0 = Ah[ra], ah1 = Ah[ra + 544], ah2 = Ah[ra+4], ah3 = Ah[ra+548];
                uint32_t al0 = Al[ra], al1 = Al[ra + 544], al2 = Al[ra+4], al3 = Al[ra+548];
                #pragma unroll
                for (int nf = 0; nf < 4; ++nf){
                    MMA_BF16(acc[mf][nf], ah0,ah1,ah2,ah3, bh[nf][0], bh[nf][1]);
                    MMA_BF16(acc[mf][nf], ah0,ah1,ah2,ah3, bl[nf][0], bl[nf][1]);
                    MMA_BF16(acc[mf][nf], al0,al1,al2,al3, bh[nf][0], bh[nf][1]);
                }
            }
        }
        const float* bw = bs[w];
        float* Cw = Cs[w];
        #pragma unroll
        for (int mf = 0; mf < 4; ++mf){
            int m = m0w + mf*16 + lr;
            #pragma unroll
            for (int nf = 0; nf < 4; ++nf){
                int n = n0w + nf*8 + lc*2;
                if (n < Nw){
                    float bb0 = bw ? bw[n]   : 0.f;
                    float bb1 = bw ? bw[n+1] : 0.f;
                    Cw[(LL)m*Nw + n]       = acc[mf][nf][0] + bb0;
                    Cw[(LL)m*Nw + n+1]     = acc[mf][nf][1] + bb1;
                    Cw[(LL)(m+8)*Nw + n]   = acc[mf][nf][2] + bb0;
                    Cw[(LL)(m+8)*Nw + n+1] = acc[mf][nf][3] + bb1;
                }
            }
        }
        __syncthreads();
    }
}

// ------------- flash-fused scores + online softmax/stats + AV ----------------
// grid (4 row-blocks, 120 kb, 2 half), 128 threads (4 warps x 32 rows).
__global__ void __launch_bounds__(128)
flash_kernel(const float* __restrict__ qg, const float* __restrict__ kg,
             const float* __restrict__ vg, float* __restrict__ o1,
             float* __restrict__ o2, float* __restrict__ rs)
{
    extern __shared__ uint32_t sm[];
    uint32_t* Qh = sm;              // [128][36]
    uint32_t* Ql = Qh + 4608;
    uint32_t* Kh = Ql + 4608;       // [32][36]
    uint32_t* Kl = Kh + 1152;
    uint32_t* Vh = Kl + 1152;       // [64][20]
    uint32_t* Vl = Vh + 1280;

    int kb = blockIdx.y, half = blockIdx.z;
    int row0 = blockIdx.x * 128;
    const float* qb  = qg + (LL)kb*65536 + half*64;
    const float* kp_ = kg + (LL)kb*65536 + half*64;
    const float* vb  = vg + (LL)kb*32768;
    int tid = threadIdx.x, lane = tid & 31, wid = tid >> 5;
    int m0w = wid * 32;
    int lr = lane >> 2, lc = lane & 3;

    // stage Q block once
    {
        const float* qr = qb + (LL)(row0 + tid)*128;
        #pragma unroll
        for (int g = 0; g < 16; ++g){
            float4 f = *(const float4*)(qr + g*4);
            uint32_t h0,l0,h1,l1;
            split2(f.x, f.y, h0, l0);
            split2(f.z, f.w, h1, l1);
            int p = tid*36 + g*2;
            Qh[p] = h0; Ql[p] = l0; Qh[p+1] = h1; Ql[p+1] = l1;
        }
    }

    float m2[2][2], dn[2][2], qq[2][2], vmn[2][2];
    #pragma unroll
    for (int a=0;a<2;a++)
        #pragma unroll
        for (int b2=0;b2<2;b2++){ m2[a][b2]=-1e30f; dn[a][b2]=0.f; qq[a][b2]=0.f; vmn[a][b2]=1e30f; }
    float o[2][8][4];
    #pragma unroll
    for (int a=0;a<2;a++)
        #pragma unroll
        for (int b2=0;b2<8;b2++)
            #pragma unroll
            for (int cql=0;cql<4;cql++) o[a][b2][cql]=0.f;

    for (int jt = 0; jt < 512; jt += 32){
        __syncthreads();
        // K chunk: [32 cols j][pairs over d]
        {
            int j = tid >> 2, ds = (tid & 3) * 16;
            const float* kr = kp_ + (LL)(jt + j)*128 + ds;
            #pragma unroll
            for (int g = 0; g < 4; ++g){
                float4 f = *(const float4*)(kr + g*4);
                uint32_t h0,l0,h1,l1;
                split2(f.x,f.y,h0,l0); split2(f.z,f.w,h1,l1);
                int p = j*36 + (ds>>1) + g*2;
                Kh[p]=h0; Kl[p]=l0; Kh[p+1]=h1; Kl[p+1]=l1;
            }
        }
        // V chunk transposed: [64 d][pairs over j]
        {
            int jp = tid & 15, ds = (tid >> 4) * 8;
            const float* v0 = vb + (LL)(jt + jp*2)*64 + ds;
            #pragma unroll
            for (int g = 0; g < 8; ++g){
                uint32_t h,l;
                split2(v0[g], v0[64+g], h, l);
                Vh[(ds+g)*20 + jp] = h; Vl[(ds+g)*20 + jp] = l;
            }
        }
        __syncthreads();
        // ---- scores 32x32 per warp ----
        float s[2][4][4];
        #pragma unroll
        for (int a=0;a<2;a++)
            #pragma unroll
            for (int b2=0;b2<4;b2++)
                #pragma unroll
                for (int cql=0;cql<4;cql++) s[a][b2][cql]=0.f;
        #pragma unroll
        for (int kc = 0; kc < 4; ++kc){
            #pragma unroll
            for (int mf = 0; mf < 2; ++mf){
                int ra = (m0w + mf*16 + lr)*36 + kc*8 + lc;
                uint32_t ah0=Qh[ra], ah1=Qh[ra+288], ah2=Qh[ra+4], ah3=Qh[ra+292];
                uint32_t al0=Ql[ra], al1=Ql[ra+288], al2=Ql[ra+4], al3=Ql[ra+292];
                #pragma unroll
                for (int nf = 0; nf < 4; ++nf){
                    int rb = (nf*8 + lr)*36 + kc*8 + lc;
                    uint32_t bh0=Kh[rb], bh1=Kh[rb+4];
                    uint32_t bl0=Kl[rb], bl1=Kl[rb+4];
                    MMA_BF16(s[mf][nf], ah0,ah1,ah2,ah3, bh0,bh1);
                    MMA_BF16(s[mf][nf], ah0,ah1,ah2,ah3, bl0,bl1);
                    MMA_BF16(s[mf][nf], al0,al1,al2,al3, bh0,bh1);
                }
            }
        }
        // ---- online softmax update (alpha=0.25), ballot-gated rescale ----
        #pragma unroll
        for (int mf = 0; mf < 2; ++mf){
            #pragma unroll
            for (int rh = 0; rh < 2; ++rh){
                float cmax = -1e30f, cmin = 1e30f;
                #pragma unroll
                for (int nf = 0; nf < 4; ++nf){
                    float e0 = s[mf][nf][rh*2]   * 0.25f;
                    float e1 = s[mf][nf][rh*2+1] * 0.25f;
                    s[mf][nf][rh*2] = e0; s[mf][nf][rh*2+1] = e1;
                    cmax = fmaxf(cmax, fmaxf(e0,e1));
                    cmin = fminf(cmin, fminf(e0,e1));
                }
                cmax = fmaxf(cmax, __shfl_xor_sync(0xffffffffu, cmax, 1));
                cmax = fmaxf(cmax, __shfl_xor_sync(0xffffffffu, cmax, 2));
                cmin = fminf(cmin, __shfl_xor_sync(0xffffffffu, cmin, 1));
                cmin = fminf(cmin, __shfl_xor_sync(0xffffffffu, cmin, 2));
                float mold = m2[mf][rh];
                float mnew = fmaxf(mold, cmax);
                bool upd = (mnew > mold);
                float rsum = 0.f, rsq = 0.f;
                #pragma unroll
                for (int nf = 0; nf < 4; ++nf){
                    float p0 = __expf(s[mf][nf][rh*2]   - mnew);
                    float p1 = __expf(s[mf][nf][rh*2+1] - mnew);
                    s[mf][nf][rh*2] = p0; s[mf][nf][rh*2+1] = p1;
                    rsum += p0 + p1;
                    rsq  += p0*p0 + p1*p1;
                }
                rsum += __shfl_xor_sync(0xffffffffu, rsum, 1);
                rsum += __shfl_xor_sync(0xffffffffu, rsum, 2);
                rsq  += __shfl_xor_sync(0xffffffffu, rsq, 1);
                rsq  += __shfl_xor_sync(0xffffffffu, rsq, 2);
                if (__any_sync(0xffffffffu, upd)){
                    float scale = __expf(mold - mnew);   // ==1 for lanes w/o update
                    dn[mf][rh] = dn[mf][rh]*scale + rsum;
                    qq[mf][rh] = qq[mf][rh]*scale*scale + rsq;
                    m2[mf][rh] = mnew;
                    #pragma unroll
                    for (int nfd = 0; nfd < 8; ++nfd){
                        o[mf][nfd][rh*2]   *= scale;
                        o[mf][nfd][rh*2+1] *= scale;
                    }
                } else {
                    dn[mf][rh] += rsum;
                    qq[mf][rh] += rsq;
                }
                vmn[mf][rh] = fminf(vmn[mf][rh], cmin);
            }
        }
        // ---- AV: P (register frags) @ V ----
        #pragma unroll
        for (int mf = 0; mf < 2; ++mf){
            #pragma unroll
            for (int kc2 = 0; kc2 < 2; ++kc2){
                uint32_t ah0,al0,ah1,al1,ah2,al2,ah3,al3;
                split2(s[mf][2*kc2][0],   s[mf][2*kc2][1],   ah0, al0);
                split2(s[mf][2*kc2][2],   s[mf][2*kc2][3],   ah1, al1);
                split2(s[mf][2*kc2+1][0], s[mf][2*kc2+1][1], ah2, al2);
                split2(s[mf][2*kc2+1][2], s[mf][2*kc2+1][3], ah3, al3);
                #pragma unroll
                for (int nfd = 0; nfd < 8; ++nfd){
                    int rb = (nfd*8 + lr)*20 + kc2*8 + lc;
                    uint32_t bh0=Vh[rb], bh1=Vh[rb+4];
                    uint32_t bl0=Vl[rb], bl1=Vl[rb+4];
                    MMA_BF16(o[mf][nfd], ah0,ah1,ah2,ah3, bh0,bh1);
                    MMA_BF16(o[mf][nfd], ah0,ah1,ah2,ah3, bl0,bl1);
                    MMA_BF16(o[mf][nfd], al0,al1,al2,al3, bh0,bh1);
                }
            }
        }
    }
    // ---- finalize: normalize, write o + per-row stats ----
    float* op = (half == 0 ? o1 : o2) + (LL)kb*32768;
    #pragma unroll
    for (int mf = 0; mf < 2; ++mf){
        #pragma unroll
        for (int rh = 0; rh < 2; ++rh){
            float inv = 1.f / dn[mf][rh];
            int r = row0 + m0w + mf*16 + lr + rh*8;
            #pragma unroll
            for (int nfd = 0; nfd < 8; ++nfd){
                o[mf][nfd][rh*2]   *= inv;
                o[mf][nfd][rh*2+1] *= inv;
            }
            if (lc == 0){
                float* rp = rs + ((LL)(half*120 + kb)*512 + r)*4;
                rp[0] = 1.0f;
                rp[1] = qq[mf][rh]*inv*inv;
                rp[2] = inv;
                rp[3] = __expf(vmn[mf][rh] - m2[mf][rh]) * inv;
            }
            float* orow = op + (LL)r*64 + lc*2;
            #pragma unroll
            for (int nfd = 0; nfd < 8; ++nfd){
                orow[nfd*8]   = o[mf][nfd][rh*2];
                orow[nfd*8+1] = o[mf][nfd][rh*2+1];
            }
        }
    }
}

// --------------------------- ob = o1 - lam*o2 --------------------------------
__global__ void combine_kernel(const float* __restrict__ o1, const float* __restrict__ o2,
                               const float* __restrict__ lam, float* __restrict__ ob){
    int i = blockIdx.x*256 + threadIdx.x;   // float4 index, 983040 total
    int kb = i >> 13;
    float l = lam[kb];
    float4 a = ((const float4*)o1)[i];
    float4 c = ((const float4*)o2)[i];
    a.x = fmaf(-l, c.x, a.x); a.y = fmaf(-l, c.y, a.y);
    a.z = fmaf(-l, c.z, a.z); a.w = fmaf(-l, c.w, a.w);
    ((float4*)ob)[i] = a;
}

// --------------------- per-(half,kb) stat aggregation ------------------------
__global__ void stats_finalize_kernel(const float* __restrict__ rs, float* __restrict__ st){
    __shared__ float sred[4];
    int hb = blockIdx.x;
    const float* r = rs + (LL)hb*512*4;
    int tid = threadIdx.x;
    float s=0.f,q=0.f,mx=-1e30f,mn=1e30f;
    for (int i = tid; i < 512; i += 128){
        s += r[i*4+0]; q += r[i*4+1];
        mx = fmaxf(mx, r[i*4+2]); mn = fminf(mn, r[i*4+3]);
    }
    s = bred(s,sred,0); q = bred(q,sred,0);
    mx = bred(mx,sred,1); mn = bred(mn,sred,2);
    if (tid == 0){
        float* o = st + hb*4;
        o[0]=s; o[1]=q; o[2]=mx; o[3]=mn;
    }
}

// ------------------------------- lambda MLP ---------------------------------
__global__ void lambda_kernel(const float* __restrict__ st,
                              const float* __restrict__ lw1, const float* __restrict__ lb1,
                              const float* __restrict__ lw2, const float* __restrict__ lb2,
                              float* __restrict__ lam){
    int kb = threadIdx.x;
    if (kb >= 120) return;
    int k = kb >> 2;
    const float M2 = 262144.f;
    float s8[8];
    #pragma unroll
    for (int h2 = 0; h2 < 2; ++h2){
        const float* sp = st + (h2*120 + kb)*4;
        float sum = sp[0], sq = sp[1];
        s8[h2*4+0] = sum / M2;
        float var = (sq - sum*sum/M2) / (M2 - 1.f);
        s8[h2*4+1] = sqrtf(fmaxf(var, 0.f));
        s8[h2*4+2] = sp[2];
        s8[h2*4+3] = sp[3];
    }
    float z = lb2[k];
    for (int o = 0; o < 16; ++o){
        float h = lb1[k*16+o];
        #pragma unroll
        for (int i = 0; i < 8; ++i) h = fmaf(s8[i], lw1[(k*8+i)*16+o], h);
        h = fmaxf(h, 0.f);
        z = fmaf(h, lw2[k*16+o], z);
    }
    lam[kb] = 1.f/(1.f + expf(-z));
}

// ------------- combined multiscale conv weights -> packed bf16 hi/lo ---------
__global__ void combine_wc_kernel(const float* __restrict__ fw,
    const float* cwA, const float* cwB, const float* cwC, const float* cwD, const float* cwE,
    const float* cbA, const float* cbB, const float* cbC, const float* cbD, const float* cbE,
    uint32_t* __restrict__ wch, uint32_t* __restrict__ wcl, float* __restrict__ bc){
    int idx = blockIdx.x*256 + threadIdx.x;
    if (idx >= 491520) return;
    int k = idx >> 14;
    int rem = idx & 16383;
    int n = rem >> 7, m = rem & 127;
    int base = (k <= 5) ? 2 : (k <= 14) ? 1 : 0;
    int taps, shift; LL woff;
    band_cfg(k, taps, shift, woff);
    int half = taps >> 1;
    float f0 = fw[k*3+0], f1 = fw[k*3+1], f2 = fw[k*3+2];
    float fm = fmaxf(f0, fmaxf(f1, f2));
    float e0 = expf(f0-fm), e1 = expf(f1-fm), e2 = expf(f2-fm);
    float den = e0+e1+e2;
    float sw[3] = {e0/den, e1/den, e2/den};
    const float* cws[5] = {cwA,cwB,cwC,cwD,cwE};
    const float* cbs[5] = {cbA,cbB,cbC,cbD,cbE};
    const int ss[5] = {2,4,8,16,32};
    LL wp = woff >> 1;
    float prev = 0.f;
    for (int u = 0; u < taps; ++u){
        int tau = u - half;
        float a = 0.f;
        #pragma unroll
        for (int j = 0; j < 3; ++j){
            int slot = base + j;
            int sc = ss[slot], h2 = sc >> 1;
            if (tau >= -h2 && tau < h2)
                a = fmaf(sw[j], cws[slot][((LL)n*128 + m)*sc + tau + h2], a);
        }
        if ((u & 1) == 0) prev = a;
        else {
            uint32_t hi, lo;
            split2(prev, a, hi, lo);
            int kk = m*taps + u - 1;
            int stp = kk >> 4;
            int kp = (kk >> 1) & 7;
            LL widx = wp + (LL)stp*1024 + n*8 + kp;
            wch[widx] = hi; wcl[widx] = lo;
        }
    }
    if (m == 0){
        float bcv = 0.f;
        #pragma unroll
        for (int j = 0; j < 3; ++j) bcv = fmaf(sw[j], cbs[base+j][n], bcv);
        bc[k*128+n] = bcv;
    }
}

// ------------------------ pack xm into bf16 hi|lo words ----------------------
__global__ void pack_x_kernel(const float* __restrict__ xm, uint32_t* __restrict__ xp2){
    int i = blockIdx.x*256 + threadIdx.x;
    float4 v = ((const float4*)xm)[i];
    float vv[4] = {v.x, v.y, v.z, v.w};
    uint32_t w[4];
    #pragma unroll
    for (int j = 0; j < 4; ++j){
        __nv_bfloat16 h = __float2bfloat16_rn(vv[j]);
        float l = vv[j] - __bfloat162float(h);
        w[j] = (uint32_t)__bfloat16_as_ushort(h)
             | ((uint32_t)__bfloat16_as_ushort(__float2bfloat16_rn(l)) << 16);
    }
    ((uint4*)xp2)[i] = make_uint4(w[0], w[1], w[2], w[3]);
}

// -------- pipelined mma.sync bf16 (3-term split) im2col conv -----------------
// z scrambled for heavy-band SM balance: z = (zraw*49) % 120.
__global__ void __launch_bounds__(256)
convgemm_mma(const uint32_t* __restrict__ wch, const uint32_t* __restrict__ wcl,
             const float* __restrict__ bc, const uint32_t* __restrict__ xp2,
             float* __restrict__ xg)
{
    extern __shared__ uint32_t smc[];
    uint32_t* Ah = smc;            // [2][1536]
    uint32_t* Al = smc + 3072;
    uint32_t* Bh = smc + 6144;
    uint32_t* Bl = smc + 9216;
    int z = (int)((blockIdx.y * 49u) % 120u);
    int b = z / 30, k = z - b*30;
    int taps, shift; LL woff;
    band_cfg(k, taps, shift, woff);
    const int NC = taps << 3;
    const int half = taps >> 1;
    const int mask = taps - 1;
    const uint32_t* Abh = wch + (woff >> 1);
    const uint32_t* Abl = wcl + (woff >> 1);
    const uint32_t* xpz = xp2 + (LL)z*65536;
    int t0 = blockIdx.x * 128;
    int tid = threadIdx.x;
    int lane = tid & 31, wid = tid >> 5;
    int m0w = (wid >> 2) * 64, n0w = (wid & 3) * 32;
    int lr = lane >> 2, lc = lane & 3;

    float acc[4][4][4];
    #pragma unroll
    for (int i=0;i<4;i++)
        #pragma unroll
        for (int j=0;j<4;j++)
            #pragma unroll
            for (int q=0;q<4;q++) acc[i][j][q]=0.f;

    int am = tid >> 1, akp = (tid & 1) * 4;
    int bkp = tid & 7, btq = tid >> 3;

    uint4 a4h, a4l;
    uint32_t bhv[4], blv[4];
    // prologue load st=0
    {
        a4h = *(const uint4*)(Abh + tid*4);
        a4l = *(const uint4*)(Abl + tid*4);
        int kk = bkp*2;
        int mi = kk >> shift, u0 = kk & mask;
        const uint32_t* src = xpz + (LL)mi*512;
        int off = u0 - half;
        #pragma unroll
        for (int i = 0; i < 4; ++i){
            int t = btq*4 + i;
            int p0 = t0 + t + off;
            uint32_t w0 = ((unsigned)p0 < 512u) ? src[p0] : 0u;
            uint32_t w1 = ((unsigned)(p0+1) < 512u) ? src[p0+1] : 0u;
            bhv[i] = __byte_perm(w0, w1, 0x5410);
            blv[i] = __byte_perm(w0, w1, 0x7632);
        }
    }
    for (int st = 0; st < NC; ++st){
        int buf = (st & 1) * 1536;
        *(uint4*)&Ah[buf + am*12 + akp] = a4h;
        *(uint4*)&Al[buf + am*12 + akp] = a4l;
        #pragma unroll
        for (int i = 0; i < 4; ++i){
            int t = btq*4 + i;
            Bh[buf + t*12 + bkp] = bhv[i];
            Bl[buf + t*12 + bkp] = blv[i];
        }
        __syncthreads();
        if (st + 1 < NC){
            int stn = st + 1;
            a4h = *(const uint4*)(Abh + (LL)stn*1024 + tid*4);
            a4l = *(const uint4*)(Abl + (LL)stn*1024 + tid*4);
            int kk = (stn << 4) + bkp*2;
            int mi = kk >> shift, u0 = kk & mask;
            const uint32_t* src = xpz + (LL)mi*512;
            int off = u0 - half;
            #pragma unroll
            for (int i = 0; i < 4; ++i){
                int t = btq*4 + i;
                int p0 = t0 + t + off;
                uint32_t w0 = ((unsigned)p0 < 512u) ? src[p0] : 0u;
                uint32_t w1 = ((unsigned)(p0+1) < 512u) ? src[p0+1] : 0u;
                bhv[i] = __byte_perm(w0, w1, 0x5410);
                blv[i] = __byte_perm(w0, w1, 0x7632);
            }
        }
        uint32_t bh[4][2], bl[4][2];
        #pragma unroll
        for (int nf = 0; nf < 4; ++nf){
            int r = buf + (n0w + nf*8 + lr) * 12 + lc;
            bh[nf][0] = Bh[r]; bh[nf][1] = Bh[r + 4];
            bl[nf][0] = Bl[r]; bl[nf][1] = Bl[r + 4];
        }
        #pragma unroll
        for (int mf = 0; mf < 4; ++mf){
            int r0 = buf + (m0w + mf*16 + lr) * 12 + lc;
            int r1 = r0 + 96;
            uint32_t ah0 = Ah[r0], ah1 = Ah[r1], ah2 = Ah[r0+4], ah3 = Ah[r1+4];
            uint32_t al0 = Al[r0], al1 = Al[r1], al2 = Al[r0+4], al3 = Al[r1+4];
            #pragma unroll
            for (int nf = 0; nf < 4; ++nf){
                MMA_BF16(acc[mf][nf], ah0,ah1,ah2,ah3, bh[nf][0], bh[nf][1]);
                MMA_BF16(acc[mf][nf], ah0,ah1,ah2,ah3, bl[nf][0], bl[nf][1]);
                MMA_BF16(acc[mf][nf], al0,al1,al2,al3, bh[nf][0], bh[nf][1]);
            }
        }
    }
    #pragma unroll
    for (int mf = 0; mf < 4; ++mf){
        int m = m0w + mf*16 + lr;
        float bc0 = bc[k*128 + m];
        float bc1 = bc[k*128 + m + 8];
        #pragma unroll
        for (int nf = 0; nf < 4; ++nf){
            int t = t0 + n0w + nf*8 + lc*2;
            LL base = ((LL)((b*512 + t)*30 + k)) * 128;
            xg[base + m]          = acc[mf][nf][0] + bc0;
            xg[base + 3840 + m]   = acc[mf][nf][1] + bc0;
            xg[base + m + 8]      = acc[mf][nf][2] + bc1;
            xg[base + 3840 + m+8] = acc[mf][nf][3] + bc1;
        }
    }
}

// ------------------------------- adjacency ----------------------------------
__global__ void adj_kernel(const float* __restrict__ be, float* __restrict__ adj){
    __shared__ float e[30][64];
    __shared__ float sim[30][30];
    __shared__ float Ar[30][30];
    int tid = threadIdx.x;
    for (int i = tid; i < 30; i += 256){
        float s = 0.f;
        for (int d = 0; d < 64; ++d){ float v = be[i*64+d]; s += v*v; }
        float inv = 1.f/(sqrtf(s)+1e-8f);
        for (int d = 0; d < 64; ++d) e[i][d] = be[i*64+d]*inv;
    }
    __syncthreads();
    for (int p = tid; p < 900; p += 256){
        int i = p/30, j = p - (p/30)*30;
        float s = 0.f;
        for (int d = 0; d < 64; ++d) s = fmaf(e[i][d], e[j][d], s);
        sim[i][j] = s; Ar[i][j] = 0.f;
    }
    __syncthreads();
    if (tid < 30){
        bool taken[30];
        for (int j = 0; j < 30; ++j) taken[j] = false;
        for (int r = 0; r < 5; ++r){
            int bi = 0; float bvv = -1e30f;
            for (int j = 0; j < 30; ++j)
                if (!taken[j] && sim[tid][j] > bvv){ bvv = sim[tid][j]; bi = j; }
            taken[bi] = true;
            Ar[tid][bi] = bvv;
        }
    }
    __syncthreads();
    for (int p = tid; p < 900; p += 256){
        int i = p/30, j = p - (p/30)*30;
        adj[p] = 0.5f*(Ar[i][j] + Ar[j][i]);
    }
}

// --------------------------- graph attention core ---------------------------
__global__ void gattn_kernel(const float* __restrict__ qg, const float* __restrict__ kg,
                             const float* __restrict__ vg, const float* __restrict__ adj,
                             float* __restrict__ outp){
    __shared__ float sq[4][30][32];
    __shared__ float sv[4][30][32];
    __shared__ float sadj[30][30];
    __shared__ float sat[4][32];
    LL m = blockIdx.x;
    int tid = threadIdx.x, h = tid >> 5, lane = tid & 31;
    for (int i = tid; i < 3840; i += 128){
        int r = i >> 7, c = i & 127;
        sq[c>>5][r][c&31] = qg[m*3840 + i];
        sv[c>>5][r][c&31] = vg[m*3840 + i];
    }
    for (int i = tid; i < 900; i += 128) sadj[i/30][i - (i/30)*30] = adj[i];
    float kreg[32];
    if (lane < 30){
        #pragma unroll
        for (int d = 0; d < 32; ++d) kreg[d] = kg[m*3840 + lane*128 + h*32 + d];
    } else {
        #pragma unroll
        for (int d = 0; d < 32; ++d) kreg[d] = 0.f;
    }
    __syncthreads();
    const float invs = 0.17677669529663687f;
    float* orow = outp + m*3840;
    for (int i = 0; i < 30; ++i){
        float qv = sq[h][i][lane];
        float d = 0.f;
        #pragma unroll
        for (int dd = 0; dd < 32; ++dd)
            d = fmaf(__shfl_sync(0xffffffffu, qv, dd), kreg[dd], d);
        bool valid = (lane < 30) && (sadj[i][lane] != 0.f);
        float sc = valid ? d*invs : -1e30f;
        float mx = sc;
        #pragma unroll
        for (int o=16;o;o>>=1) mx = fmaxf(mx, __shfl_xor_sync(0xffffffffu, mx, o));
        float e = valid ? expf(sc - mx) : 0.f;
        float s = e;
        #pragma unroll
        for (int o=16;o;o>>=1) s += __shfl_xor_sync(0xffffffffu, s, o);
        float at = (s > 0.f) ? e/s : 0.f;
        sat[h][lane] = at;
        __syncwarp();
        float o = 0.f;
        for (int j = 0; j < 30; ++j) o = fmaf(sat[h][j], sv[h][j][lane], o);
        orow[i*128 + h*32 + lane] = o;
        __syncwarp();
    }
}

// ------------------------------ output transpose -----------------------------
__global__ void transpose_out_kernel(const float* __restrict__ og, float* __restrict__ out){
    __shared__ float s[30*129 + 32];
    int t = blockIdx.x, b = blockIdx.y;
    const float* src = og + (LL)(b*512 + t)*3840;
    for (int i = threadIdx.x; i < 3840; i += 256){
        int k = i >> 7, n = i & 127;
        s[k*129 + n] = src[i];
    }
    __syncthreads();
    float* dst = out + (LL)b*1966080 + (LL)t*30;
    for (int i = threadIdx.x; i < 3840; i += 256){
        int n = i / 30, k = i - n*30;
        dst[(LL)n*15360 + k] = s[k*129 + n];
    }
}

// ----------------------------------- launch ----------------------------------
extern "C" void kernel_launch(void* const* d_in, const int* in_sizes, int n_in,
                              void* d_out, int out_size) {
    const float* x   = (const float*)d_in[0];
    const float* Wq  = (const float*)d_in[1];
    const float* Wk  = (const float*)d_in[2];
    const float* Wv  = (const float*)d_in[3];
    const float* Wo  = (const float*)d_in[4];
    const float* bo  = (const float*)d_in[5];
    const float* lw1 = (const float*)d_in[6];
    const float* lb1 = (const float*)d_in[7];
    const float* lw2 = (const float*)d_in[8];
    const float* lb2 = (const float*)d_in[9];
    const float* cw2 = (const float*)d_in[10];
    const float* cb2 = (const float*)d_in[11];
    const float* cw4 = (const float*)d_in[12];
    const float* cb4 = (const float*)d_in[13];
    const float* cw8 = (const float*)d_in[14];
    const float* cb8 = (const float*)d_in[15];
    const float* cw16= (const float*)d_in[16];
    const float* cb16= (const float*)d_in[17];
    const float* cw32= (const float*)d_in[18];
    const float* cb32= (const float*)d_in[19];
    const float* fw  = (const float*)d_in[20];
    const float* be  = (const float*)d_in[21];
    const float* gWq = (const float*)d_in[22];
    const float* gbq = (const float*)d_in[23];
    const float* gWk = (const float*)d_in[24];
    const float* gbk = (const float*)d_in[25];
    const float* gWv = (const float*)d_in[26];
    const float* gbv = (const float*)d_in[27];
    const float* gWo = (const float*)d_in[28];
    const float* gbo = (const float*)d_in[29];
    float* out = (float*)d_out;

    void *xb,*q,*k_,*v,*S,*rs,*st,*lam,*ob,*xm,*wch,*wcl,*xp2,*bc,*xg,*adj;
    cudaGetSymbolAddress(&xb, g_xb);  cudaGetSymbolAddress(&q,  g_q);
    cudaGetSymbolAddress(&k_, g_k);   cudaGetSymbolAddress(&v,  g_v);
    cudaGetSymbolAddress(&S,  g_S);   cudaGetSymbolAddress(&rs, g_rs);
    cudaGetSymbolAddress(&st, g_st);  cudaGetSymbolAddress(&lam,g_lam);
    cudaGetSymbolAddress(&ob, g_ob);  cudaGetSymbolAddress(&xm, g_xm);
    cudaGetSymbolAddress(&wch,g_wch); cudaGetSymbolAddress(&wcl,g_wcl);
    cudaGetSymbolAddress(&xp2,g_xp2); cudaGetSymbolAddress(&bc, g_bc);
    cudaGetSymbolAddress(&xg, g_xg);  cudaGetSymbolAddress(&adj,g_adj);

    float* o1 = (float*)S;
    float* o2 = (float*)S + 3932160;

    cudaFuncSetAttribute(flash_kernel, cudaFuncAttributeMaxDynamicSharedMemorySize, 57344);
    cudaFuncSetAttribute(proj3_kernel, cudaFuncAttributeMaxDynamicSharedMemorySize, 94208);
    cudaFuncSetAttribute(mgemm_p, cudaFuncAttributeMaxDynamicSharedMemorySize, 49152);
    cudaFuncSetAttribute(convgemm_mma, cudaFuncAttributeMaxDynamicSharedMemorySize, 49152);

    transpose_x_kernel<<<dim3(512,4), 256>>>(x, (float*)xb);
    combine_wc_kernel<<<1920, 256>>>(fw, cw2,cw4,cw8,cw16,cw32,
                                     cb2,cb4,cb8,cb16,cb32,
                                     (uint32_t*)wch, (uint32_t*)wcl, (float*)bc);
    adj_kernel<<<1, 256>>>(be, (float*)adj);

    // band q/k/v projections fused: A tile split once per (kb, tile)
    proj3_kernel<<<dim3(4,120), 256, 94208>>>((const float*)xb, 65536LL,
        Wq, 16384LL, Wk, 16384LL, Wv, 8192LL, 4,
        nullptr, nullptr, nullptr,
        (float*)q, 65536LL, (float*)k_, 65536LL, (float*)v, 32768LL, 64);

    // flash: scores + online softmax/stats + AV (both halves), no S materialized
    flash_kernel<<<dim3(4,120,2), 128, 57344>>>((const float*)q, (const float*)k_,
                                                (const float*)v, o1, o2, (float*)rs);

    stats_finalize_kernel<<<240,128>>>((const float*)rs, (float*)st);
    lambda_kernel<<<1,128>>>((const float*)st, lw1, lb1, lw2, lb2, (float*)lam);
    combine_kernel<<<3840,256>>>(o1, o2, (const float*)lam, (float*)ob);

    // ob @ Wo + bo -> xm[b,k,n,t]: M=512,N=128,K=64
    mgemm_p<<<dim3(1,4,120),256,49152>>>((const float*)ob, Wo, bo, (float*)xm,
        64, 4, 131072LL, 32768LL, 64, 8192LL, 0LL, 128,
        65536LL, 1966080LL, 1, 512, 128, 1.f);

    pack_x_kernel<<<7680, 256>>>((const float*)xm, (uint32_t*)xp2);
    convgemm_mma<<<dim3(4,120), 256, 49152>>>((const uint32_t*)wch, (const uint32_t*)wcl,
                                              (const float*)bc, (const uint32_t*)xp2, (float*)xg);

    // graph q/k/v projections fused: M=61440, A tile split once per tile
    proj3_kernel<<<dim3(480,1), 256, 94208>>>((const float*)xg, 0LL,
        gWq, 0LL, gWk, 0LL, gWv, 0LL, 1,
        gbq, gbk, gbv,
        (float*)q, 0LL, (float*)k_, 0LL, (float*)xb, 0LL, 128);

    gattn_kernel<<<2048,128>>>((const float*)q, (const float*)k_, (const float*)xb,
                               (const float*)adj, (float*)xg);

    mgemm_p<<<dim3(1,480,1),256,49152>>>((const float*)xg, gWo, gbo, (float*)xm,
        128, 1, 0LL, 0LL, 128, 0LL, 0LL, 128, 0LL, 0LL, 128, 1, 0, 1.f);

    transpose_out_kernel<<<dim3(512,4),256>>>((const float*)xm, out);
}

// round 14
// speedup vs baseline: 1.1007x; 1.1007x over previous
#include <cuda_runtime.h>
#include <cuda_bf16.h>
#include <cstdint>

typedef long long LL;

// ------------------------------- scratch ------------------------------------
__device__ float g_xb[7864320];   // [kb=k*4+b][t][n]   (reused as vg)
__device__ float g_q [7864320];   // [kb][t][128]       (reused as qg)
__device__ float g_k [7864320];   // [kb][t][128]       (reused as kg)
__device__ float g_v [3932160];   // [kb][t][64]
__device__ float g_S [62914560];  // o1 / o2 flash outputs (reuse)
__device__ float g_rs[491520];
__device__ float g_st[960];
__device__ float g_lam[120];
__device__ float g_ob[3932160];   // [kb][t][64]
__device__ float g_xm[7864320];   // [b][k][n][t]       (reused as og)
__device__ uint32_t g_wch[3735552]; // packed bf16-hi pairs, step-major per band
__device__ uint32_t g_wcl[3735552]; // packed bf16-lo pairs
__device__ uint32_t g_xp2[7864320]; // xm as (hi | lo<<16) packed bf16
__device__ float g_bc[3840];
__device__ float g_xg[7864320];   // [(b*512+t)*30+k][n]
__device__ float g_adj[900];

__device__ __forceinline__ void band_cfg(int k, int& taps, int& shift, LL& woff){
    if (k <= 5)      { taps=32; shift=5; woff = (LL)k*(16384*32); }
    else if (k <= 14){ taps=16; shift=4; woff = 6LL*(16384*32) + (LL)(k-6)*(16384*16); }
    else             { taps=8;  shift=3; woff = 6LL*(16384*32) + 9LL*(16384*16) + (LL)(k-15)*(16384*8); }
}

__device__ __forceinline__ void split2(float v0, float v1, uint32_t& hi, uint32_t& lo){
    __nv_bfloat16 h0 = __float2bfloat16_rn(v0);
    __nv_bfloat16 h1 = __float2bfloat16_rn(v1);
    float l0 = v0 - __bfloat162float(h0);
    float l1 = v1 - __bfloat162float(h1);
    hi = (uint32_t)__bfloat16_as_ushort(h0) | ((uint32_t)__bfloat16_as_ushort(h1) << 16);
    lo = (uint32_t)__bfloat16_as_ushort(__float2bfloat16_rn(l0))
       | ((uint32_t)__bfloat16_as_ushort(__float2bfloat16_rn(l1)) << 16);
}

#define MMA_BF16(d, a0,a1,a2,a3, b0,b1) \
    asm volatile("mma.sync.aligned.m16n8k16.row.col.f32.bf16.bf16.f32 " \
        "{%0,%1,%2,%3}, {%4,%5,%6,%7}, {%8,%9}, {%0,%1,%2,%3};" \
        : "+f"((d)[0]), "+f"((d)[1]), "+f"((d)[2]), "+f"((d)[3]) \
        : "r"(a0), "r"(a1), "r"(a2), "r"(a3), "r"(b0), "r"(b1))

__device__ __forceinline__ void ldsm4(uint32_t& r0, uint32_t& r1, uint32_t& r2, uint32_t& r3, uint32_t a){
    asm volatile("ldmatrix.sync.aligned.m8n8.x4.shared.b16 {%0,%1,%2,%3}, [%4];"
        : "=r"(r0), "=r"(r1), "=r"(r2), "=r"(r3) : "r"(a));
}
__device__ __forceinline__ uint32_t s2u(const void* p){
    return (uint32_t)__cvta_generic_to_shared(p);
}

// ------------------------- block reduce (128 thr) ---------------------------
__device__ __forceinline__ float bred(float v, float* sred, int op){
    #pragma unroll
    for (int o = 16; o; o >>= 1){
        float t = __shfl_xor_sync(0xffffffffu, v, o);
        v = (op==0) ? v+t : (op==1) ? fmaxf(v,t) : fminf(v,t);
    }
    if ((threadIdx.x & 31) == 0) sred[threadIdx.x >> 5] = v;
    __syncthreads();
    float r = (op==0) ? (sred[0]+sred[1])+(sred[2]+sred[3])
            : (op==1) ? fmaxf(fmaxf(sred[0],sred[1]),fmaxf(sred[2],sred[3]))
            :           fminf(fminf(sred[0],sred[1]),fminf(sred[2],sred[3]));
    __syncthreads();
    return r;
}

// ------------------------------ transpose x ---------------------------------
__global__ void transpose_x_kernel(const float* __restrict__ x, float* __restrict__ xb){
    __shared__ float s[128*31 + 32];
    int t = blockIdx.x, b = blockIdx.y;
    const float* src = x + (LL)b*1966080 + (LL)t*30;
    for (int i = threadIdx.x; i < 3840; i += 256){
        int n = i / 30, k = i - n*30;
        s[n*31 + k] = src[(LL)n*15360 + k];
    }
    __syncthreads();
    for (int i = threadIdx.x; i < 3840; i += 256){
        int k = i >> 7, n = i & 127;
        xb[((LL)(k*4 + b)*512 + t)*128 + n] = s[n*31 + k];
    }
}

// ---------- pipelined bf16-split tensor-core GEMM (128x128, ldmatrix) --------
__global__ void __launch_bounds__(256)
mgemm_p(const float* __restrict__ A, const float* __restrict__ Bm,
        const float* __restrict__ bias, float* __restrict__ C, int Kd, int inner,
        LL a_o, LL a_i, int lda,
        LL b_o, LL b_i, int ldb,
        LL c_o, LL c_i, int c_m, int c_n,
        int bias_stride, float alpha)
{
    extern __shared__ uint32_t smm[];
    uint32_t* Ah = smm;            // [2][1536]
    uint32_t* Al = smm + 3072;
    uint32_t* Bh = smm + 6144;
    uint32_t* Bl = smm + 9216;
    int z = blockIdx.z;
    int ko = z / inner, bi = z - ko*inner;
    const float* Ab = A + (LL)ko*a_o + (LL)bi*a_i;
    const float* Bb = Bm + (LL)ko*b_o + (LL)bi*b_i;
    float* Cb = C + (LL)ko*c_o + (LL)bi*c_i;
    int m0 = blockIdx.y * 128, n0 = blockIdx.x * 128;
    int tid = threadIdx.x, lane = tid & 31, wid = tid >> 5;
    int m0w = (wid >> 2) * 64, n0w = (wid & 3) * 32;
    int lr = lane >> 2, lc = lane & 3;

    float acc[4][4][4];
    #pragma unroll
    for (int i=0;i<4;i++)
        #pragma unroll
        for (int j=0;j<4;j++)
            #pragma unroll
            for (int q=0;q<4;q++) acc[i][j][q]=0.f;

    int am = tid >> 1, ak8 = (tid & 1) * 8;
    int n4 = (tid & 31) * 4, kp = tid >> 5;
    const int NSTEP = Kd >> 4;

    // ldmatrix addresses
    int arow = (lane & 7) + ((lane >> 3) & 1) * 8;
    int akh = lane >> 4;
    uint32_t aAh[4], aAl[4];
    #pragma unroll
    for (int mf = 0; mf < 4; ++mf){
        int row = m0w + mf*16 + arow;
        aAh[mf] = s2u(Ah) + (uint32_t)((row*12 + akh*4)*4);
        aAl[mf] = s2u(Al) + (uint32_t)((row*12 + akh*4)*4);
    }
    int brow = n0w + (lane >> 4)*8 + (lane & 7);
    int bkh = (lane >> 3) & 1;
    uint32_t aBh = s2u(Bh) + (uint32_t)((brow*12 + bkh*4)*4);
    uint32_t aBl = s2u(Bl) + (uint32_t)((brow*12 + bkh*4)*4);

    float va[8];
    float4 rb0, rb1;
    {   // prologue (st = 0)
        const float* ap = Ab + (LL)(m0 + am)*lda + ak8;
        *(float4*)&va[0] = *(const float4*)(ap);
        *(float4*)&va[4] = *(const float4*)(ap + 4);
        const float* bp = Bb + (LL)(kp*2)*ldb + n0 + n4;
        rb0 = *(const float4*)bp;
        rb1 = *(const float4*)(bp + ldb);
    }
    for (int st = 0; st < NSTEP; ++st){
        int buf = (st & 1) * 1536;
        uint32_t bufb = (uint32_t)(st & 1) * 6144u;
        int basea = buf + am*12 + (tid & 1)*4;
        #pragma unroll
        for (int j=0;j<4;j++){
            uint32_t hi, lo;
            split2(va[2*j], va[2*j+1], hi, lo);
            Ah[basea + j] = hi; Al[basea + j] = lo;
        }
        {
            float e0[4] = {rb0.x, rb0.y, rb0.z, rb0.w};
            float e1[4] = {rb1.x, rb1.y, rb1.z, rb1.w};
            #pragma unroll
            for (int j=0;j<4;j++){
                uint32_t hi, lo;
                split2(e0[j], e1[j], hi, lo);
                Bh[buf + (n4+j)*12 + kp] = hi;
                Bl[buf + (n4+j)*12 + kp] = lo;
            }
        }
        __syncthreads();
        if (st + 1 < NSTEP){
            int c = (st + 1) << 4;
            const float* ap = Ab + (LL)(m0 + am)*lda + c + ak8;
            *(float4*)&va[0] = *(const float4*)(ap);
            *(float4*)&va[4] = *(const float4*)(ap + 4);
            const float* bp = Bb + (LL)(c + kp*2)*ldb + n0 + n4;
            rb0 = *(const float4*)bp;
            rb1 = *(const float4*)(bp + ldb);
        }
        uint32_t bh[4][2], bl[4][2];
        ldsm4(bh[0][0], bh[0][1], bh[1][0], bh[1][1], aBh + bufb);
        ldsm4(bh[2][0], bh[2][1], bh[3][0], bh[3][1], aBh + 768u + bufb);
        ldsm4(bl[0][0], bl[0][1], bl[1][0], bl[1][1], aBl + bufb);
        ldsm4(bl[2][0], bl[2][1], bl[3][0], bl[3][1], aBl + 768u + bufb);
        #pragma unroll
        for (int mf = 0; mf < 4; ++mf){
            uint32_t ah0,ah1,ah2,ah3, al0,al1,al2,al3;
            ldsm4(ah0,ah1,ah2,ah3, aAh[mf] + bufb);
            ldsm4(al0,al1,al2,al3, aAl[mf] + bufb);
            #pragma unroll
            for (int nf = 0; nf < 4; ++nf){
                MMA_BF16(acc[mf][nf], ah0,ah1,ah2,ah3, bh[nf][0], bh[nf][1]);
                MMA_BF16(acc[mf][nf], ah0,ah1,ah2,ah3, bl[nf][0], bl[nf][1]);
                MMA_BF16(acc[mf][nf], al0,al1,al2,al3, bh[nf][0], bh[nf][1]);
            }
        }
        __syncthreads();
    }
    #pragma unroll
    for (int mf = 0; mf < 4; ++mf){
        int m = m0 + m0w + mf*16 + lr;
        #pragma unroll
        for (int nf = 0; nf < 4; ++nf){
            int n = n0 + n0w + nf*8 + lc*2;
            float b0 = bias ? bias[bias_stride*ko + n]   : 0.f;
            float b1 = bias ? bias[bias_stride*ko + n+1] : 0.f;
            Cb[(LL)m*c_m + (LL)n*c_n]         = fmaf(alpha, acc[mf][nf][0], b0);
            Cb[(LL)m*c_m + (LL)(n+1)*c_n]     = fmaf(alpha, acc[mf][nf][1], b1);
            Cb[(LL)(m+8)*c_m + (LL)n*c_n]     = fmaf(alpha, acc[mf][nf][2], b0);
            Cb[(LL)(m+8)*c_m + (LL)(n+1)*c_n] = fmaf(alpha, acc[mf][nf][3], b1);
        }
    }
}

// ------- fused triple projection, ldmatrix fragments, pipelined B ------------
__global__ void __launch_bounds__(256)
proj3_kernel(const float* __restrict__ A, LL a_z,
             const float* __restrict__ W0, LL wz0,
             const float* __restrict__ W1, LL wz1,
             const float* __restrict__ W2, LL wz2,
             int kodiv,
             const float* __restrict__ b0, const float* __restrict__ b1,
             const float* __restrict__ b2,
             float* __restrict__ C0, LL cz0,
             float* __restrict__ C1, LL cz1,
             float* __restrict__ C2, LL cz2,
             int N2)
{
    extern __shared__ uint32_t smp[];
    uint32_t* Ah = smp;                 // [128][68]
    uint32_t* Al = Ah + 128*68;
    uint32_t* Bh = Al + 128*68;         // [2][1536]
    uint32_t* Bl = Bh + 3072;

    int z = blockIdx.y;
    int ko = z / kodiv;
    int tile = blockIdx.x;
    const float* Ab = A + (LL)z*a_z + (LL)tile*16384;
    int tid = threadIdx.x, lane = tid & 31, wid = tid >> 5;
    int m0w = (wid >> 2) * 64, n0w = (wid & 3) * 32;
    int lr = lane >> 2, lc = lane & 3;

    // ---- stage full A tile (split once): 2 threads/row, 64 floats each ----
    {
        int am = tid >> 1, koff = (tid & 1) * 64;
        const float* ap = Ab + (LL)am*128 + koff;
        int base = am*68 + (tid & 1)*32;
        #pragma unroll
        for (int g = 0; g < 8; ++g){
            float4 f0 = *(const float4*)(ap + g*8);
            float4 f1 = *(const float4*)(ap + g*8 + 4);
            float v[8] = {f0.x,f0.y,f0.z,f0.w,f1.x,f1.y,f1.z,f1.w};
            #pragma unroll
            for (int j = 0; j < 4; ++j){
                uint32_t hi, lo;
                split2(v[2*j], v[2*j+1], hi, lo);
                Ah[base + g*4 + j] = hi;
                Al[base + g*4 + j] = lo;
            }
        }
    }
    __syncthreads();

    const float* Ws[3] = {W0 + (LL)ko*wz0, W1 + (LL)ko*wz1, W2 + (LL)ko*wz2};
    const float* bs[3] = {b0, b1, b2};
    float* Cs[3];
    Cs[0] = C0 + (LL)z*cz0 + (LL)tile*16384;
    Cs[1] = C1 + (LL)z*cz1 + (LL)tile*16384;
    Cs[2] = C2 + (LL)z*cz2 + (LL)tile*128*N2;
    int Ns[3] = {128, 128, N2};
    int n4 = (tid & 31) * 4, kp = tid >> 5;

    // ldmatrix addresses
    int arow = (lane & 7) + ((lane >> 3) & 1) * 8;
    int akh = lane >> 4;
    uint32_t aAh[4], aAl[4];
    #pragma unroll
    for (int mf = 0; mf < 4; ++mf){
        int row = m0w + mf*16 + arow;
        aAh[mf] = s2u(Ah) + (uint32_t)((row*68 + akh*4)*4);
        aAl[mf] = s2u(Al) + (uint32_t)((row*68 + akh*4)*4);
    }
    int brow = n0w + (lane >> 4)*8 + (lane & 7);
    int bkh = (lane >> 3) & 1;
    uint32_t aBh = s2u(Bh) + (uint32_t)((brow*12 + bkh*4)*4);
    uint32_t aBl = s2u(Bl) + (uint32_t)((brow*12 + bkh*4)*4);

    for (int w = 0; w < 3; ++w){
        const float* Wb = Ws[w];
        int Nw = Ns[w];
        bool act = n4 < Nw;
        float acc[4][4][4];
        #pragma unroll
        for (int i=0;i<4;i++)
            #pragma unroll
            for (int j=0;j<4;j++)
                #pragma unroll
                for (int q=0;q<4;q++) acc[i][j][q]=0.f;

        float4 r0, r1;
        if (act){
            const float* bp0 = Wb + (LL)(kp*2)*Nw + n4;
            r0 = *(const float4*)bp0;
            r1 = *(const float4*)(bp0 + Nw);
        }
        for (int st = 0; st < 8; ++st){
            int buf = (st & 1) * 1536;
            uint32_t bufb = (uint32_t)(st & 1) * 6144u;
            if (act){
                float e0[4] = {r0.x, r0.y, r0.z, r0.w};
                float e1[4] = {r1.x, r1.y, r1.z, r1.w};
                #pragma unroll
                for (int j = 0; j < 4; ++j){
                    uint32_t hi, lo;
                    split2(e0[j], e1[j], hi, lo);
                    Bh[buf + (n4+j)*12 + kp] = hi;
                    Bl[buf + (n4+j)*12 + kp] = lo;
                }
            }
            __syncthreads();
            if (st < 7 && act){
                int c = (st + 1) << 4;
                const float* bp0 = Wb + (LL)(c + kp*2)*Nw + n4;
                r0 = *(const float4*)bp0;
                r1 = *(const float4*)(bp0 + Nw);
            }
            uint32_t bh[4][2], bl[4][2];
            ldsm4(bh[0][0], bh[0][1], bh[1][0], bh[1][1], aBh + bufb);
            ldsm4(bh[2][0], bh[2][1], bh[3][0], bh[3][1], aBh + 768u + bufb);
            ldsm4(bl[0][0], bl[0][1], bl[1][0], bl[1][1], aBl + bufb);
            ldsm4(bl[2][0], bl[2][1], bl[3][0], bl[3][1], aBl + 768u + bufb);
            uint32_t stb = (uint32_t)st * 32u;
            #pragma unroll
            for (int mf = 0; mf < 4; ++mf){
                uint32_t ah0,ah1,ah2,ah3, al0,al1,al2,al3;
                ldsm4(ah0,ah1,ah2,ah3, aAh[mf] + stb);
                ldsm4(al0,al1,al2,al3, aAl[mf] + stb);
                #pragma unroll
                for (int nf = 0; nf < 4; ++nf){
                    MMA_BF16(acc[mf][nf], ah0,ah1,ah2,ah3, bh[nf][0], bh[nf][1]);
                    MMA_BF16(acc[mf][nf], ah0,ah1,ah2,ah3, bl[nf][0], bl[nf][1]);
                    MMA_BF16(acc[mf][nf], al0,al1,al2,al3, bh[nf][0], bh[nf][1]);
                }
            }
        }
        const float* bw = bs[w];
        float* Cw = Cs[w];
        #pragma unroll
        for (int mf = 0; mf < 4; ++mf){
            int m = m0w + mf*16 + lr;
            #pragma unroll
            for (int nf = 0; nf < 4; ++nf){
                int n = n0w + nf*8 + lc*2;
                if (n < Nw){
                    float bb0 = bw ? bw[n]   : 0.f;
                    float bb1 = bw ? bw[n+1] : 0.f;
                    Cw[(LL)m*Nw + n]       = acc[mf][nf][0] + bb0;
                    Cw[(LL)m*Nw + n+1]     = acc[mf][nf][1] + bb1;
                    Cw[(LL)(m+8)*Nw + n]   = acc[mf][nf][2] + bb0;
                    Cw[(LL)(m+8)*Nw + n+1] = acc[mf][nf][3] + bb1;
                }
            }
        }
        __syncthreads();
    }
}

// ------------- flash-fused scores + online softmax/stats + AV ----------------
__global__ void __launch_bounds__(128)
flash_kernel(const float* __restrict__ qg, const float* __restrict__ kg,
             const float* __restrict__ vg, float* __restrict__ o1,
             float* __restrict__ o2, float* __restrict__ rs)
{
    extern __shared__ uint32_t sm[];
    uint32_t* Qh = sm;              // [128][36]
    uint32_t* Ql = Qh + 4608;
    uint32_t* Kh = Ql + 4608;       // [32][36]
    uint32_t* Kl = Kh + 1152;
    uint32_t* Vh = Kl + 1152;       // [64][20]
    uint32_t* Vl = Vh + 1280;

    int kb = blockIdx.y, half = blockIdx.z;
    int row0 = blockIdx.x * 128;
    const float* qb  = qg + (LL)kb*65536 + half*64;
    const float* kp_ = kg + (LL)kb*65536 + half*64;
    const float* vb  = vg + (LL)kb*32768;
    int tid = threadIdx.x, lane = tid & 31, wid = tid >> 5;
    int m0w = wid * 32;
    int lr = lane >> 2, lc = lane & 3;

    {
        const float* qr = qb + (LL)(row0 + tid)*128;
        #pragma unroll
        for (int g = 0; g < 16; ++g){
            float4 f = *(const float4*)(qr + g*4);
            uint32_t h0,l0,h1,l1;
            split2(f.x, f.y, h0, l0);
            split2(f.z, f.w, h1, l1);
            int p = tid*36 + g*2;
            Qh[p] = h0; Ql[p] = l0; Qh[p+1] = h1; Ql[p+1] = l1;
        }
    }

    float m2[2][2], dn[2][2], qq[2][2], vmn[2][2];
    #pragma unroll
    for (int a=0;a<2;a++)
        #pragma unroll
        for (int b2=0;b2<2;b2++){ m2[a][b2]=-1e30f; dn[a][b2]=0.f; qq[a][b2]=0.f; vmn[a][b2]=1e30f; }
    float o[2][8][4];
    #pragma unroll
    for (int a=0;a<2;a++)
        #pragma unroll
        for (int b2=0;b2<8;b2++)
            #pragma unroll
            for (int cql=0;cql<4;cql++) o[a][b2][cql]=0.f;

    for (int jt = 0; jt < 512; jt += 32){
        __syncthreads();
        {
            int j = tid >> 2, ds = (tid & 3) * 16;
            const float* kr = kp_ + (LL)(jt + j)*128 + ds;
            #pragma unroll
            for (int g = 0; g < 4; ++g){
                float4 f = *(const float4*)(kr + g*4);
                uint32_t h0,l0,h1,l1;
                split2(f.x,f.y,h0,l0); split2(f.z,f.w,h1,l1);
                int p = j*36 + (ds>>1) + g*2;
                Kh[p]=h0; Kl[p]=l0; Kh[p+1]=h1; Kl[p+1]=l1;
            }
        }
        {
            int jp = tid & 15, ds = (tid >> 4) * 8;
            const float* v0 = vb + (LL)(jt + jp*2)*64 + ds;
            #pragma unroll
            for (int g = 0; g < 8; ++g){
                uint32_t h,l;
                split2(v0[g], v0[64+g], h, l);
                Vh[(ds+g)*20 + jp] = h; Vl[(ds+g)*20 + jp] = l;
            }
        }
        __syncthreads();
        float s[2][4][4];
        #pragma unroll
        for (int a=0;a<2;a++)
            #pragma unroll
            for (int b2=0;b2<4;b2++)
                #pragma unroll
                for (int cql=0;cql<4;cql++) s[a][b2][cql]=0.f;
        #pragma unroll
        for (int kc = 0; kc < 4; ++kc){
            #pragma unroll
            for (int mf = 0; mf < 2; ++mf){
                int ra = (m0w + mf*16 + lr)*36 + kc*8 + lc;
                uint32_t ah0=Qh[ra], ah1=Qh[ra+288], ah2=Qh[ra+4], ah3=Qh[ra+292];
                uint32_t al0=Ql[ra], al1=Ql[ra+288], al2=Ql[ra+4], al3=Ql[ra+292];
                #pragma unroll
                for (int nf = 0; nf < 4; ++nf){
                    int rb = (nf*8 + lr)*36 + kc*8 + lc;
                    uint32_t bh0=Kh[rb], bh1=Kh[rb+4];
                    uint32_t bl0=Kl[rb], bl1=Kl[rb+4];
                    MMA_BF16(s[mf][nf], ah0,ah1,ah2,ah3, bh0,bh1);
                    MMA_BF16(s[mf][nf], ah0,ah1,ah2,ah3, bl0,bl1);
                    MMA_BF16(s[mf][nf], al0,al1,al2,al3, bh0,bh1);
                }
            }
        }
        #pragma unroll
        for (int mf = 0; mf < 2; ++mf){
            #pragma unroll
            for (int rh = 0; rh < 2; ++rh){
                float cmax = -1e30f, cmin = 1e30f;
                #pragma unroll
                for (int nf = 0; nf < 4; ++nf){
                    float e0 = s[mf][nf][rh*2]   * 0.25f;
                    float e1 = s[mf][nf][rh*2+1] * 0.25f;
                    s[mf][nf][rh*2] = e0; s[mf][nf][rh*2+1] = e1;
                    cmax = fmaxf(cmax, fmaxf(e0,e1));
                    cmin = fminf(cmin, fminf(e0,e1));
                }
                cmax = fmaxf(cmax, __shfl_xor_sync(0xffffffffu, cmax, 1));
                cmax = fmaxf(cmax, __shfl_xor_sync(0xffffffffu, cmax, 2));
                cmin = fminf(cmin, __shfl_xor_sync(0xffffffffu, cmin, 1));
                cmin = fminf(cmin, __shfl_xor_sync(0xffffffffu, cmin, 2));
                float mold = m2[mf][rh];
                float mnew = fmaxf(mold, cmax);
                bool upd = (mnew > mold);
                float rsum = 0.f, rsq = 0.f;
                #pragma unroll
                for (int nf = 0; nf < 4; ++nf){
                    float p0 = __expf(s[mf][nf][rh*2]   - mnew);
                    float p1 = __expf(s[mf][nf][rh*2+1] - mnew);
                    s[mf][nf][rh*2] = p0; s[mf][nf][rh*2+1] = p1;
                    rsum += p0 + p1;
                    rsq  += p0*p0 + p1*p1;
                }
                rsum += __shfl_xor_sync(0xffffffffu, rsum, 1);
                rsum += __shfl_xor_sync(0xffffffffu, rsum, 2);
                rsq  += __shfl_xor_sync(0xffffffffu, rsq, 1);
                rsq  += __shfl_xor_sync(0xffffffffu, rsq, 2);
                if (__any_sync(0xffffffffu, upd)){
                    float scale = __expf(mold - mnew);
                    dn[mf][rh] = dn[mf][rh]*scale + rsum;
                    qq[mf][rh] = qq[mf][rh]*scale*scale + rsq;
                    m2[mf][rh] = mnew;
                    #pragma unroll
                    for (int nfd = 0; nfd < 8; ++nfd){
                        o[mf][nfd][rh*2]   *= scale;
                        o[mf][nfd][rh*2+1] *= scale;
                    }
                } else {
                    dn[mf][rh] += rsum;
                    qq[mf][rh] += rsq;
                }
                vmn[mf][rh] = fminf(vmn[mf][rh], cmin);
            }
        }
        #pragma unroll
        for (int mf = 0; mf < 2; ++mf){
            #pragma unroll
            for (int kc2 = 0; kc2 < 2; ++kc2){
                uint32_t ah0,al0,ah1,al1,ah2,al2,ah3,al3;
                split2(s[mf][2*kc2][0],   s[mf][2*kc2][1],   ah0, al0);
                split2(s[mf][2*kc2][2],   s[mf][2*kc2][3],   ah1, al1);
                split2(s[mf][2*kc2+1][0], s[mf][2*kc2+1][1], ah2, al2);
                split2(s[mf][2*kc2+1][2], s[mf][2*kc2+1][3], ah3, al3);
                #pragma unroll
                for (int nfd = 0; nfd < 8; ++nfd){
                    int rb = (nfd*8 + lr)*20 + kc2*8 + lc;
                    uint32_t bh0=Vh[rb], bh1=Vh[rb+4];
                    uint32_t bl0=Vl[rb], bl1=Vl[rb+4];
                    MMA_BF16(o[mf][nfd], ah0,ah1,ah2,ah3, bh0,bh1);
                    MMA_BF16(o[mf][nfd], ah0,ah1,ah2,ah3, bl0,bl1);
                    MMA_BF16(o[mf][nfd], al0,al1,al2,al3, bh0,bh1);
                }
            }
        }
    }
    float* op = (half == 0 ? o1 : o2) + (LL)kb*32768;
    #pragma unroll
    for (int mf = 0; mf < 2; ++mf){
        #pragma unroll
        for (int rh = 0; rh < 2; ++rh){
            float inv = 1.f / dn[mf][rh];
            int r = row0 + m0w + mf*16 + lr + rh*8;
            #pragma unroll
            for (int nfd = 0; nfd < 8; ++nfd){
                o[mf][nfd][rh*2]   *= inv;
                o[mf][nfd][rh*2+1] *= inv;
            }
            if (lc == 0){
                float* rp = rs + ((LL)(half*120 + kb)*512 + r)*4;
                rp[0] = 1.0f;
                rp[1] = qq[mf][rh]*inv*inv;
                rp[2] = inv;
                rp[3] = __expf(vmn[mf][rh] - m2[mf][rh]) * inv;
            }
            float* orow = op + (LL)r*64 + lc*2;
            #pragma unroll
            for (int nfd = 0; nfd < 8; ++nfd){
                orow[nfd*8]   = o[mf][nfd][rh*2];
                orow[nfd*8+1] = o[mf][nfd][rh*2+1];
            }
        }
    }
}

// --------------------------- ob = o1 - lam*o2 --------------------------------
__global__ void combine_kernel(const float* __restrict__ o1, const float* __restrict__ o2,
                               const float* __restrict__ lam, float* __restrict__ ob){
    int i = blockIdx.x*256 + threadIdx.x;
    int kb = i >> 13;
    float l = lam[kb];
    float4 a = ((const float4*)o1)[i];
    float4 c = ((const float4*)o2)[i];
    a.x = fmaf(-l, c.x, a.x); a.y = fmaf(-l, c.y, a.y);
    a.z = fmaf(-l, c.z, a.z); a.w = fmaf(-l, c.w, a.w);
    ((float4*)ob)[i] = a;
}

// --------------------- per-(half,kb) stat aggregation ------------------------
__global__ void stats_finalize_kernel(const float* __restrict__ rs, float* __restrict__ st){
    __shared__ float sred[4];
    int hb = blockIdx.x;
    const float* r = rs + (LL)hb*512*4;
    int tid = threadIdx.x;
    float s=0.f,q=0.f,mx=-1e30f,mn=1e30f;
    for (int i = tid; i < 512; i += 128){
        s += r[i*4+0]; q += r[i*4+1];
        mx = fmaxf(mx, r[i*4+2]); mn = fminf(mn, r[i*4+3]);
    }
    s = bred(s,sred,0); q = bred(q,sred,0);
    mx = bred(mx,sred,1); mn = bred(mn,sred,2);
    if (tid == 0){
        float* o = st + hb*4;
        o[0]=s; o[1]=q; o[2]=mx; o[3]=mn;
    }
}

// ------------------------------- lambda MLP ---------------------------------
__global__ void lambda_kernel(const float* __restrict__ st,
                              const float* __restrict__ lw1, const float* __restrict__ lb1,
                              const float* __restrict__ lw2, const float* __restrict__ lb2,
                              float* __restrict__ lam){
    int kb = threadIdx.x;
    if (kb >= 120) return;
    int k = kb >> 2;
    const float M2 = 262144.f;
    float s8[8];
    #pragma unroll
    for (int h2 = 0; h2 < 2; ++h2){
        const float* sp = st + (h2*120 + kb)*4;
        float sum = sp[0], sq = sp[1];
        s8[h2*4+0] = sum / M2;
        float var = (sq - sum*sum/M2) / (M2 - 1.f);
        s8[h2*4+1] = sqrtf(fmaxf(var, 0.f));
        s8[h2*4+2] = sp[2];
        s8[h2*4+3] = sp[3];
    }
    float z = lb2[k];
    for (int o = 0; o < 16; ++o){
        float h = lb1[k*16+o];
        #pragma unroll
        for (int i = 0; i < 8; ++i) h = fmaf(s8[i], lw1[(k*8+i)*16+o], h);
        h = fmaxf(h, 0.f);
        z = fmaf(h, lw2[k*16+o], z);
    }
    lam[kb] = 1.f/(1.f + expf(-z));
}

// ------------- combined multiscale conv weights -> packed bf16 hi/lo ---------
__global__ void combine_wc_kernel(const float* __restrict__ fw,
    const float* cwA, const float* cwB, const float* cwC, const float* cwD, const float* cwE,
    const float* cbA, const float* cbB, const float* cbC, const float* cbD, const float* cbE,
    uint32_t* __restrict__ wch, uint32_t* __restrict__ wcl, float* __restrict__ bc){
    int idx = blockIdx.x*256 + threadIdx.x;
    if (idx >= 491520) return;
    int k = idx >> 14;
    int rem = idx & 16383;
    int n = rem >> 7, m = rem & 127;
    int base = (k <= 5) ? 2 : (k <= 14) ? 1 : 0;
    int taps, shift; LL woff;
    band_cfg(k, taps, shift, woff);
    int half = taps >> 1;
    float f0 = fw[k*3+0], f1 = fw[k*3+1], f2 = fw[k*3+2];
    float fm = fmaxf(f0, fmaxf(f1, f2));
    float e0 = expf(f0-fm), e1 = expf(f1-fm), e2 = expf(f2-fm);
    float den = e0+e1+e2;
    float sw[3] = {e0/den, e1/den, e2/den};
    const float* cws[5] = {cwA,cwB,cwC,cwD,cwE};
    const float* cbs[5] = {cbA,cbB,cbC,cbD,cbE};
    const int ss[5] = {2,4,8,16,32};
    LL wp = woff >> 1;
    float prev = 0.f;
    for (int u = 0; u < taps; ++u){
        int tau = u - half;
        float a = 0.f;
        #pragma unroll
        for (int j = 0; j < 3; ++j){
            int slot = base + j;
            int sc = ss[slot], h2 = sc >> 1;
            if (tau >= -h2 && tau < h2)
                a = fmaf(sw[j], cws[slot][((LL)n*128 + m)*sc + tau + h2], a);
        }
        if ((u & 1) == 0) prev = a;
        else {
            uint32_t hi, lo;
            split2(prev, a, hi, lo);
            int kk = m*taps + u - 1;
            int stp = kk >> 4;
            int kp = (kk >> 1) & 7;
            LL widx = wp + (LL)stp*1024 + n*8 + kp;
            wch[widx] = hi; wcl[widx] = lo;
        }
    }
    if (m == 0){
        float bcv = 0.f;
        #pragma unroll
        for (int j = 0; j < 3; ++j) bcv = fmaf(sw[j], cbs[base+j][n], bcv);
        bc[k*128+n] = bcv;
    }
}

// ------------------------ pack xm into bf16 hi|lo words ----------------------
__global__ void pack_x_kernel(const float* __restrict__ xm, uint32_t* __restrict__ xp2){
    int i = blockIdx.x*256 + threadIdx.x;
    float4 v = ((const float4*)xm)[i];
    float vv[4] = {v.x, v.y, v.z, v.w};
    uint32_t w[4];
    #pragma unroll
    for (int j = 0; j < 4; ++j){
        __nv_bfloat16 h = __float2bfloat16_rn(vv[j]);
        float l = vv[j] - __bfloat162float(h);
        w[j] = (uint32_t)__bfloat16_as_ushort(h)
             | ((uint32_t)__bfloat16_as_ushort(__float2bfloat16_rn(l)) << 16);
    }
    ((uint4*)xp2)[i] = make_uint4(w[0], w[1], w[2], w[3]);
}

// -------- pipelined mma.sync bf16 conv (ldmatrix fragments) ------------------
__global__ void __launch_bounds__(256)
convgemm_mma(const uint32_t* __restrict__ wch, const uint32_t* __restrict__ wcl,
             const float* __restrict__ bc, const uint32_t* __restrict__ xp2,
             float* __restrict__ xg)
{
    extern __shared__ uint32_t smc[];
    uint32_t* Ah = smc;            // [2][1536]
    uint32_t* Al = smc + 3072;
    uint32_t* Bh = smc + 6144;
    uint32_t* Bl = smc + 9216;
    int z = (int)((blockIdx.y * 49u) % 120u);
    int b = z / 30, k = z - b*30;
    int taps, shift; LL woff;
    band_cfg(k, taps, shift, woff);
    const int NC = taps << 3;
    const int half = taps >> 1;
    const int mask = taps - 1;
    const uint32_t* Abh = wch + (woff >> 1);
    const uint32_t* Abl = wcl + (woff >> 1);
    const uint32_t* xpz = xp2 + (LL)z*65536;
    int t0 = blockIdx.x * 128;
    int tid = threadIdx.x;
    int lane = tid & 31, wid = tid >> 5;
    int m0w = (wid >> 2) * 64, n0w = (wid & 3) * 32;
    int lr = lane >> 2, lc = lane & 3;

    float acc[4][4][4];
    #pragma unroll
    for (int i=0;i<4;i++)
        #pragma unroll
        for (int j=0;j<4;j++)
            #pragma unroll
            for (int q=0;q<4;q++) acc[i][j][q]=0.f;

    int am = tid >> 1, akp = (tid & 1) * 4;
    int bkp = tid & 7, btq = tid >> 3;

    // ldmatrix addresses
    int arow = (lane & 7) + ((lane >> 3) & 1) * 8;
    int akh = lane >> 4;
    uint32_t aAh[4], aAl[4];
    #pragma unroll
    for (int mf = 0; mf < 4; ++mf){
        int row = m0w + mf*16 + arow;
        aAh[mf] = s2u(Ah) + (uint32_t)((row*12 + akh*4)*4);
        aAl[mf] = s2u(Al) + (uint32_t)((row*12 + akh*4)*4);
    }
    int brow = n0w + (lane >> 4)*8 + (lane & 7);
    int bkh = (lane >> 3) & 1;
    uint32_t aBh = s2u(Bh) + (uint32_t)((brow*12 + bkh*4)*4);
    uint32_t aBl = s2u(Bl) + (uint32_t)((brow*12 + bkh*4)*4);

    uint4 a4h, a4l;
    uint32_t bhv[4], blv[4];
    {
        a4h = *(const uint4*)(Abh + tid*4);
        a4l = *(const uint4*)(Abl + tid*4);
        int kk = bkp*2;
        int mi = kk >> shift, u0 = kk & mask;
        const uint32_t* src = xpz + (LL)mi*512;
        int off = u0 - half;
        #pragma unroll
        for (int i = 0; i < 4; ++i){
            int t = btq*4 + i;
            int p0 = t0 + t + off;
            uint32_t w0 = ((unsigned)p0 < 512u) ? src[p0] : 0u;
            uint32_t w1 = ((unsigned)(p0+1) < 512u) ? src[p0+1] : 0u;
            bhv[i] = __byte_perm(w0, w1, 0x5410);
            blv[i] = __byte_perm(w0, w1, 0x7632);
        }
    }
    for (int st = 0; st < NC; ++st){
        int buf = (st & 1) * 1536;
        uint32_t bufb = (uint32_t)(st & 1) * 6144u;
        *(uint4*)&Ah[buf + am*12 + akp] = a4h;
        *(uint4*)&Al[buf + am*12 + akp] = a4l;
        #pragma unroll
        for (int i = 0; i < 4; ++i){
            int t = btq*4 + i;
            Bh[buf + t*12 + bkp] = bhv[i];
            Bl[buf + t*12 + bkp] = blv[i];
        }
        __syncthreads();
        if (st + 1 < NC){
            int stn = st + 1;
            a4h = *(const uint4*)(Abh + (LL)stn*1024 + tid*4);
            a4l = *(const uint4*)(Abl + (LL)stn*1024 + tid*4);
            int kk = (stn << 4) + bkp*2;
            int mi = kk >> shift, u0 = kk & mask;
            const uint32_t* src = xpz + (LL)mi*512;
            int off = u0 - half;
            #pragma unroll
            for (int i = 0; i < 4; ++i){
                int t = btq*4 + i;
                int p0 = t0 + t + off;
                uint32_t w0 = ((unsigned)p0 < 512u) ? src[p0] : 0u;
                uint32_t w1 = ((unsigned)(p0+1) < 512u) ? src[p0+1] : 0u;
                bhv[i] = __byte_perm(w0, w1, 0x5410);
                blv[i] = __byte_perm(w0, w1, 0x7632);
            }
        }
        uint32_t bh[4][2], bl[4][2];
        ldsm4(bh[0][0], bh[0][1], bh[1][0], bh[1][1], aBh + bufb);
        ldsm4(bh[2][0], bh[2][1], bh[3][0], bh[3][1], aBh + 768u + bufb);
        ldsm4(bl[0][0], bl[0][1], bl[1][0], bl[1][1], aBl + bufb);
        ldsm4(bl[2][0], bl[2][1], bl[3][0], bl[3][1], aBl + 768u + bufb);
        #pragma unroll
        for (int mf = 0; mf < 4; ++mf){
            uint32_t ah0,ah1,ah2,ah3, al0,al1,al2,al3;
            ldsm4(ah0,ah1,ah2,ah3, aAh[mf] + bufb);
            ldsm4(al0,al1,al2,al3, aAl[mf] + bufb);
            #pragma unroll
            for (int nf = 0; nf < 4; ++nf){
                MMA_BF16(acc[mf][nf], ah0,ah1,ah2,ah3, bh[nf][0], bh[nf][1]);
                MMA_BF16(acc[mf][nf], ah0,ah1,ah2,ah3, bl[nf][0], bl[nf][1]);
                MMA_BF16(acc[mf][nf], al0,al1,al2,al3, bh[nf][0], bh[nf][1]);
            }
        }
    }
    #pragma unroll
    for (int mf = 0; mf < 4; ++mf){
        int m = m0w + mf*16 + lr;
        float bc0 = bc[k*128 + m];
        float bc1 = bc[k*128 + m + 8];
        #pragma unroll
        for (int nf = 0; nf < 4; ++nf){
            int t = t0 + n0w + nf*8 + lc*2;
            LL base = ((LL)((b*512 + t)*30 + k)) * 128;
            xg[base + m]          = acc[mf][nf][0] + bc0;
            xg[base + 3840 + m]   = acc[mf][nf][1] + bc0;
            xg[base + m + 8]      = acc[mf][nf][2] + bc1;
            xg[base + 3840 + m+8] = acc[mf][nf][3] + bc1;
        }
    }
}

// ------------------------------- adjacency ----------------------------------
__global__ void adj_kernel(const float* __restrict__ be, float* __restrict__ adj){
    __shared__ float e[30][64];
    __shared__ float sim[30][30];
    __shared__ float Ar[30][30];
    int tid = threadIdx.x;
    for (int i = tid; i < 30; i += 256){
        float s = 0.f;
        for (int d = 0; d < 64; ++d){ float v = be[i*64+d]; s += v*v; }
        float inv = 1.f/(sqrtf(s)+1e-8f);
        for (int d = 0; d < 64; ++d) e[i][d] = be[i*64+d]*inv;
    }
    __syncthreads();
    for (int p = tid; p < 900; p += 256){
        int i = p/30, j = p - (p/30)*30;
        float s = 0.f;
        for (int d = 0; d < 64; ++d) s = fmaf(e[i][d], e[j][d], s);
        sim[i][j] = s; Ar[i][j] = 0.f;
    }
    __syncthreads();
    if (tid < 30){
        bool taken[30];
        for (int j = 0; j < 30; ++j) taken[j] = false;
        for (int r = 0; r < 5; ++r){
            int bi = 0; float bvv = -1e30f;
            for (int j = 0; j < 30; ++j)
                if (!taken[j] && sim[tid][j] > bvv){ bvv = sim[tid][j]; bi = j; }
            taken[bi] = true;
            Ar[tid][bi] = bvv;
        }
    }
    __syncthreads();
    for (int p = tid; p < 900; p += 256){
        int i = p/30, j = p - (p/30)*30;
        adj[p] = 0.5f*(Ar[i][j] + Ar[j][i]);
    }
}

// --------------------------- graph attention core ---------------------------
__global__ void gattn_kernel(const float* __restrict__ qg, const float* __restrict__ kg,
                             const float* __restrict__ vg, const float* __restrict__ adj,
                             float* __restrict__ outp){
    __shared__ float sq[4][30][32];
    __shared__ float sv[4][30][32];
    __shared__ float sadj[30][30];
    __shared__ float sat[4][32];
    LL m = blockIdx.x;
    int tid = threadIdx.x, h = tid >> 5, lane = tid & 31;
    for (int i = tid; i < 3840; i += 128){
        int r = i >> 7, c = i & 127;
        sq[c>>5][r][c&31] = qg[m*3840 + i];
        sv[c>>5][r][c&31] = vg[m*3840 + i];
    }
    for (int i = tid; i < 900; i += 128) sadj[i/30][i - (i/30)*30] = adj[i];
    float kreg[32];
    if (lane < 30){
        #pragma unroll
        for (int d = 0; d < 32; ++d) kreg[d] = kg[m*3840 + lane*128 + h*32 + d];
    } else {
        #pragma unroll
        for (int d = 0; d < 32; ++d) kreg[d] = 0.f;
    }
    __syncthreads();
    const float invs = 0.17677669529663687f;
    float* orow = outp + m*3840;
    for (int i = 0; i < 30; ++i){
        float qv = sq[h][i][lane];
        float d = 0.f;
        #pragma unroll
        for (int dd = 0; dd < 32; ++dd)
            d = fmaf(__shfl_sync(0xffffffffu, qv, dd), kreg[dd], d);
        bool valid = (lane < 30) && (sadj[i][lane] != 0.f);
        float sc = valid ? d*invs : -1e30f;
        float mx = sc;
        #pragma unroll
        for (int o=16;o;o>>=1) mx = fmaxf(mx, __shfl_xor_sync(0xffffffffu, mx, o));
        float e = valid ? expf(sc - mx) : 0.f;
        float s = e;
        #pragma unroll
        for (int o=16;o;o>>=1) s += __shfl_xor_sync(0xffffffffu, s, o);
        float at = (s > 0.f) ? e/s : 0.f;
        sat[h][lane] = at;
        __syncwarp();
        float o = 0.f;
        for (int j = 0; j < 30; ++j) o = fmaf(sat[h][j], sv[h][j][lane], o);
        orow[i*128 + h*32 + lane] = o;
        __syncwarp();
    }
}

// ------------------------------ output transpose -----------------------------
__global__ void transpose_out_kernel(const float* __restrict__ og, float* __restrict__ out){
    __shared__ float s[30*129 + 32];
    int t = blockIdx.x, b = blockIdx.y;
    const float* src = og + (LL)(b*512 + t)*3840;
    for (int i = threadIdx.x; i < 3840; i += 256){
        int k = i >> 7, n = i & 127;
        s[k*129 + n] = src[i];
    }
    __syncthreads();
    float* dst = out + (LL)b*1966080 + (LL)t*30;
    for (int i = threadIdx.x; i < 3840; i += 256){
        int n = i / 30, k = i - n*30;
        dst[(LL)n*15360 + k] = s[k*129 + n];
    }
}

// ----------------------------------- launch ----------------------------------
extern "C" void kernel_launch(void* const* d_in, const int* in_sizes, int n_in,
                              void* d_out, int out_size) {
    const float* x   = (const float*)d_in[0];
    const float* Wq  = (const float*)d_in[1];
    const float* Wk  = (const float*)d_in[2];
    const float* Wv  = (const float*)d_in[3];
    const float* Wo  = (const float*)d_in[4];
    const float* bo  = (const float*)d_in[5];
    const float* lw1 = (const float*)d_in[6];
    const float* lb1 = (const float*)d_in[7];
    const float* lw2 = (const float*)d_in[8];
    const float* lb2 = (const float*)d_in[9];
    const float* cw2 = (const float*)d_in[10];
    const float* cb2 = (const float*)d_in[11];
    const float* cw4 = (const float*)d_in[12];
    const float* cb4 = (const float*)d_in[13];
    const float* cw8 = (const float*)d_in[14];
    const float* cb8 = (const float*)d_in[15];
    const float* cw16= (const float*)d_in[16];
    const float* cb16= (const float*)d_in[17];
    const float* cw32= (const float*)d_in[18];
    const float* cb32= (const float*)d_in[19];
    const float* fw  = (const float*)d_in[20];
    const float* be  = (const float*)d_in[21];
    const float* gWq = (const float*)d_in[22];
    const float* gbq = (const float*)d_in[23];
    const float* gWk = (const float*)d_in[24];
    const float* gbk = (const float*)d_in[25];
    const float* gWv = (const float*)d_in[26];
    const float* gbv = (const float*)d_in[27];
    const float* gWo = (const float*)d_in[28];
    const float* gbo = (const float*)d_in[29];
    float* out = (float*)d_out;

    void *xb,*q,*k_,*v,*S,*rs,*st,*lam,*ob,*xm,*wch,*wcl,*xp2,*bc,*xg,*adj;
    cudaGetSymbolAddress(&xb, g_xb);  cudaGetSymbolAddress(&q,  g_q);
    cudaGetSymbolAddress(&k_, g_k);   cudaGetSymbolAddress(&v,  g_v);
    cudaGetSymbolAddress(&S,  g_S);   cudaGetSymbolAddress(&rs, g_rs);
    cudaGetSymbolAddress(&st, g_st);  cudaGetSymbolAddress(&lam,g_lam);
    cudaGetSymbolAddress(&ob, g_ob);  cudaGetSymbolAddress(&xm, g_xm);
    cudaGetSymbolAddress(&wch,g_wch); cudaGetSymbolAddress(&wcl,g_wcl);
    cudaGetSymbolAddress(&xp2,g_xp2); cudaGetSymbolAddress(&bc, g_bc);
    cudaGetSymbolAddress(&xg, g_xg);  cudaGetSymbolAddress(&adj,g_adj);

    float* o1 = (float*)S;
    float* o2 = (float*)S + 3932160;

    cudaFuncSetAttribute(flash_kernel, cudaFuncAttributeMaxDynamicSharedMemorySize, 57344);
    cudaFuncSetAttribute(proj3_kernel, cudaFuncAttributeMaxDynamicSharedMemorySize, 94208);
    cudaFuncSetAttribute(mgemm_p, cudaFuncAttributeMaxDynamicSharedMemorySize, 49152);
    cudaFuncSetAttribute(convgemm_mma, cudaFuncAttributeMaxDynamicSharedMemorySize, 49152);

    transpose_x_kernel<<<dim3(512,4), 256>>>(x, (float*)xb);
    combine_wc_kernel<<<1920, 256>>>(fw, cw2,cw4,cw8,cw16,cw32,
                                     cb2,cb4,cb8,cb16,cb32,
                                     (uint32_t*)wch, (uint32_t*)wcl, (float*)bc);
    adj_kernel<<<1, 256>>>(be, (float*)adj);

    proj3_kernel<<<dim3(4,120), 256, 94208>>>((const float*)xb, 65536LL,
        Wq, 16384LL, Wk, 16384LL, Wv, 8192LL, 4,
        nullptr, nullptr, nullptr,
        (float*)q, 65536LL, (float*)k_, 65536LL, (float*)v, 32768LL, 64);

    flash_kernel<<<dim3(4,120,2), 128, 57344>>>((const float*)q, (const float*)k_,
                                                (const float*)v, o1, o2, (float*)rs);

    stats_finalize_kernel<<<240,128>>>((const float*)rs, (float*)st);
    lambda_kernel<<<1,128>>>((const float*)st, lw1, lb1, lw2, lb2, (float*)lam);
    combine_kernel<<<3840,256>>>(o1, o2, (const float*)lam, (float*)ob);

    mgemm_p<<<dim3(1,4,120),256,49152>>>((const float*)ob, Wo, bo, (float*)xm,
        64, 4, 131072LL, 32768LL, 64, 8192LL, 0LL, 128,
        65536LL, 1966080LL, 1, 512, 128, 1.f);

    pack_x_kernel<<<7680, 256>>>((const float*)xm, (uint32_t*)xp2);
    convgemm_mma<<<dim3(4,120), 256, 49152>>>((const uint32_t*)wch, (const uint32_t*)wcl,
                                              (const float*)bc, (const uint32_t*)xp2, (float*)xg);

    proj3_kernel<<<dim3(480,1), 256, 94208>>>((const float*)xg, 0LL,
        gWq, 0LL, gWk, 0LL, gWv, 0LL, 1,
        gbq, gbk, gbv,
        (float*)q, 0LL, (float*)k_, 0LL, (float*)xb, 0LL, 128);

    gattn_kernel<<<2048,128>>>((const float*)q, (const float*)k_, (const float*)xb,
                               (const float*)adj, (float*)xg);

    mgemm_p<<<dim3(1,480,1),256,49152>>>((const float*)xg, gWo, gbo, (float*)xm,
        128, 1, 0LL, 0LL, 128, 0LL, 0LL, 128, 0LL, 0LL, 128, 1, 0, 1.f);

    transpose_out_kernel<<<dim3(512,4),256>>>((const float*)xm, out);
}

// round 15
// speedup vs baseline: 1.1787x; 1.0709x over previous
#include <cuda_runtime.h>
#include <cuda_bf16.h>
#include <cstdint>

typedef long long LL;

// ------------------------------- scratch ------------------------------------
__device__ float g_xb[7864320];   // [kb=k*4+b][t][n]   (reused as vg)
__device__ float g_q [7864320];   // [kb][t][128]       (reused as qg)
__device__ float g_k [7864320];   // [kb][t][128]       (reused as kg)
__device__ float g_v [3932160];   // [kb][t][64]
__device__ float g_S [62914560];  // o1 / o2 flash outputs
__device__ float g_rs[491520];
__device__ float g_st[960];
__device__ float g_lam[120];
__device__ float g_xm[7864320];   // [b][k][n][t]       (reused as og)
__device__ uint32_t g_wch[3735552];
__device__ uint32_t g_wcl[3735552];
__device__ uint32_t g_xp2[7864320]; // xm packed bf16 (hi | lo<<16)
__device__ float g_bc[3840];
__device__ float g_xg[7864320];   // [(b*512+t)*30+k][n]
__device__ float g_adj[900];

__device__ __forceinline__ void band_cfg(int k, int& taps, int& shift, LL& woff){
    if (k <= 5)      { taps=32; shift=5; woff = (LL)k*(16384*32); }
    else if (k <= 14){ taps=16; shift=4; woff = 6LL*(16384*32) + (LL)(k-6)*(16384*16); }
    else             { taps=8;  shift=3; woff = 6LL*(16384*32) + 9LL*(16384*16) + (LL)(k-15)*(16384*8); }
}

__device__ __forceinline__ void split2(float v0, float v1, uint32_t& hi, uint32_t& lo){
    __nv_bfloat16 h0 = __float2bfloat16_rn(v0);
    __nv_bfloat16 h1 = __float2bfloat16_rn(v1);
    float l0 = v0 - __bfloat162float(h0);
    float l1 = v1 - __bfloat162float(h1);
    hi = (uint32_t)__bfloat16_as_ushort(h0) | ((uint32_t)__bfloat16_as_ushort(h1) << 16);
    lo = (uint32_t)__bfloat16_as_ushort(__float2bfloat16_rn(l0))
       | ((uint32_t)__bfloat16_as_ushort(__float2bfloat16_rn(l1)) << 16);
}
__device__ __forceinline__ uint32_t pack1(float v){
    __nv_bfloat16 h = __float2bfloat16_rn(v);
    float l = v - __bfloat162float(h);
    return (uint32_t)__bfloat16_as_ushort(h)
         | ((uint32_t)__bfloat16_as_ushort(__float2bfloat16_rn(l)) << 16);
}

#define MMA_BF16(d, a0,a1,a2,a3, b0,b1) \
    asm volatile("mma.sync.aligned.m16n8k16.row.col.f32.bf16.bf16.f32 " \
        "{%0,%1,%2,%3}, {%4,%5,%6,%7}, {%8,%9}, {%0,%1,%2,%3};" \
        : "+f"((d)[0]), "+f"((d)[1]), "+f"((d)[2]), "+f"((d)[3]) \
        : "r"(a0), "r"(a1), "r"(a2), "r"(a3), "r"(b0), "r"(b1))

__device__ __forceinline__ void ldsm4(uint32_t& r0, uint32_t& r1, uint32_t& r2, uint32_t& r3, uint32_t a){
    asm volatile("ldmatrix.sync.aligned.m8n8.x4.shared.b16 {%0,%1,%2,%3}, [%4];"
        : "=r"(r0), "=r"(r1), "=r"(r2), "=r"(r3) : "r"(a));
}
__device__ __forceinline__ void ldsm4t(uint32_t& r0, uint32_t& r1, uint32_t& r2, uint32_t& r3, uint32_t a){
    asm volatile("ldmatrix.sync.aligned.m8n8.x4.trans.shared.b16 {%0,%1,%2,%3}, [%4];"
        : "=r"(r0), "=r"(r1), "=r"(r2), "=r"(r3) : "r"(a));
}
__device__ __forceinline__ uint32_t s2u(const void* p){
    return (uint32_t)__cvta_generic_to_shared(p);
}

// ------------------------- block reduce (128 thr) ---------------------------
__device__ __forceinline__ float bred(float v, float* sred, int op){
    #pragma unroll
    for (int o = 16; o; o >>= 1){
        float t = __shfl_xor_sync(0xffffffffu, v, o);
        v = (op==0) ? v+t : (op==1) ? fmaxf(v,t) : fminf(v,t);
    }
    if ((threadIdx.x & 31) == 0) sred[threadIdx.x >> 5] = v;
    __syncthreads();
    float r = (op==0) ? (sred[0]+sred[1])+(sred[2]+sred[3])
            : (op==1) ? fmaxf(fmaxf(sred[0],sred[1]),fmaxf(sred[2],sred[3]))
            :           fminf(fminf(sred[0],sred[1]),fminf(sred[2],sred[3]));
    __syncthreads();
    return r;
}

// ------------------------------ transpose x ---------------------------------
__global__ void transpose_x_kernel(const float* __restrict__ x, float* __restrict__ xb){
    __shared__ float s[128*31 + 32];
    int t = blockIdx.x, b = blockIdx.y;
    const float* src = x + (LL)b*1966080 + (LL)t*30;
    for (int i = threadIdx.x; i < 3840; i += 256){
        int n = i / 30, k = i - n*30;
        s[n*31 + k] = src[(LL)n*15360 + k];
    }
    __syncthreads();
    for (int i = threadIdx.x; i < 3840; i += 256){
        int k = i >> 7, n = i & 127;
        xb[((LL)(k*4 + b)*512 + t)*128 + n] = s[n*31 + k];
    }
}

// ---------- pipelined bf16-split GEMM (128x128), conflict-free B -------------
// A_eff = A - lam[z]*A2 when A2 != null. Cp != null -> also write packed bf16.
__global__ void __launch_bounds__(256)
mgemm_p(const float* __restrict__ A, const float* __restrict__ A2,
        const float* __restrict__ lam,
        const float* __restrict__ Bm, const float* __restrict__ bias,
        float* __restrict__ C, uint32_t* __restrict__ Cp, int Kd, int inner,
        LL a_o, LL a_i, int lda,
        LL b_o, LL b_i, int ldb,
        LL c_o, LL c_i, int c_m, int c_n,
        int bias_stride, float alpha)
{
    extern __shared__ uint32_t smm[];
    uint32_t* Ah = smm;              // [2][1536]
    uint32_t* Al = smm + 3072;
    uint32_t* Bh = smm + 6144;       // [2][16*68]
    uint32_t* Bl = smm + 6144 + 2176;
    int z = blockIdx.z;
    int ko = z / inner, bi = z - ko*inner;
    const float* Ab  = A + (LL)ko*a_o + (LL)bi*a_i;
    const float* A2b = A2 ? A2 + (LL)ko*a_o + (LL)bi*a_i : nullptr;
    float lamv = lam ? lam[z] : 0.f;
    const float* Bb = Bm + (LL)ko*b_o + (LL)bi*b_i;
    float* Cb = C + (LL)ko*c_o + (LL)bi*c_i;
    uint32_t* Cpb = Cp ? Cp + (LL)ko*c_o + (LL)bi*c_i : nullptr;
    int m0 = blockIdx.y * 128, n0 = blockIdx.x * 128;
    int tid = threadIdx.x, lane = tid & 31, wid = tid >> 5;
    int m0w = (wid >> 2) * 64, n0w = (wid & 3) * 32;
    int lr = lane >> 2, lc = lane & 3;

    float acc[4][4][4];
    #pragma unroll
    for (int i=0;i<4;i++)
        #pragma unroll
        for (int j=0;j<4;j++)
            #pragma unroll
            for (int q=0;q<4;q++) acc[i][j][q]=0.f;

    int am = tid >> 1, ak8 = (tid & 1) * 8;
    int n4 = (tid & 31) * 4, kp = tid >> 5;
    const int NSTEP = Kd >> 4;

    // ldmatrix addresses (A non-trans, B trans k-major)
    int arow = (lane & 7) + ((lane >> 3) & 1) * 8;
    int akh = lane >> 4;
    uint32_t aAh[4], aAl[4];
    #pragma unroll
    for (int mf = 0; mf < 4; ++mf){
        int row = m0w + mf*16 + arow;
        aAh[mf] = s2u(Ah) + (uint32_t)((row*12 + akh*4)*4);
        aAl[mf] = s2u(Al) + (uint32_t)((row*12 + akh*4)*4);
    }
    int rl = lane & 15;
    uint32_t bwo = (uint32_t)((rl*68 + (n0w >> 1) + ((lane >> 4) << 2)) * 4);
    uint32_t aBh = s2u(Bh) + bwo;
    uint32_t aBl = s2u(Bl) + bwo;

    float va[8];
    float4 rb0, rb1;
    {   // prologue (st = 0)
        const float* ap = Ab + (LL)(m0 + am)*lda + ak8;
        *(float4*)&va[0] = *(const float4*)(ap);
        *(float4*)&va[4] = *(const float4*)(ap + 4);
        if (A2b){
            const float* a2p = A2b + (LL)(m0 + am)*lda + ak8;
            float4 w0 = *(const float4*)(a2p);
            float4 w1 = *(const float4*)(a2p + 4);
            float w[8] = {w0.x,w0.y,w0.z,w0.w,w1.x,w1.y,w1.z,w1.w};
            #pragma unroll
            for (int j=0;j<8;j++) va[j] = fmaf(-lamv, w[j], va[j]);
        }
        const float* bp = Bb + (LL)(kp*2)*ldb + n0 + n4;
        rb0 = *(const float4*)bp;
        rb1 = *(const float4*)(bp + ldb);
    }
    for (int st = 0; st < NSTEP; ++st){
        int buf = (st & 1) * 1536;
        int buf2 = (st & 1) * 1088;
        uint32_t bufb  = (uint32_t)(st & 1) * 6144u;
        uint32_t bufb2 = (uint32_t)(st & 1) * 4352u;
        int basea = buf + am*12 + (tid & 1)*4;
        #pragma unroll
        for (int j=0;j<4;j++){
            uint32_t hi, lo;
            split2(va[2*j], va[2*j+1], hi, lo);
            Ah[basea + j] = hi; Al[basea + j] = lo;
        }
        {
            uint32_t h00,l00,h01,l01,h10,l10,h11,l11;
            split2(rb0.x, rb0.y, h00, l00);
            split2(rb0.z, rb0.w, h01, l01);
            split2(rb1.x, rb1.y, h10, l10);
            split2(rb1.z, rb1.w, h11, l11);
            int r0 = buf2 + (kp*2)*68 + (n4 >> 1);
            *(uint2*)&Bh[r0]      = make_uint2(h00, h01);
            *(uint2*)&Bh[r0 + 68] = make_uint2(h10, h11);
            *(uint2*)&Bl[r0]      = make_uint2(l00, l01);
            *(uint2*)&Bl[r0 + 68] = make_uint2(l10, l11);
        }
        __syncthreads();
        if (st + 1 < NSTEP){
            int c = (st + 1) << 4;
            const float* ap = Ab + (LL)(m0 + am)*lda + c + ak8;
            *(float4*)&va[0] = *(const float4*)(ap);
            *(float4*)&va[4] = *(const float4*)(ap + 4);
            if (A2b){
                const float* a2p = A2b + (LL)(m0 + am)*lda + c + ak8;
                float4 w0 = *(const float4*)(a2p);
                float4 w1 = *(const float4*)(a2p + 4);
                float w[8] = {w0.x,w0.y,w0.z,w0.w,w1.x,w1.y,w1.z,w1.w};
                #pragma unroll
                for (int j=0;j<8;j++) va[j] = fmaf(-lamv, w[j], va[j]);
            }
            const float* bp = Bb + (LL)(c + kp*2)*ldb + n0 + n4;
            rb0 = *(const float4*)bp;
            rb1 = *(const float4*)(bp + ldb);
        }
        uint32_t bh[4][2], bl[4][2];
        ldsm4t(bh[0][0], bh[0][1], bh[1][0], bh[1][1], aBh + bufb2);
        ldsm4t(bh[2][0], bh[2][1], bh[3][0], bh[3][1], aBh + 32u + bufb2);
        ldsm4t(bl[0][0], bl[0][1], bl[1][0], bl[1][1], aBl + bufb2);
        ldsm4t(bl[2][0], bl[2][1], bl[3][0], bl[3][1], aBl + 32u + bufb2);
        #pragma unroll
        for (int mf = 0; mf < 4; ++mf){
            uint32_t ah0,ah1,ah2,ah3, al0,al1,al2,al3;
            ldsm4(ah0,ah1,ah2,ah3, aAh[mf] + bufb);
            ldsm4(al0,al1,al2,al3, aAl[mf] + bufb);
            #pragma unroll
            for (int nf = 0; nf < 4; ++nf){
                MMA_BF16(acc[mf][nf], ah0,ah1,ah2,ah3, bh[nf][0], bh[nf][1]);
                MMA_BF16(acc[mf][nf], ah0,ah1,ah2,ah3, bl[nf][0], bl[nf][1]);
                MMA_BF16(acc[mf][nf], al0,al1,al2,al3, bh[nf][0], bh[nf][1]);
            }
        }
        __syncthreads();
    }
    #pragma unroll
    for (int mf = 0; mf < 4; ++mf){
        int m = m0 + m0w + mf*16 + lr;
        #pragma unroll
        for (int nf = 0; nf < 4; ++nf){
            int n = n0 + n0w + nf*8 + lc*2;
            float b0 = bias ? bias[bias_stride*ko + n]   : 0.f;
            float b1 = bias ? bias[bias_stride*ko + n+1] : 0.f;
            float v00 = fmaf(alpha, acc[mf][nf][0], b0);
            float v01 = fmaf(alpha, acc[mf][nf][1], b1);
            float v10 = fmaf(alpha, acc[mf][nf][2], b0);
            float v11 = fmaf(alpha, acc[mf][nf][3], b1);
            Cb[(LL)m*c_m + (LL)n*c_n]         = v00;
            Cb[(LL)m*c_m + (LL)(n+1)*c_n]     = v01;
            Cb[(LL)(m+8)*c_m + (LL)n*c_n]     = v10;
            Cb[(LL)(m+8)*c_m + (LL)(n+1)*c_n] = v11;
            if (Cpb){
                Cpb[(LL)m*c_m + (LL)n*c_n]         = pack1(v00);
                Cpb[(LL)m*c_m + (LL)(n+1)*c_n]     = pack1(v01);
                Cpb[(LL)(m+8)*c_m + (LL)n*c_n]     = pack1(v10);
                Cpb[(LL)(m+8)*c_m + (LL)(n+1)*c_n] = pack1(v11);
            }
        }
    }
}

// ------- fused triple projection, conflict-free B, ldmatrix ------------------
__global__ void __launch_bounds__(256)
proj3_kernel(const float* __restrict__ A, LL a_z,
             const float* __restrict__ W0, LL wz0,
             const float* __restrict__ W1, LL wz1,
             const float* __restrict__ W2, LL wz2,
             int kodiv,
             const float* __restrict__ b0, const float* __restrict__ b1,
             const float* __restrict__ b2,
             float* __restrict__ C0, LL cz0,
             float* __restrict__ C1, LL cz1,
             float* __restrict__ C2, LL cz2,
             int N2)
{
    extern __shared__ uint32_t smp[];
    uint32_t* Ah = smp;                 // [128][68]
    uint32_t* Al = smp + 8704;
    uint32_t* Bh = smp + 17408;         // [2][16*68]
    uint32_t* Bl = smp + 19584;

    int z = blockIdx.y;
    int ko = z / kodiv;
    int tile = blockIdx.x;
    const float* Ab = A + (LL)z*a_z + (LL)tile*16384;
    int tid = threadIdx.x, lane = tid & 31, wid = tid >> 5;
    int m0w = (wid >> 2) * 64, n0w = (wid & 3) * 32;
    int lr = lane >> 2, lc = lane & 3;

    // ---- stage full A tile (split once) ----
    {
        int am = tid >> 1, koff = (tid & 1) * 64;
        const float* ap = Ab + (LL)am*128 + koff;
        int base = am*68 + (tid & 1)*32;
        #pragma unroll
        for (int g = 0; g < 8; ++g){
            float4 f0 = *(const float4*)(ap + g*8);
            float4 f1 = *(const float4*)(ap + g*8 + 4);
            float v[8] = {f0.x,f0.y,f0.z,f0.w,f1.x,f1.y,f1.z,f1.w};
            #pragma unroll
            for (int j = 0; j < 4; ++j){
                uint32_t hi, lo;
                split2(v[2*j], v[2*j+1], hi, lo);
                Ah[base + g*4 + j] = hi;
                Al[base + g*4 + j] = lo;
            }
        }
    }
    __syncthreads();

    const float* Ws[3] = {W0 + (LL)ko*wz0, W1 + (LL)ko*wz1, W2 + (LL)ko*wz2};
    const float* bs[3] = {b0, b1, b2};
    float* Cs[3];
    Cs[0] = C0 + (LL)z*cz0 + (LL)tile*16384;
    Cs[1] = C1 + (LL)z*cz1 + (LL)tile*16384;
    Cs[2] = C2 + (LL)z*cz2 + (LL)tile*128*N2;
    int Ns[3] = {128, 128, N2};
    int n4 = (tid & 31) * 4, kp = tid >> 5;

    // ldmatrix addresses
    int arow = (lane & 7) + ((lane >> 3) & 1) * 8;
    int akh = lane >> 4;
    uint32_t aAh[4], aAl[4];
    #pragma unroll
    for (int mf = 0; mf < 4; ++mf){
        int row = m0w + mf*16 + arow;
        aAh[mf] = s2u(Ah) + (uint32_t)((row*68 + akh*4)*4);
        aAl[mf] = s2u(Al) + (uint32_t)((row*68 + akh*4)*4);
    }
    int rl = lane & 15;
    uint32_t bwo = (uint32_t)((rl*68 + (n0w >> 1) + ((lane >> 4) << 2)) * 4);
    uint32_t aBh = s2u(Bh) + bwo;
    uint32_t aBl = s2u(Bl) + bwo;

    for (int w = 0; w < 3; ++w){
        const float* Wb = Ws[w];
        int Nw = Ns[w];
        bool act = n4 < Nw;
        float acc[4][4][4];
        #pragma unroll
        for (int i=0;i<4;i++)
            #pragma unroll
            for (int j=0;j<4;j++)
                #pragma unroll
                for (int q=0;q<4;q++) acc[i][j][q]=0.f;

        float4 r0, r1;
        if (act){
            const float* bp0 = Wb + (LL)(kp*2)*Nw + n4;
            r0 = *(const float4*)bp0;
            r1 = *(const float4*)(bp0 + Nw);
        }
        for (int st = 0; st < 8; ++st){
            int buf2 = (st & 1) * 1088;
            uint32_t bufb2 = (uint32_t)(st & 1) * 4352u;
            if (act){
                uint32_t h00,l00,h01,l01,h10,l10,h11,l11;
                split2(r0.x, r0.y, h00, l00);
                split2(r0.z, r0.w, h01, l01);
                split2(r1.x, r1.y, h10, l10);
                split2(r1.z, r1.w, h11, l11);
                int rr = buf2 + (kp*2)*68 + (n4 >> 1);
                *(uint2*)&Bh[rr]      = make_uint2(h00, h01);
                *(uint2*)&Bh[rr + 68] = make_uint2(h10, h11);
                *(uint2*)&Bl[rr]      = make_uint2(l00, l01);
                *(uint2*)&Bl[rr + 68] = make_uint2(l10, l11);
            }
            __syncthreads();
            if (st < 7 && act){
                int c = (st + 1) << 4;
                const float* bp0 = Wb + (LL)(c + kp*2)*Nw + n4;
                r0 = *(const float4*)bp0;
                r1 = *(const float4*)(bp0 + Nw);
            }
            uint32_t bh[4][2], bl[4][2];
            ldsm4t(bh[0][0], bh[0][1], bh[1][0], bh[1][1], aBh + bufb2);
            ldsm4t(bh[2][0], bh[2][1], bh[3][0], bh[3][1], aBh + 32u + bufb2);
            ldsm4t(bl[0][0], bl[0][1], bl[1][0], bl[1][1], aBl + bufb2);
            ldsm4t(bl[2][0], bl[2][1], bl[3][0], bl[3][1], aBl + 32u + bufb2);
            uint32_t stb = (uint32_t)st * 32u;
            #pragma unroll
            for (int mf = 0; mf < 4; ++mf){
                uint32_t ah0,ah1,ah2,ah3, al0,al1,al2,al3;
                ldsm4(ah0,ah1,ah2,ah3, aAh[mf] + stb);
                ldsm4(al0,al1,al2,al3, aAl[mf] + stb);
                #pragma unroll
                for (int nf = 0; nf < 4; ++nf){
                    MMA_BF16(acc[mf][nf], ah0,ah1,ah2,ah3, bh[nf][0], bh[nf][1]);
                    MMA_BF16(acc[mf][nf], ah0,ah1,ah2,ah3, bl[nf][0], bl[nf][1]);
                    MMA_BF16(acc[mf][nf], al0,al1,al2,al3, bh[nf][0], bh[nf][1]);
                }
            }
            __syncthreads();
        }
        const float* bw = bs[w];
        float* Cw = Cs[w];
        #pragma unroll
        for (int mf = 0; mf < 4; ++mf){
            int m = m0w + mf*16 + lr;
            #pragma unroll
            for (int nf = 0; nf < 4; ++nf){
                int n = n0w + nf*8 + lc*2;
                if (n < Nw){
                    float bb0 = bw ? bw[n]   : 0.f;
                    float bb1 = bw ? bw[n+1] : 0.f;
                    Cw[(LL)m*Nw + n]       = acc[mf][nf][0] + bb0;
                    Cw[(LL)m*Nw + n+1]     = acc[mf][nf][1] + bb1;
                    Cw[(LL)(m+8)*Nw + n]   = acc[mf][nf][2] + bb0;
                    Cw[(LL)(m+8)*Nw + n+1] = acc[mf][nf][3] + bb1;
                }
            }
        }
    }
}

// ------------- flash-fused scores + online softmax/stats + AV ----------------
__global__ void __launch_bounds__(128)
flash_kernel(const float* __restrict__ qg, const float* __restrict__ kg,
             const float* __restrict__ vg, float* __restrict__ o1,
             float* __restrict__ o2, float* __restrict__ rs)
{
    extern __shared__ uint32_t sm[];
    uint32_t* Qh = sm;              // [128][36]
    uint32_t* Ql = Qh + 4608;
    uint32_t* Kh = Ql + 4608;       // [32][36]
    uint32_t* Kl = Kh + 1152;
    uint32_t* Vh = Kl + 1152;       // [64][20]
    uint32_t* Vl = Vh + 1280;

    int kb = blockIdx.y, half = blockIdx.z;
    int row0 = blockIdx.x * 128;
    const float* qb  = qg + (LL)kb*65536 + half*64;
    const float* kp_ = kg + (LL)kb*65536 + half*64;
    const float* vb  = vg + (LL)kb*32768;
    int tid = threadIdx.x, lane = tid & 31, wid = tid >> 5;
    int m0w = wid * 32;
    int lr = lane >> 2, lc = lane & 3;

    {
        const float* qr = qb + (LL)(row0 + tid)*128;
        #pragma unroll
        for (int g = 0; g < 16; ++g){
            float4 f = *(const float4*)(qr + g*4);
            uint32_t h0,l0,h1,l1;
            split2(f.x, f.y, h0, l0);
            split2(f.z, f.w, h1, l1);
            int p = tid*36 + g*2;
            Qh[p] = h0; Ql[p] = l0; Qh[p+1] = h1; Ql[p+1] = l1;
        }
    }

    float m2[2][2], dn[2][2], qq[2][2], vmn[2][2];
    #pragma unroll
    for (int a=0;a<2;a++)
        #pragma unroll
        for (int b2=0;b2<2;b2++){ m2[a][b2]=-1e30f; dn[a][b2]=0.f; qq[a][b2]=0.f; vmn[a][b2]=1e30f; }
    float o[2][8][4];
    #pragma unroll
    for (int a=0;a<2;a++)
        #pragma unroll
        for (int b2=0;b2<8;b2++)
            #pragma unroll
            for (int cql=0;cql<4;cql++) o[a][b2][cql]=0.f;

    for (int jt = 0; jt < 512; jt += 32){
        __syncthreads();
        {
            int j = tid >> 2, ds = (tid & 3) * 16;
            const float* kr = kp_ + (LL)(jt + j)*128 + ds;
            #pragma unroll
            for (int g = 0; g < 4; ++g){
                float4 f = *(const float4*)(kr + g*4);
                uint32_t h0,l0,h1,l1;
                split2(f.x,f.y,h0,l0); split2(f.z,f.w,h1,l1);
                int p = j*36 + (ds>>1) + g*2;
                Kh[p]=h0; Kl[p]=l0; Kh[p+1]=h1; Kl[p+1]=l1;
            }
        }
        {
            int jp = tid & 15, ds = (tid >> 4) * 8;
            const float* v0 = vb + (LL)(jt + jp*2)*64 + ds;
            #pragma unroll
            for (int g = 0; g < 8; ++g){
                uint32_t h,l;
                split2(v0[g], v0[64+g], h, l);
                Vh[(ds+g)*20 + jp] = h; Vl[(ds+g)*20 + jp] = l;
            }
        }
        __syncthreads();
        float s[2][4][4];
        #pragma unroll
        for (int a=0;a<2;a++)
            #pragma unroll
            for (int b2=0;b2<4;b2++)
                #pragma unroll
                for (int cql=0;cql<4;cql++) s[a][b2][cql]=0.f;
        #pragma unroll
        for (int kc = 0; kc < 4; ++kc){
            #pragma unroll
            for (int mf = 0; mf < 2; ++mf){
                int ra = (m0w + mf*16 + lr)*36 + kc*8 + lc;
                uint32_t ah0=Qh[ra], ah1=Qh[ra+288], ah2=Qh[ra+4], ah3=Qh[ra+292];
                uint32_t al0=Ql[ra], al1=Ql[ra+288], al2=Ql[ra+4], al3=Ql[ra+292];
                #pragma unroll
                for (int nf = 0; nf < 4; ++nf){
                    int rb = (nf*8 + lr)*36 + kc*8 + lc;
                    uint32_t bh0=Kh[rb], bh1=Kh[rb+4];
                    uint32_t bl0=Kl[rb], bl1=Kl[rb+4];
                    MMA_BF16(s[mf][nf], ah0,ah1,ah2,ah3, bh0,bh1);
                    MMA_BF16(s[mf][nf], ah0,ah1,ah2,ah3, bl0,bl1);
                    MMA_BF16(s[mf][nf], al0,al1,al2,al3, bh0,bh1);
                }
            }
        }
        #pragma unroll
        for (int mf = 0; mf < 2; ++mf){
            #pragma unroll
            for (int rh = 0; rh < 2; ++rh){
                float cmax = -1e30f, cmin = 1e30f;
                #pragma unroll
                for (int nf = 0; nf < 4; ++nf){
                    float e0 = s[mf][nf][rh*2]   * 0.25f;
                    float e1 = s[mf][nf][rh*2+1] * 0.25f;
                    s[mf][nf][rh*2] = e0; s[mf][nf][rh*2+1] = e1;
                    cmax = fmaxf(cmax, fmaxf(e0,e1));
                    cmin = fminf(cmin, fminf(e0,e1));
                }
                cmax = fmaxf(cmax, __shfl_xor_sync(0xffffffffu, cmax, 1));
                cmax = fmaxf(cmax, __shfl_xor_sync(0xffffffffu, cmax, 2));
                cmin = fminf(cmin, __shfl_xor_sync(0xffffffffu, cmin, 1));
                cmin = fminf(cmin, __shfl_xor_sync(0xffffffffu, cmin, 2));
                float mold = m2[mf][rh];
                float mnew = fmaxf(mold, cmax);
                bool upd = (mnew > mold);
                float rsum = 0.f, rsq = 0.f;
                #pragma unroll
                for (int nf = 0; nf < 4; ++nf){
                    float p0 = __expf(s[mf][nf][rh*2]   - mnew);
                    float p1 = __expf(s[mf][nf][rh*2+1] - mnew);
                    s[mf][nf][rh*2] = p0; s[mf][nf][rh*2+1] = p1;
                    rsum += p0 + p1;
                    rsq  += p0*p0 + p1*p1;
                }
                rsum += __shfl_xor_sync(0xffffffffu, rsum, 1);
                rsum += __shfl_xor_sync(0xffffffffu, rsum, 2);
                rsq  += __shfl_xor_sync(0xffffffffu, rsq, 1);
                rsq  += __shfl_xor_sync(0xffffffffu, rsq, 2);
                if (__any_sync(0xffffffffu, upd)){
                    float scale = __expf(mold - mnew);
                    dn[mf][rh] = dn[mf][rh]*scale + rsum;
                    qq[mf][rh] = qq[mf][rh]*scale*scale + rsq;
                    m2[mf][rh] = mnew;
                    #pragma unroll
                    for (int nfd = 0; nfd < 8; ++nfd){
                        o[mf][nfd][rh*2]   *= scale;
                        o[mf][nfd][rh*2+1] *= scale;
                    }
                } else {
                    dn[mf][rh] += rsum;
                    qq[mf][rh] += rsq;
                }
                vmn[mf][rh] = fminf(vmn[mf][rh], cmin);
            }
        }
        #pragma unroll
        for (int mf = 0; mf < 2; ++mf){
            #pragma unroll
            for (int kc2 = 0; kc2 < 2; ++kc2){
                uint32_t ah0,al0,ah1,al1,ah2,al2,ah3,al3;
                split2(s[mf][2*kc2][0],   s[mf][2*kc2][1],   ah0, al0);
                split2(s[mf][2*kc2][2],   s[mf][2*kc2][3],   ah1, al1);
                split2(s[mf][2*kc2+1][0], s[mf][2*kc2+1][1], ah2, al2);
                split2(s[mf][2*kc2+1][2], s[mf][2*kc2+1][3], ah3, al3);
                #pragma unroll
                for (int nfd = 0; nfd < 8; ++nfd){
                    int rb = (nfd*8 + lr)*20 + kc2*8 + lc;
                    uint32_t bh0=Vh[rb], bh1=Vh[rb+4];
                    uint32_t bl0=Vl[rb], bl1=Vl[rb+4];
                    MMA_BF16(o[mf][nfd], ah0,ah1,ah2,ah3, bh0,bh1);
                    MMA_BF16(o[mf][nfd], ah0,ah1,ah2,ah3, bl0,bl1);
                    MMA_BF16(o[mf][nfd], al0,al1,al2,al3, bh0,bh1);
                }
            }
        }
    }
    float* op = (half == 0 ? o1 : o2) + (LL)kb*32768;
    #pragma unroll
    for (int mf = 0; mf < 2; ++mf){
        #pragma unroll
        for (int rh = 0; rh < 2; ++rh){
            float inv = 1.f / dn[mf][rh];
            int r = row0 + m0w + mf*16 + lr + rh*8;
            #pragma unroll
            for (int nfd = 0; nfd < 8; ++nfd){
                o[mf][nfd][rh*2]   *= inv;
                o[mf][nfd][rh*2+1] *= inv;
            }
            if (lc == 0){
                float* rp = rs + ((LL)(half*120 + kb)*512 + r)*4;
                rp[0] = 1.0f;
                rp[1] = qq[mf][rh]*inv*inv;
                rp[2] = inv;
                rp[3] = __expf(vmn[mf][rh] - m2[mf][rh]) * inv;
            }
            float* orow = op + (LL)r*64 + lc*2;
            #pragma unroll
            for (int nfd = 0; nfd < 8; ++nfd){
                orow[nfd*8]   = o[mf][nfd][rh*2];
                orow[nfd*8+1] = o[mf][nfd][rh*2+1];
            }
        }
    }
}

// --------------------- per-(half,kb) stat aggregation ------------------------
__global__ void stats_finalize_kernel(const float* __restrict__ rs, float* __restrict__ st){
    __shared__ float sred[4];
    int hb = blockIdx.x;
    const float* r = rs + (LL)hb*512*4;
    int tid = threadIdx.x;
    float s=0.f,q=0.f,mx=-1e30f,mn=1e30f;
    for (int i = tid; i < 512; i += 128){
        s += r[i*4+0]; q += r[i*4+1];
        mx = fmaxf(mx, r[i*4+2]); mn = fminf(mn, r[i*4+3]);
    }
    s = bred(s,sred,0); q = bred(q,sred,0);
    mx = bred(mx,sred,1); mn = bred(mn,sred,2);
    if (tid == 0){
        float* o = st + hb*4;
        o[0]=s; o[1]=q; o[2]=mx; o[3]=mn;
    }
}

// ------------------------------- lambda MLP ---------------------------------
__global__ void lambda_kernel(const float* __restrict__ st,
                              const float* __restrict__ lw1, const float* __restrict__ lb1,
                              const float* __restrict__ lw2, const float* __restrict__ lb2,
                              float* __restrict__ lam){
    int kb = threadIdx.x;
    if (kb >= 120) return;
    int k = kb >> 2;
    const float M2 = 262144.f;
    float s8[8];
    #pragma unroll
    for (int h2 = 0; h2 < 2; ++h2){
        const float* sp = st + (h2*120 + kb)*4;
        float sum = sp[0], sq = sp[1];
        s8[h2*4+0] = sum / M2;
        float var = (sq - sum*sum/M2) / (M2 - 1.f);
        s8[h2*4+1] = sqrtf(fmaxf(var, 0.f));
        s8[h2*4+2] = sp[2];
        s8[h2*4+3] = sp[3];
    }
    float z = lb2[k];
    for (int o = 0; o < 16; ++o){
        float h = lb1[k*16+o];
        #pragma unroll
        for (int i = 0; i < 8; ++i) h = fmaf(s8[i], lw1[(k*8+i)*16+o], h);
        h = fmaxf(h, 0.f);
        z = fmaf(h, lw2[k*16+o], z);
    }
    lam[kb] = 1.f/(1.f + expf(-z));
}

// ------------- combined multiscale conv weights -> packed bf16 hi/lo ---------
__global__ void combine_wc_kernel(const float* __restrict__ fw,
    const float* cwA, const float* cwB, const float* cwC, const float* cwD, const float* cwE,
    const float* cbA, const float* cbB, const float* cbC, const float* cbD, const float* cbE,
    uint32_t* __restrict__ wch, uint32_t* __restrict__ wcl, float* __restrict__ bc){
    int idx = blockIdx.x*256 + threadIdx.x;
    if (idx >= 491520) return;
    int k = idx >> 14;
    int rem = idx & 16383;
    int n = rem >> 7, m = rem & 127;
    int base = (k <= 5) ? 2 : (k <= 14) ? 1 : 0;
    int taps, shift; LL woff;
    band_cfg(k, taps, shift, woff);
    int half = taps >> 1;
    float f0 = fw[k*3+0], f1 = fw[k*3+1], f2 = fw[k*3+2];
    float fm = fmaxf(f0, fmaxf(f1, f2));
    float e0 = expf(f0-fm), e1 = expf(f1-fm), e2 = expf(f2-fm);
    float den = e0+e1+e2;
    float sw[3] = {e0/den, e1/den, e2/den};
    const float* cws[5] = {cwA,cwB,cwC,cwD,cwE};
    const float* cbs[5] = {cbA,cbB,cbC,cbD,cbE};
    const int ss[5] = {2,4,8,16,32};
    LL wp = woff >> 1;
    float prev = 0.f;
    for (int u = 0; u < taps; ++u){
        int tau = u - half;
        float a = 0.f;
        #pragma unroll
        for (int j = 0; j < 3; ++j){
            int slot = base + j;
            int sc = ss[slot], h2 = sc >> 1;
            if (tau >= -h2 && tau < h2)
                a = fmaf(sw[j], cws[slot][((LL)n*128 + m)*sc + tau + h2], a);
        }
        if ((u & 1) == 0) prev = a;
        else {
            uint32_t hi, lo;
            split2(prev, a, hi, lo);
            int kk = m*taps + u - 1;
            int stp = kk >> 4;
            int kp = (kk >> 1) & 7;
            LL widx = wp + (LL)stp*1024 + n*8 + kp;
            wch[widx] = hi; wcl[widx] = lo;
        }
    }
    if (m == 0){
        float bcv = 0.f;
        #pragma unroll
        for (int j = 0; j < 3; ++j) bcv = fmaf(sw[j], cbs[base+j][n], bcv);
        bc[k*128+n] = bcv;
    }
}

// -------- pipelined mma.sync bf16 conv (ldmatrix fragments) ------------------
__global__ void __launch_bounds__(256)
convgemm_mma(const uint32_t* __restrict__ wch, const uint32_t* __restrict__ wcl,
             const float* __restrict__ bc, const uint32_t* __restrict__ xp2,
             float* __restrict__ xg)
{
    extern __shared__ uint32_t smc[];
    uint32_t* Ah = smc;            // [2][1536]
    uint32_t* Al = smc + 3072;
    uint32_t* Bh = smc + 6144;
    uint32_t* Bl = smc + 9216;
    int z = (int)((blockIdx.y * 49u) % 120u);
    int b = z / 30, k = z - b*30;
    int taps, shift; LL woff;
    band_cfg(k, taps, shift, woff);
    const int NC = taps << 3;
    const int half = taps >> 1;
    const int mask = taps - 1;
    const uint32_t* Abh = wch + (woff >> 1);
    const uint32_t* Abl = wcl + (woff >> 1);
    const uint32_t* xpz = xp2 + (LL)z*65536;
    int t0 = blockIdx.x * 128;
    int tid = threadIdx.x;
    int lane = tid & 31, wid = tid >> 5;
    int m0w = (wid >> 2) * 64, n0w = (wid & 3) * 32;
    int lr = lane >> 2, lc = lane & 3;

    float acc[4][4][4];
    #pragma unroll
    for (int i=0;i<4;i++)
        #pragma unroll
        for (int j=0;j<4;j++)
            #pragma unroll
            for (int q=0;q<4;q++) acc[i][j][q]=0.f;

    int am = tid >> 1, akp = (tid & 1) * 4;
    int bkp = tid & 7, btq = tid >> 3;

    int arow = (lane & 7) + ((lane >> 3) & 1) * 8;
    int akh = lane >> 4;
    uint32_t aAh[4], aAl[4];
    #pragma unroll
    for (int mf = 0; mf < 4; ++mf){
        int row = m0w + mf*16 + arow;
        aAh[mf] = s2u(Ah) + (uint32_t)((row*12 + akh*4)*4);
        aAl[mf] = s2u(Al) + (uint32_t)((row*12 + akh*4)*4);
    }
    int brow = n0w + (lane >> 4)*8 + (lane & 7);
    int bkh = (lane >> 3) & 1;
    uint32_t aBh = s2u(Bh) + (uint32_t)((brow*12 + bkh*4)*4);
    uint32_t aBl = s2u(Bl) + (uint32_t)((brow*12 + bkh*4)*4);

    uint4 a4h, a4l;
    uint32_t bhv[4], blv[4];
    {
        a4h = *(const uint4*)(Abh + tid*4);
        a4l = *(const uint4*)(Abl + tid*4);
        int kk = bkp*2;
        int mi = kk >> shift, u0 = kk & mask;
        const uint32_t* src = xpz + (LL)mi*512;
        int off = u0 - half;
        #pragma unroll
        for (int i = 0; i < 4; ++i){
            int t = btq*4 + i;
            int p0 = t0 + t + off;
            uint32_t w0 = ((unsigned)p0 < 512u) ? src[p0] : 0u;
            uint32_t w1 = ((unsigned)(p0+1) < 512u) ? src[p0+1] : 0u;
            bhv[i] = __byte_perm(w0, w1, 0x5410);
            blv[i] = __byte_perm(w0, w1, 0x7632);
        }
    }
    for (int st = 0; st < NC; ++st){
        int buf = (st & 1) * 1536;
        uint32_t bufb = (uint32_t)(st & 1) * 6144u;
        *(uint4*)&Ah[buf + am*12 + akp] = a4h;
        *(uint4*)&Al[buf + am*12 + akp] = a4l;
        #pragma unroll
        for (int i = 0; i < 4; ++i){
            int t = btq*4 + i;
            Bh[buf + t*12 + bkp] = bhv[i];
            Bl[buf + t*12 + bkp] = blv[i];
        }
        __syncthreads();
        if (st + 1 < NC){
            int stn = st + 1;
            a4h = *(const uint4*)(Abh + (LL)stn*1024 + tid*4);
            a4l = *(const uint4*)(Abl + (LL)stn*1024 + tid*4);
            int kk = (stn << 4) + bkp*2;
            int mi = kk >> shift, u0 = kk & mask;
            const uint32_t* src = xpz + (LL)mi*512;
            int off = u0 - half;
            #pragma unroll
            for (int i = 0; i < 4; ++i){
                int t = btq*4 + i;
                int p0 = t0 + t + off;
                uint32_t w0 = ((unsigned)p0 < 512u) ? src[p0] : 0u;
                uint32_t w1 = ((unsigned)(p0+1) < 512u) ? src[p0+1] : 0u;
                bhv[i] = __byte_perm(w0, w1, 0x5410);
                blv[i] = __byte_perm(w0, w1, 0x7632);
            }
        }
        uint32_t bh[4][2], bl[4][2];
        ldsm4(bh[0][0], bh[0][1], bh[1][0], bh[1][1], aBh + bufb);
        ldsm4(bh[2][0], bh[2][1], bh[3][0], bh[3][1], aBh + 768u + bufb);
        ldsm4(bl[0][0], bl[0][1], bl[1][0], bl[1][1], aBl + bufb);
        ldsm4(bl[2][0], bl[2][1], bl[3][0], bl[3][1], aBl + 768u + bufb);
        #pragma unroll
        for (int mf = 0; mf < 4; ++mf){
            uint32_t ah0,ah1,ah2,ah3, al0,al1,al2,al3;
            ldsm4(ah0,ah1,ah2,ah3, aAh[mf] + bufb);
            ldsm4(al0,al1,al2,al3, aAl[mf] + bufb);
            #pragma unroll
            for (int nf = 0; nf < 4; ++nf){
                MMA_BF16(acc[mf][nf], ah0,ah1,ah2,ah3, bh[nf][0], bh[nf][1]);
                MMA_BF16(acc[mf][nf], ah0,ah1,ah2,ah3, bl[nf][0], bl[nf][1]);
                MMA_BF16(acc[mf][nf], al0,al1,al2,al3, bh[nf][0], bh[nf][1]);
            }
        }
    }
    #pragma unroll
    for (int mf = 0; mf < 4; ++mf){
        int m = m0w + mf*16 + lr;
        float bc0 = bc[k*128 + m];
        float bc1 = bc[k*128 + m + 8];
        #pragma unroll
        for (int nf = 0; nf < 4; ++nf){
            int t = t0 + n0w + nf*8 + lc*2;
            LL base = ((LL)((b*512 + t)*30 + k)) * 128;
            xg[base + m]          = acc[mf][nf][0] + bc0;
            xg[base + 3840 + m]   = acc[mf][nf][1] + bc0;
            xg[base + m + 8]      = acc[mf][nf][2] + bc1;
            xg[base + 3840 + m+8] = acc[mf][nf][3] + bc1;
        }
    }
}

// ------------------------------- adjacency ----------------------------------
__global__ void adj_kernel(const float* __restrict__ be, float* __restrict__ adj){
    __shared__ float e[30][64];
    __shared__ float sim[30][30];
    __shared__ float Ar[30][30];
    int tid = threadIdx.x;
    for (int i = tid; i < 30; i += 256){
        float s = 0.f;
        for (int d = 0; d < 64; ++d){ float v = be[i*64+d]; s += v*v; }
        float inv = 1.f/(sqrtf(s)+1e-8f);
        for (int d = 0; d < 64; ++d) e[i][d] = be[i*64+d]*inv;
    }
    __syncthreads();
    for (int p = tid; p < 900; p += 256){
        int i = p/30, j = p - (p/30)*30;
        float s = 0.f;
        for (int d = 0; d < 64; ++d) s = fmaf(e[i][d], e[j][d], s);
        sim[i][j] = s; Ar[i][j] = 0.f;
    }
    __syncthreads();
    if (tid < 30){
        bool taken[30];
        for (int j = 0; j < 30; ++j) taken[j] = false;
        for (int r = 0; r < 5; ++r){
            int bi = 0; float bvv = -1e30f;
            for (int j = 0; j < 30; ++j)
                if (!taken[j] && sim[tid][j] > bvv){ bvv = sim[tid][j]; bi = j; }
            taken[bi] = true;
            Ar[tid][bi] = bvv;
        }
    }
    __syncthreads();
    for (int p = tid; p < 900; p += 256){
        int i = p/30, j = p - (p/30)*30;
        adj[p] = 0.5f*(Ar[i][j] + Ar[j][i]);
    }
}

// --------------------------- graph attention core ---------------------------
__global__ void gattn_kernel(const float* __restrict__ qg, const float* __restrict__ kg,
                             const float* __restrict__ vg, const float* __restrict__ adj,
                             float* __restrict__ outp){
    __shared__ float sq[4][30][32];
    __shared__ float sv[4][30][32];
    __shared__ float sadj[30][30];
    __shared__ float sat[4][32];
    LL m = blockIdx.x;
    int tid = threadIdx.x, h = tid >> 5, lane = tid & 31;
    for (int i = tid; i < 3840; i += 128){
        int r = i >> 7, c = i & 127;
        sq[c>>5][r][c&31] = qg[m*3840 + i];
        sv[c>>5][r][c&31] = vg[m*3840 + i];
    }
    for (int i = tid; i < 900; i += 128) sadj[i/30][i - (i/30)*30] = adj[i];
    float kreg[32];
    if (lane < 30){
        #pragma unroll
        for (int d = 0; d < 32; ++d) kreg[d] = kg[m*3840 + lane*128 + h*32 + d];
    } else {
        #pragma unroll
        for (int d = 0; d < 32; ++d) kreg[d] = 0.f;
    }
    __syncthreads();
    const float invs = 0.17677669529663687f;
    float* orow = outp + m*3840;
    for (int i = 0; i < 30; ++i){
        float qv = sq[h][i][lane];
        float d = 0.f;
        #pragma unroll
        for (int dd = 0; dd < 32; ++dd)
            d = fmaf(__shfl_sync(0xffffffffu, qv, dd), kreg[dd], d);
        bool valid = (lane < 30) && (sadj[i][lane] != 0.f);
        float sc = valid ? d*invs : -1e30f;
        float mx = sc;
        #pragma unroll
        for (int o=16;o;o>>=1) mx = fmaxf(mx, __shfl_xor_sync(0xffffffffu, mx, o));
        float e = valid ? expf(sc - mx) : 0.f;
        float s = e;
        #pragma unroll
        for (int o=16;o;o>>=1) s += __shfl_xor_sync(0xffffffffu, s, o);
        float at = (s > 0.f) ? e/s : 0.f;
        sat[h][lane] = at;
        __syncwarp();
        float o = 0.f;
        for (int j = 0; j < 30; ++j) o = fmaf(sat[h][j], sv[h][j][lane], o);
        orow[i*128 + h*32 + lane] = o;
        __syncwarp();
    }
}

// ------------------------------ output transpose -----------------------------
__global__ void transpose_out_kernel(const float* __restrict__ og, float* __restrict__ out){
    __shared__ float s[30*129 + 32];
    int t = blockIdx.x, b = blockIdx.y;
    const float* src = og + (LL)(b*512 + t)*3840;
    for (int i = threadIdx.x; i < 3840; i += 256){
        int k = i >> 7, n = i & 127;
        s[k*129 + n] = src[i];
    }
    __syncthreads();
    float* dst = out + (LL)b*1966080 + (LL)t*30;
    for (int i = threadIdx.x; i < 3840; i += 256){
        int n = i / 30, k = i - n*30;
        dst[(LL)n*15360 + k] = s[k*129 + n];
    }
}

// ----------------------------------- launch ----------------------------------
extern "C" void kernel_launch(void* const* d_in, const int* in_sizes, int n_in,
                              void* d_out, int out_size) {
    const float* x   = (const float*)d_in[0];
    const float* Wq  = (const float*)d_in[1];
    const float* Wk  = (const float*)d_in[2];
    const float* Wv  = (const float*)d_in[3];
    const float* Wo  = (const float*)d_in[4];
    const float* bo  = (const float*)d_in[5];
    const float* lw1 = (const float*)d_in[6];
    const float* lb1 = (const float*)d_in[7];
    const float* lw2 = (const float*)d_in[8];
    const float* lb2 = (const float*)d_in[9];
    const float* cw2 = (const float*)d_in[10];
    const float* cb2 = (const float*)d_in[11];
    const float* cw4 = (const float*)d_in[12];
    const float* cb4 = (const float*)d_in[13];
    const float* cw8 = (const float*)d_in[14];
    const float* cb8 = (const float*)d_in[15];
    const float* cw16= (const float*)d_in[16];
    const float* cb16= (const float*)d_in[17];
    const float* cw32= (const float*)d_in[18];
    const float* cb32= (const float*)d_in[19];
    const float* fw  = (const float*)d_in[20];
    const float* be  = (const float*)d_in[21];
    const float* gWq = (const float*)d_in[22];
    const float* gbq = (const float*)d_in[23];
    const float* gWk = (const float*)d_in[24];
    const float* gbk = (const float*)d_in[25];
    const float* gWv = (const float*)d_in[26];
    const float* gbv = (const float*)d_in[27];
    const float* gWo = (const float*)d_in[28];
    const float* gbo = (const float*)d_in[29];
    float* out = (float*)d_out;

    void *xb,*q,*k_,*v,*S,*rs,*st,*lam,*xm,*wch,*wcl,*xp2,*bc,*xg,*adj;
    cudaGetSymbolAddress(&xb, g_xb);  cudaGetSymbolAddress(&q,  g_q);
    cudaGetSymbolAddress(&k_, g_k);   cudaGetSymbolAddress(&v,  g_v);
    cudaGetSymbolAddress(&S,  g_S);   cudaGetSymbolAddress(&rs, g_rs);
    cudaGetSymbolAddress(&st, g_st);  cudaGetSymbolAddress(&lam,g_lam);
    cudaGetSymbolAddress(&xm, g_xm);
    cudaGetSymbolAddress(&wch,g_wch); cudaGetSymbolAddress(&wcl,g_wcl);
    cudaGetSymbolAddress(&xp2,g_xp2); cudaGetSymbolAddress(&bc, g_bc);
    cudaGetSymbolAddress(&xg, g_xg);  cudaGetSymbolAddress(&adj,g_adj);

    float* o1 = (float*)S;
    float* o2 = (float*)S + 3932160;

    cudaFuncSetAttribute(flash_kernel, cudaFuncAttributeMaxDynamicSharedMemorySize, 57344);
    cudaFuncSetAttribute(proj3_kernel, cudaFuncAttributeMaxDynamicSharedMemorySize, 87040);
    cudaFuncSetAttribute(mgemm_p, cudaFuncAttributeMaxDynamicSharedMemorySize, 49152);
    cudaFuncSetAttribute(convgemm_mma, cudaFuncAttributeMaxDynamicSharedMemorySize, 49152);

    transpose_x_kernel<<<dim3(512,4), 256>>>(x, (float*)xb);
    combine_wc_kernel<<<1920, 256>>>(fw, cw2,cw4,cw8,cw16,cw32,
                                     cb2,cb4,cb8,cb16,cb32,
                                     (uint32_t*)wch, (uint32_t*)wcl, (float*)bc);
    adj_kernel<<<1, 256>>>(be, (float*)adj);

    // band q/k/v projections fused
    proj3_kernel<<<dim3(4,120), 256, 87040>>>((const float*)xb, 65536LL,
        Wq, 16384LL, Wk, 16384LL, Wv, 8192LL, 4,
        nullptr, nullptr, nullptr,
        (float*)q, 65536LL, (float*)k_, 65536LL, (float*)v, 32768LL, 64);

    // flash: scores + online softmax/stats + AV
    flash_kernel<<<dim3(4,120,2), 128, 57344>>>((const float*)q, (const float*)k_,
                                                (const float*)v, o1, o2, (float*)rs);

    stats_finalize_kernel<<<240,128>>>((const float*)rs, (float*)st);
    lambda_kernel<<<1,128>>>((const float*)st, lw1, lb1, lw2, lb2, (float*)lam);

    // (o1 - lam*o2) @ Wo + bo -> xm  (DIFF fused; packed bf16 written too)
    mgemm_p<<<dim3(1,4,120),256,41984>>>(o1, o2, (const float*)lam, Wo, bo,
        (float*)xm, (uint32_t*)xp2, 64, 4, 131072LL, 32768LL, 64,
        8192LL, 0LL, 128, 65536LL, 1966080LL, 1, 512, 128, 1.f);

    convgemm_mma<<<dim3(4,120), 256, 49152>>>((const uint32_t*)wch, (const uint32_t*)wcl,
                                              (const float*)bc, (const uint32_t*)xp2, (float*)xg);

    // graph q/k/v projections fused
    proj3_kernel<<<dim3(480,1), 256, 87040>>>((const float*)xg, 0LL,
        gWq, 0LL, gWk, 0LL, gWv, 0LL, 1,
        gbq, gbk, gbv,
        (float*)q, 0LL, (float*)k_, 0LL, (float*)xb, 0LL, 128);

    gattn_kernel<<<2048,128>>>((const float*)q, (const float*)k_, (const float*)xb,
                               (const float*)adj, (float*)xg);

    mgemm_p<<<dim3(1,480,1),256,41984>>>((const float*)xg, nullptr, nullptr, gWo, gbo,
        (float*)xm, nullptr, 128, 1, 0LL, 0LL, 128,
        0LL, 0LL, 128, 0LL, 0LL, 128, 1, 0, 1.f);

    transpose_out_kernel<<<dim3(512,4),256>>>((const float*)xm, out);
}

// round 16
// speedup vs baseline: 1.1910x; 1.0104x over previous
#include <cuda_runtime.h>
#include <cuda_bf16.h>
#include <cstdint>

typedef long long LL;

// ------------------------------- scratch ------------------------------------
__device__ float g_xb[7864320];   // [kb=k*4+b][t][n]   (reused as vg)
__device__ float g_q [7864320];   // [kb][t][128]       (reused as qg)
__device__ float g_k [7864320];   // [kb][t][128]       (reused as kg)
__device__ float g_v [3932160];   // [kb][t][64]
__device__ float g_S [62914560];  // o1 / o2 flash outputs
__device__ float g_rs[491520];
__device__ float g_st[960];
__device__ float g_lam[120];
__device__ float g_xm[7864320];   // [b][k][n][t]       (reused as og)
__device__ uint32_t g_wch[3735552];
__device__ uint32_t g_wcl[3735552];
__device__ uint32_t g_xp2[7864320]; // xm packed bf16 (hi | lo<<16)
__device__ float g_bc[3840];
__device__ float g_xg[7864320];   // [(b*512+t)*30+k][n]
__device__ float g_adj[900];

__device__ __forceinline__ void band_cfg(int k, int& taps, int& shift, LL& woff){
    if (k <= 5)      { taps=32; shift=5; woff = (LL)k*(16384*32); }
    else if (k <= 14){ taps=16; shift=4; woff = 6LL*(16384*32) + (LL)(k-6)*(16384*16); }
    else             { taps=8;  shift=3; woff = 6LL*(16384*32) + 9LL*(16384*16) + (LL)(k-15)*(16384*8); }
}

__device__ __forceinline__ void split2(float v0, float v1, uint32_t& hi, uint32_t& lo){
    __nv_bfloat16 h0 = __float2bfloat16_rn(v0);
    __nv_bfloat16 h1 = __float2bfloat16_rn(v1);
    float l0 = v0 - __bfloat162float(h0);
    float l1 = v1 - __bfloat162float(h1);
    hi = (uint32_t)__bfloat16_as_ushort(h0) | ((uint32_t)__bfloat16_as_ushort(h1) << 16);
    lo = (uint32_t)__bfloat16_as_ushort(__float2bfloat16_rn(l0))
       | ((uint32_t)__bfloat16_as_ushort(__float2bfloat16_rn(l1)) << 16);
}
__device__ __forceinline__ uint32_t pack1(float v){
    __nv_bfloat16 h = __float2bfloat16_rn(v);
    float l = v - __bfloat162float(h);
    return (uint32_t)__bfloat16_as_ushort(h)
         | ((uint32_t)__bfloat16_as_ushort(__float2bfloat16_rn(l)) << 16);
}

#define MMA_BF16(d, a0,a1,a2,a3, b0,b1) \
    asm volatile("mma.sync.aligned.m16n8k16.row.col.f32.bf16.bf16.f32 " \
        "{%0,%1,%2,%3}, {%4,%5,%6,%7}, {%8,%9}, {%0,%1,%2,%3};" \
        : "+f"((d)[0]), "+f"((d)[1]), "+f"((d)[2]), "+f"((d)[3]) \
        : "r"(a0), "r"(a1), "r"(a2), "r"(a3), "r"(b0), "r"(b1))

__device__ __forceinline__ void ldsm4(uint32_t& r0, uint32_t& r1, uint32_t& r2, uint32_t& r3, uint32_t a){
    asm volatile("ldmatrix.sync.aligned.m8n8.x4.shared.b16 {%0,%1,%2,%3}, [%4];"
        : "=r"(r0), "=r"(r1), "=r"(r2), "=r"(r3) : "r"(a));
}
__device__ __forceinline__ void ldsm4t(uint32_t& r0, uint32_t& r1, uint32_t& r2, uint32_t& r3, uint32_t a){
    asm volatile("ldmatrix.sync.aligned.m8n8.x4.trans.shared.b16 {%0,%1,%2,%3}, [%4];"
        : "=r"(r0), "=r"(r1), "=r"(r2), "=r"(r3) : "r"(a));
}
__device__ __forceinline__ uint32_t s2u(const void* p){
    return (uint32_t)__cvta_generic_to_shared(p);
}

// ------------------------- block reduce (128 thr) ---------------------------
__device__ __forceinline__ float bred(float v, float* sred, int op){
    #pragma unroll
    for (int o = 16; o; o >>= 1){
        float t = __shfl_xor_sync(0xffffffffu, v, o);
        v = (op==0) ? v+t : (op==1) ? fmaxf(v,t) : fminf(v,t);
    }
    if ((threadIdx.x & 31) == 0) sred[threadIdx.x >> 5] = v;
    __syncthreads();
    float r = (op==0) ? (sred[0]+sred[1])+(sred[2]+sred[3])
            : (op==1) ? fmaxf(fmaxf(sred[0],sred[1]),fmaxf(sred[2],sred[3]))
            :           fminf(fminf(sred[0],sred[1]),fminf(sred[2],sred[3]));
    __syncthreads();
    return r;
}

// ------------------------------ transpose x ---------------------------------
__global__ void transpose_x_kernel(const float* __restrict__ x, float* __restrict__ xb){
    __shared__ float s[128*31 + 32];
    int t = blockIdx.x, b = blockIdx.y;
    const float* src = x + (LL)b*1966080 + (LL)t*30;
    for (int i = threadIdx.x; i < 3840; i += 256){
        int n = i / 30, k = i - n*30;
        s[n*31 + k] = src[(LL)n*15360 + k];
    }
    __syncthreads();
    for (int i = threadIdx.x; i < 3840; i += 256){
        int k = i >> 7, n = i & 127;
        xb[((LL)(k*4 + b)*512 + t)*128 + n] = s[n*31 + k];
    }
}

// ---------- pipelined bf16-split GEMM (128x128), conflict-free B -------------
__global__ void __launch_bounds__(256)
mgemm_p(const float* __restrict__ A, const float* __restrict__ A2,
        const float* __restrict__ lam,
        const float* __restrict__ Bm, const float* __restrict__ bias,
        float* __restrict__ C, uint32_t* __restrict__ Cp, int Kd, int inner,
        LL a_o, LL a_i, int lda,
        LL b_o, LL b_i, int ldb,
        LL c_o, LL c_i, int c_m, int c_n,
        int bias_stride, float alpha)
{
    extern __shared__ uint32_t smm[];
    uint32_t* Ah = smm;              // [2][1536]
    uint32_t* Al = smm + 3072;
    uint32_t* Bh = smm + 6144;       // [2][16*68]
    uint32_t* Bl = smm + 6144 + 2176;
    int z = blockIdx.z;
    int ko = z / inner, bi = z - ko*inner;
    const float* Ab  = A + (LL)ko*a_o + (LL)bi*a_i;
    const float* A2b = A2 ? A2 + (LL)ko*a_o + (LL)bi*a_i : nullptr;
    float lamv = lam ? lam[z] : 0.f;
    const float* Bb = Bm + (LL)ko*b_o + (LL)bi*b_i;
    float* Cb = C + (LL)ko*c_o + (LL)bi*c_i;
    uint32_t* Cpb = Cp ? Cp + (LL)ko*c_o + (LL)bi*c_i : nullptr;
    int m0 = blockIdx.y * 128, n0 = blockIdx.x * 128;
    int tid = threadIdx.x, lane = tid & 31, wid = tid >> 5;
    int m0w = (wid >> 2) * 64, n0w = (wid & 3) * 32;
    int lr = lane >> 2, lc = lane & 3;

    float acc[4][4][4];
    #pragma unroll
    for (int i=0;i<4;i++)
        #pragma unroll
        for (int j=0;j<4;j++)
            #pragma unroll
            for (int q=0;q<4;q++) acc[i][j][q]=0.f;

    int am = tid >> 1, ak8 = (tid & 1) * 8;
    int n4 = (tid & 31) * 4, kp = tid >> 5;
    const int NSTEP = Kd >> 4;

    int arow = (lane & 7) + ((lane >> 3) & 1) * 8;
    int akh = lane >> 4;
    uint32_t aAh[4], aAl[4];
    #pragma unroll
    for (int mf = 0; mf < 4; ++mf){
        int row = m0w + mf*16 + arow;
        aAh[mf] = s2u(Ah) + (uint32_t)((row*12 + akh*4)*4);
        aAl[mf] = s2u(Al) + (uint32_t)((row*12 + akh*4)*4);
    }
    int rl = lane & 15;
    uint32_t bwo = (uint32_t)((rl*68 + (n0w >> 1) + ((lane >> 4) << 2)) * 4);
    uint32_t aBh = s2u(Bh) + bwo;
    uint32_t aBl = s2u(Bl) + bwo;

    float va[8];
    float4 rb0, rb1;
    {   // prologue (st = 0)
        const float* ap = Ab + (LL)(m0 + am)*lda + ak8;
        *(float4*)&va[0] = *(const float4*)(ap);
        *(float4*)&va[4] = *(const float4*)(ap + 4);
        if (A2b){
            const float* a2p = A2b + (LL)(m0 + am)*lda + ak8;
            float4 w0 = *(const float4*)(a2p);
            float4 w1 = *(const float4*)(a2p + 4);
            float w[8] = {w0.x,w0.y,w0.z,w0.w,w1.x,w1.y,w1.z,w1.w};
            #pragma unroll
            for (int j=0;j<8;j++) va[j] = fmaf(-lamv, w[j], va[j]);
        }
        const float* bp = Bb + (LL)(kp*2)*ldb + n0 + n4;
        rb0 = *(const float4*)bp;
        rb1 = *(const float4*)(bp + ldb);
    }
    for (int st = 0; st < NSTEP; ++st){
        int buf = (st & 1) * 1536;
        int buf2 = (st & 1) * 1088;
        uint32_t bufb  = (uint32_t)(st & 1) * 6144u;
        uint32_t bufb2 = (uint32_t)(st & 1) * 4352u;
        int basea = buf + am*12 + (tid & 1)*4;
        #pragma unroll
        for (int j=0;j<4;j++){
            uint32_t hi, lo;
            split2(va[2*j], va[2*j+1], hi, lo);
            Ah[basea + j] = hi; Al[basea + j] = lo;
        }
        {
            uint32_t h00,l00,h01,l01,h10,l10,h11,l11;
            split2(rb0.x, rb0.y, h00, l00);
            split2(rb0.z, rb0.w, h01, l01);
            split2(rb1.x, rb1.y, h10, l10);
            split2(rb1.z, rb1.w, h11, l11);
            int r0 = buf2 + (kp*2)*68 + (n4 >> 1);
            *(uint2*)&Bh[r0]      = make_uint2(h00, h01);
            *(uint2*)&Bh[r0 + 68] = make_uint2(h10, h11);
            *(uint2*)&Bl[r0]      = make_uint2(l00, l01);
            *(uint2*)&Bl[r0 + 68] = make_uint2(l10, l11);
        }
        __syncthreads();
        if (st + 1 < NSTEP){
            int c = (st + 1) << 4;
            const float* ap = Ab + (LL)(m0 + am)*lda + c + ak8;
            *(float4*)&va[0] = *(const float4*)(ap);
            *(float4*)&va[4] = *(const float4*)(ap + 4);
            if (A2b){
                const float* a2p = A2b + (LL)(m0 + am)*lda + c + ak8;
                float4 w0 = *(const float4*)(a2p);
                float4 w1 = *(const float4*)(a2p + 4);
                float w[8] = {w0.x,w0.y,w0.z,w0.w,w1.x,w1.y,w1.z,w1.w};
                #pragma unroll
                for (int j=0;j<8;j++) va[j] = fmaf(-lamv, w[j], va[j]);
            }
            const float* bp = Bb + (LL)(c + kp*2)*ldb + n0 + n4;
            rb0 = *(const float4*)bp;
            rb1 = *(const float4*)(bp + ldb);
        }
        uint32_t bh[4][2], bl[4][2];
        ldsm4t(bh[0][0], bh[0][1], bh[1][0], bh[1][1], aBh + bufb2);
        ldsm4t(bh[2][0], bh[2][1], bh[3][0], bh[3][1], aBh + 32u + bufb2);
        ldsm4t(bl[0][0], bl[0][1], bl[1][0], bl[1][1], aBl + bufb2);
        ldsm4t(bl[2][0], bl[2][1], bl[3][0], bl[3][1], aBl + 32u + bufb2);
        #pragma unroll
        for (int mf = 0; mf < 4; ++mf){
            uint32_t ah0,ah1,ah2,ah3, al0,al1,al2,al3;
            ldsm4(ah0,ah1,ah2,ah3, aAh[mf] + bufb);
            ldsm4(al0,al1,al2,al3, aAl[mf] + bufb);
            #pragma unroll
            for (int nf = 0; nf < 4; ++nf){
                MMA_BF16(acc[mf][nf], ah0,ah1,ah2,ah3, bh[nf][0], bh[nf][1]);
                MMA_BF16(acc[mf][nf], ah0,ah1,ah2,ah3, bl[nf][0], bl[nf][1]);
                MMA_BF16(acc[mf][nf], al0,al1,al2,al3, bh[nf][0], bh[nf][1]);
            }
        }
    }
    #pragma unroll
    for (int mf = 0; mf < 4; ++mf){
        int m = m0 + m0w + mf*16 + lr;
        #pragma unroll
        for (int nf = 0; nf < 4; ++nf){
            int n = n0 + n0w + nf*8 + lc*2;
            float b0 = bias ? bias[bias_stride*ko + n]   : 0.f;
            float b1 = bias ? bias[bias_stride*ko + n+1] : 0.f;
            float v00 = fmaf(alpha, acc[mf][nf][0], b0);
            float v01 = fmaf(alpha, acc[mf][nf][1], b1);
            float v10 = fmaf(alpha, acc[mf][nf][2], b0);
            float v11 = fmaf(alpha, acc[mf][nf][3], b1);
            Cb[(LL)m*c_m + (LL)n*c_n]         = v00;
            Cb[(LL)m*c_m + (LL)(n+1)*c_n]     = v01;
            Cb[(LL)(m+8)*c_m + (LL)n*c_n]     = v10;
            Cb[(LL)(m+8)*c_m + (LL)(n+1)*c_n] = v11;
            if (Cpb){
                Cpb[(LL)m*c_m + (LL)n*c_n]         = pack1(v00);
                Cpb[(LL)m*c_m + (LL)(n+1)*c_n]     = pack1(v01);
                Cpb[(LL)(m+8)*c_m + (LL)n*c_n]     = pack1(v10);
                Cpb[(LL)(m+8)*c_m + (LL)(n+1)*c_n] = pack1(v11);
            }
        }
    }
}

// ------- fused triple projection, conflict-free B, ldmatrix ------------------
__global__ void __launch_bounds__(256)
proj3_kernel(const float* __restrict__ A, LL a_z,
             const float* __restrict__ W0, LL wz0,
             const float* __restrict__ W1, LL wz1,
             const float* __restrict__ W2, LL wz2,
             int kodiv,
             const float* __restrict__ b0, const float* __restrict__ b1,
             const float* __restrict__ b2,
             float* __restrict__ C0, LL cz0,
             float* __restrict__ C1, LL cz1,
             float* __restrict__ C2, LL cz2,
             int N2)
{
    extern __shared__ uint32_t smp[];
    uint32_t* Ah = smp;                 // [128][68]
    uint32_t* Al = smp + 8704;
    uint32_t* Bh = smp + 17408;         // [2][16*68]
    uint32_t* Bl = smp + 19584;

    int z = blockIdx.y;
    int ko = z / kodiv;
    int tile = blockIdx.x;
    const float* Ab = A + (LL)z*a_z + (LL)tile*16384;
    int tid = threadIdx.x, lane = tid & 31, wid = tid >> 5;
    int m0w = (wid >> 2) * 64, n0w = (wid & 3) * 32;
    int lr = lane >> 2, lc = lane & 3;

    {
        int am = tid >> 1, koff = (tid & 1) * 64;
        const float* ap = Ab + (LL)am*128 + koff;
        int base = am*68 + (tid & 1)*32;
        #pragma unroll
        for (int g = 0; g < 8; ++g){
            float4 f0 = *(const float4*)(ap + g*8);
            float4 f1 = *(const float4*)(ap + g*8 + 4);
            float v[8] = {f0.x,f0.y,f0.z,f0.w,f1.x,f1.y,f1.z,f1.w};
            #pragma unroll
            for (int j = 0; j < 4; ++j){
                uint32_t hi, lo;
                split2(v[2*j], v[2*j+1], hi, lo);
                Ah[base + g*4 + j] = hi;
                Al[base + g*4 + j] = lo;
            }
        }
    }
    __syncthreads();

    const float* Ws[3] = {W0 + (LL)ko*wz0, W1 + (LL)ko*wz1, W2 + (LL)ko*wz2};
    const float* bs[3] = {b0, b1, b2};
    float* Cs[3];
    Cs[0] = C0 + (LL)z*cz0 + (LL)tile*16384;
    Cs[1] = C1 + (LL)z*cz1 + (LL)tile*16384;
    Cs[2] = C2 + (LL)z*cz2 + (LL)tile*128*N2;
    int Ns[3] = {128, 128, N2};
    int n4 = (tid & 31) * 4, kp = tid >> 5;

    int arow = (lane & 7) + ((lane >> 3) & 1) * 8;
    int akh = lane >> 4;
    uint32_t aAh[4], aAl[4];
    #pragma unroll
    for (int mf = 0; mf < 4; ++mf){
        int row = m0w + mf*16 + arow;
        aAh[mf] = s2u(Ah) + (uint32_t)((row*68 + akh*4)*4);
        aAl[mf] = s2u(Al) + (uint32_t)((row*68 + akh*4)*4);
    }
    int rl = lane & 15;
    uint32_t bwo = (uint32_t)((rl*68 + (n0w >> 1) + ((lane >> 4) << 2)) * 4);
    uint32_t aBh = s2u(Bh) + bwo;
    uint32_t aBl = s2u(Bl) + bwo;

    for (int w = 0; w < 3; ++w){
        const float* Wb = Ws[w];
        int Nw = Ns[w];
        bool act = n4 < Nw;
        float acc[4][4][4];
        #pragma unroll
        for (int i=0;i<4;i++)
            #pragma unroll
            for (int j=0;j<4;j++)
                #pragma unroll
                for (int q=0;q<4;q++) acc[i][j][q]=0.f;

        float4 r0, r1;
        if (act){
            const float* bp0 = Wb + (LL)(kp*2)*Nw + n4;
            r0 = *(const float4*)bp0;
            r1 = *(const float4*)(bp0 + Nw);
        }
        for (int st = 0; st < 8; ++st){
            int buf2 = (st & 1) * 1088;
            uint32_t bufb2 = (uint32_t)(st & 1) * 4352u;
            if (act){
                uint32_t h00,l00,h01,l01,h10,l10,h11,l11;
                split2(r0.x, r0.y, h00, l00);
                split2(r0.z, r0.w, h01, l01);
                split2(r1.x, r1.y, h10, l10);
                split2(r1.z, r1.w, h11, l11);
                int rr = buf2 + (kp*2)*68 + (n4 >> 1);
                *(uint2*)&Bh[rr]      = make_uint2(h00, h01);
                *(uint2*)&Bh[rr + 68] = make_uint2(h10, h11);
                *(uint2*)&Bl[rr]      = make_uint2(l00, l01);
                *(uint2*)&Bl[rr + 68] = make_uint2(l10, l11);
            }
            __syncthreads();
            if (st < 7 && act){
                int c = (st + 1) << 4;
                const float* bp0 = Wb + (LL)(c + kp*2)*Nw + n4;
                r0 = *(const float4*)bp0;
                r1 = *(const float4*)(bp0 + Nw);
            }
            uint32_t bh[4][2], bl[4][2];
            ldsm4t(bh[0][0], bh[0][1], bh[1][0], bh[1][1], aBh + bufb2);
            ldsm4t(bh[2][0], bh[2][1], bh[3][0], bh[3][1], aBh + 32u + bufb2);
            ldsm4t(bl[0][0], bl[0][1], bl[1][0], bl[1][1], aBl + bufb2);
            ldsm4t(bl[2][0], bl[2][1], bl[3][0], bl[3][1], aBl + 32u + bufb2);
            uint32_t stb = (uint32_t)st * 32u;
            #pragma unroll
            for (int mf = 0; mf < 4; ++mf){
                uint32_t ah0,ah1,ah2,ah3, al0,al1,al2,al3;
                ldsm4(ah0,ah1,ah2,ah3, aAh[mf] + stb);
                ldsm4(al0,al1,al2,al3, aAl[mf] + stb);
                #pragma unroll
                for (int nf = 0; nf < 4; ++nf){
                    MMA_BF16(acc[mf][nf], ah0,ah1,ah2,ah3, bh[nf][0], bh[nf][1]);
                    MMA_BF16(acc[mf][nf], ah0,ah1,ah2,ah3, bl[nf][0], bl[nf][1]);
                    MMA_BF16(acc[mf][nf], al0,al1,al2,al3, bh[nf][0], bh[nf][1]);
                }
            }
        }
        const float* bw = bs[w];
        float* Cw = Cs[w];
        __syncthreads();
        #pragma unroll
        for (int mf = 0; mf < 4; ++mf){
            int m = m0w + mf*16 + lr;
            #pragma unroll
            for (int nf = 0; nf < 4; ++nf){
                int n = n0w + nf*8 + lc*2;
                if (n < Nw){
                    float bb0 = bw ? bw[n]   : 0.f;
                    float bb1 = bw ? bw[n+1] : 0.f;
                    Cw[(LL)m*Nw + n]       = acc[mf][nf][0] + bb0;
                    Cw[(LL)m*Nw + n+1]     = acc[mf][nf][1] + bb1;
                    Cw[(LL)(m+8)*Nw + n]   = acc[mf][nf][2] + bb0;
                    Cw[(LL)(m+8)*Nw + n+1] = acc[mf][nf][3] + bb1;
                }
            }
        }
    }
}

// ------------- flash-fused scores + online softmax/stats + AV ----------------
// ldmatrix fragment loads; K/V fragments hoisted out of the mf loop.
__global__ void __launch_bounds__(128)
flash_kernel(const float* __restrict__ qg, const float* __restrict__ kg,
             const float* __restrict__ vg, float* __restrict__ o1,
             float* __restrict__ o2, float* __restrict__ rs)
{
    extern __shared__ uint32_t sm[];
    uint32_t* Qh = sm;              // [128][36]
    uint32_t* Ql = Qh + 4608;
    uint32_t* Kh = Ql + 4608;       // [32][36]
    uint32_t* Kl = Kh + 1152;
    uint32_t* Vh = Kl + 1152;       // [64][20]
    uint32_t* Vl = Vh + 1280;

    int kb = blockIdx.y, half = blockIdx.z;
    int row0 = blockIdx.x * 128;
    const float* qb  = qg + (LL)kb*65536 + half*64;
    const float* kp_ = kg + (LL)kb*65536 + half*64;
    const float* vb  = vg + (LL)kb*32768;
    int tid = threadIdx.x, lane = tid & 31, wid = tid >> 5;
    int m0w = wid * 32;
    int lr = lane >> 2, lc = lane & 3;

    {
        const float* qr = qb + (LL)(row0 + tid)*128;
        #pragma unroll
        for (int g = 0; g < 16; ++g){
            float4 f = *(const float4*)(qr + g*4);
            uint32_t h0,l0,h1,l1;
            split2(f.x, f.y, h0, l0);
            split2(f.z, f.w, h1, l1);
            int p = tid*36 + g*2;
            Qh[p] = h0; Ql[p] = l0; Qh[p+1] = h1; Ql[p+1] = l1;
        }
    }

    // ldmatrix addresses
    int arow = (lane & 7) + ((lane >> 3) & 1) * 8;
    int akh = lane >> 4;
    uint32_t aQh[2], aQl[2];
    #pragma unroll
    for (int mf = 0; mf < 2; ++mf){
        int row = m0w + mf*16 + arow;
        aQh[mf] = s2u(Qh) + (uint32_t)((row*36 + akh*4)*4);
        aQl[mf] = s2u(Ql) + (uint32_t)((row*36 + akh*4)*4);
    }
    int krow = (lane & 7) + ((lane >> 4) & 1) * 8;
    int kcl  = ((lane >> 3) & 1) * 4;
    uint32_t aKh = s2u(Kh) + (uint32_t)((krow*36 + kcl)*4);
    uint32_t aKl = s2u(Kl) + (uint32_t)((krow*36 + kcl)*4);
    uint32_t aVh = s2u(Vh) + (uint32_t)((krow*20 + kcl)*4);
    uint32_t aVl = s2u(Vl) + (uint32_t)((krow*20 + kcl)*4);

    float m2[2][2], dn[2][2], qq[2][2], vmn[2][2];
    #pragma unroll
    for (int a=0;a<2;a++)
        #pragma unroll
        for (int b2=0;b2<2;b2++){ m2[a][b2]=-1e30f; dn[a][b2]=0.f; qq[a][b2]=0.f; vmn[a][b2]=1e30f; }
    float o[2][8][4];
    #pragma unroll
    for (int a=0;a<2;a++)
        #pragma unroll
        for (int b2=0;b2<8;b2++)
            #pragma unroll
            for (int cql=0;cql<4;cql++) o[a][b2][cql]=0.f;

    for (int jt = 0; jt < 512; jt += 32){
        __syncthreads();
        {
            int j = tid >> 2, ds = (tid & 3) * 16;
            const float* kr = kp_ + (LL)(jt + j)*128 + ds;
            #pragma unroll
            for (int g = 0; g < 4; ++g){
                float4 f = *(const float4*)(kr + g*4);
                uint32_t h0,l0,h1,l1;
                split2(f.x,f.y,h0,l0); split2(f.z,f.w,h1,l1);
                int p = j*36 + (ds>>1) + g*2;
                Kh[p]=h0; Kl[p]=l0; Kh[p+1]=h1; Kl[p+1]=l1;
            }
        }
        {
            int jp = tid & 15, ds = (tid >> 4) * 8;
            const float* v0 = vb + (LL)(jt + jp*2)*64 + ds;
            #pragma unroll
            for (int g = 0; g < 8; ++g){
                uint32_t h,l;
                split2(v0[g], v0[64+g], h, l);
                Vh[(ds+g)*20 + jp] = h; Vl[(ds+g)*20 + jp] = l;
            }
        }
        __syncthreads();
        // ---- scores 32x32 per warp (ldmatrix fragments) ----
        float s[2][4][4];
        #pragma unroll
        for (int a=0;a<2;a++)
            #pragma unroll
            for (int b2=0;b2<4;b2++)
                #pragma unroll
                for (int cql=0;cql<4;cql++) s[a][b2][cql]=0.f;
        #pragma unroll
        for (int kc = 0; kc < 4; ++kc){
            uint32_t off = (uint32_t)kc * 32u;
            uint32_t bh[4][2], bl[4][2];
            ldsm4(bh[0][0], bh[0][1], bh[1][0], bh[1][1], aKh + off);
            ldsm4(bh[2][0], bh[2][1], bh[3][0], bh[3][1], aKh + 2304u + off);  // +16 rows*36*4
            ldsm4(bl[0][0], bl[0][1], bl[1][0], bl[1][1], aKl + off);
            ldsm4(bl[2][0], bl[2][1], bl[3][0], bl[3][1], aKl + 2304u + off);
            #pragma unroll
            for (int mf = 0; mf < 2; ++mf){
                uint32_t ah0,ah1,ah2,ah3, al0,al1,al2,al3;
                ldsm4(ah0,ah1,ah2,ah3, aQh[mf] + off);
                ldsm4(al0,al1,al2,al3, aQl[mf] + off);
                #pragma unroll
                for (int nf = 0; nf < 4; ++nf){
                    MMA_BF16(s[mf][nf], ah0,ah1,ah2,ah3, bh[nf][0], bh[nf][1]);
                    MMA_BF16(s[mf][nf], ah0,ah1,ah2,ah3, bl[nf][0], bl[nf][1]);
                    MMA_BF16(s[mf][nf], al0,al1,al2,al3, bh[nf][0], bh[nf][1]);
                }
            }
        }
        // ---- online softmax update (alpha=0.25), ballot-gated rescale ----
        #pragma unroll
        for (int mf = 0; mf < 2; ++mf){
            #pragma unroll
            for (int rh = 0; rh < 2; ++rh){
                float cmax = -1e30f, cmin = 1e30f;
                #pragma unroll
                for (int nf = 0; nf < 4; ++nf){
                    float e0 = s[mf][nf][rh*2]   * 0.25f;
                    float e1 = s[mf][nf][rh*2+1] * 0.25f;
                    s[mf][nf][rh*2] = e0; s[mf][nf][rh*2+1] = e1;
                    cmax = fmaxf(cmax, fmaxf(e0,e1));
                    cmin = fminf(cmin, fminf(e0,e1));
                }
                cmax = fmaxf(cmax, __shfl_xor_sync(0xffffffffu, cmax, 1));
                cmax = fmaxf(cmax, __shfl_xor_sync(0xffffffffu, cmax, 2));
                cmin = fminf(cmin, __shfl_xor_sync(0xffffffffu, cmin, 1));
                cmin = fminf(cmin, __shfl_xor_sync(0xffffffffu, cmin, 2));
                float mold = m2[mf][rh];
                float mnew = fmaxf(mold, cmax);
                bool upd = (mnew > mold);
                float rsum = 0.f, rsq = 0.f;
                #pragma unroll
                for (int nf = 0; nf < 4; ++nf){
                    float p0 = __expf(s[mf][nf][rh*2]   - mnew);
                    float p1 = __expf(s[mf][nf][rh*2+1] - mnew);
                    s[mf][nf][rh*2] = p0; s[mf][nf][rh*2+1] = p1;
                    rsum += p0 + p1;
                    rsq  += p0*p0 + p1*p1;
                }
                rsum += __shfl_xor_sync(0xffffffffu, rsum, 1);
                rsum += __shfl_xor_sync(0xffffffffu, rsum, 2);
                rsq  += __shfl_xor_sync(0xffffffffu, rsq, 1);
                rsq  += __shfl_xor_sync(0xffffffffu, rsq, 2);
                if (__any_sync(0xffffffffu, upd)){
                    float scale = __expf(mold - mnew);
                    dn[mf][rh] = dn[mf][rh]*scale + rsum;
                    qq[mf][rh] = qq[mf][rh]*scale*scale + rsq;
                    m2[mf][rh] = mnew;
                    #pragma unroll
                    for (int nfd = 0; nfd < 8; ++nfd){
                        o[mf][nfd][rh*2]   *= scale;
                        o[mf][nfd][rh*2+1] *= scale;
                    }
                } else {
                    dn[mf][rh] += rsum;
                    qq[mf][rh] += rsq;
                }
                vmn[mf][rh] = fminf(vmn[mf][rh], cmin);
            }
        }
        // ---- AV: P (register frags) @ V, V via ldmatrix ----
        #pragma unroll
        for (int kc2 = 0; kc2 < 2; ++kc2){
            uint32_t off = (uint32_t)kc2 * 32u;
            uint32_t vh[4][4], vl[4][4];
            #pragma unroll
            for (int p = 0; p < 4; ++p){
                ldsm4(vh[p][0], vh[p][1], vh[p][2], vh[p][3], aVh + (uint32_t)p*1280u + off);
                ldsm4(vl[p][0], vl[p][1], vl[p][2], vl[p][3], aVl + (uint32_t)p*1280u + off);
            }
            #pragma unroll
            for (int mf = 0; mf < 2; ++mf){
                uint32_t ah0,al0,ah1,al1,ah2,al2,ah3,al3;
                split2(s[mf][2*kc2][0],   s[mf][2*kc2][1],   ah0, al0);
                split2(s[mf][2*kc2][2],   s[mf][2*kc2][3],   ah1, al1);
                split2(s[mf][2*kc2+1][0], s[mf][2*kc2+1][1], ah2, al2);
                split2(s[mf][2*kc2+1][2], s[mf][2*kc2+1][3], ah3, al3);
                #pragma unroll
                for (int nfd = 0; nfd < 8; ++nfd){
                    int p = nfd >> 1, ix = (nfd & 1) * 2;
                    uint32_t bh0 = vh[p][ix], bh1 = vh[p][ix+1];
                    uint32_t bl0 = vl[p][ix], bl1 = vl[p][ix+1];
                    MMA_BF16(o[mf][nfd], ah0,ah1,ah2,ah3, bh0,bh1);
                    MMA_BF16(o[mf][nfd], ah0,ah1,ah2,ah3, bl0,bl1);
                    MMA_BF16(o[mf][nfd], al0,al1,al2,al3, bh0,bh1);
                }
            }
        }
    }
    float* op = (half == 0 ? o1 : o2) + (LL)kb*32768;
    #pragma unroll
    for (int mf = 0; mf < 2; ++mf){
        #pragma unroll
        for (int rh = 0; rh < 2; ++rh){
            float inv = 1.f / dn[mf][rh];
            int r = row0 + m0w + mf*16 + lr + rh*8;
            #pragma unroll
            for (int nfd = 0; nfd < 8; ++nfd){
                o[mf][nfd][rh*2]   *= inv;
                o[mf][nfd][rh*2+1] *= inv;
            }
            if (lc == 0){
                float* rp = rs + ((LL)(half*120 + kb)*512 + r)*4;
                rp[0] = 1.0f;
                rp[1] = qq[mf][rh]*inv*inv;
                rp[2] = inv;
                rp[3] = __expf(vmn[mf][rh] - m2[mf][rh]) * inv;
            }
            float* orow = op + (LL)r*64 + lc*2;
            #pragma unroll
            for (int nfd = 0; nfd < 8; ++nfd){
                orow[nfd*8]   = o[mf][nfd][rh*2];
                orow[nfd*8+1] = o[mf][nfd][rh*2+1];
            }
        }
    }
}

// --------------------- per-(half,kb) stat aggregation ------------------------
__global__ void stats_finalize_kernel(const float* __restrict__ rs, float* __restrict__ st){
    __shared__ float sred[4];
    int hb = blockIdx.x;
    const float* r = rs + (LL)hb*512*4;
    int tid = threadIdx.x;
    float s=0.f,q=0.f,mx=-1e30f,mn=1e30f;
    for (int i = tid; i < 512; i += 128){
        s += r[i*4+0]; q += r[i*4+1];
        mx = fmaxf(mx, r[i*4+2]); mn = fminf(mn, r[i*4+3]);
    }
    s = bred(s,sred,0); q = bred(q,sred,0);
    mx = bred(mx,sred,1); mn = bred(mn,sred,2);
    if (tid == 0){
        float* o = st + hb*4;
        o[0]=s; o[1]=q; o[2]=mx; o[3]=mn;
    }
}

// ------------------------------- lambda MLP ---------------------------------
__global__ void lambda_kernel(const float* __restrict__ st,
                              const float* __restrict__ lw1, const float* __restrict__ lb1,
                              const float* __restrict__ lw2, const float* __restrict__ lb2,
                              float* __restrict__ lam){
    int kb = threadIdx.x;
    if (kb >= 120) return;
    int k = kb >> 2;
    const float M2 = 262144.f;
    float s8[8];
    #pragma unroll
    for (int h2 = 0; h2 < 2; ++h2){
        const float* sp = st + (h2*120 + kb)*4;
        float sum = sp[0], sq = sp[1];
        s8[h2*4+0] = sum / M2;
        float var = (sq - sum*sum/M2) / (M2 - 1.f);
        s8[h2*4+1] = sqrtf(fmaxf(var, 0.f));
        s8[h2*4+2] = sp[2];
        s8[h2*4+3] = sp[3];
    }
    float z = lb2[k];
    for (int o = 0; o < 16; ++o){
        float h = lb1[k*16+o];
        #pragma unroll
        for (int i = 0; i < 8; ++i) h = fmaf(s8[i], lw1[(k*8+i)*16+o], h);
        h = fmaxf(h, 0.f);
        z = fmaf(h, lw2[k*16+o], z);
    }
    lam[kb] = 1.f/(1.f + expf(-z));
}

// ------------- combined multiscale conv weights -> packed bf16 hi/lo ---------
__global__ void combine_wc_kernel(const float* __restrict__ fw,
    const float* cwA, const float* cwB, const float* cwC, const float* cwD, const float* cwE,
    const float* cbA, const float* cbB, const float* cbC, const float* cbD, const float* cbE,
    uint32_t* __restrict__ wch, uint32_t* __restrict__ wcl, float* __restrict__ bc){
    int idx = blockIdx.x*256 + threadIdx.x;
    if (idx >= 491520) return;
    int k = idx >> 14;
    int rem = idx & 16383;
    int n = rem >> 7, m = rem & 127;
    int base = (k <= 5) ? 2 : (k <= 14) ? 1 : 0;
    int taps, shift; LL woff;
    band_cfg(k, taps, shift, woff);
    int half = taps >> 1;
    float f0 = fw[k*3+0], f1 = fw[k*3+1], f2 = fw[k*3+2];
    float fm = fmaxf(f0, fmaxf(f1, f2));
    float e0 = expf(f0-fm), e1 = expf(f1-fm), e2 = expf(f2-fm);
    float den = e0+e1+e2;
    float sw[3] = {e0/den, e1/den, e2/den};
    const float* cws[5] = {cwA,cwB,cwC,cwD,cwE};
    const float* cbs[5] = {cbA,cbB,cbC,cbD,cbE};
    const int ss[5] = {2,4,8,16,32};
    LL wp = woff >> 1;
    float prev = 0.f;
    for (int u = 0; u < taps; ++u){
        int tau = u - half;
        float a = 0.f;
        #pragma unroll
        for (int j = 0; j < 3; ++j){
            int slot = base + j;
            int sc = ss[slot], h2 = sc >> 1;
            if (tau >= -h2 && tau < h2)
                a = fmaf(sw[j], cws[slot][((LL)n*128 + m)*sc + tau + h2], a);
        }
        if ((u & 1) == 0) prev = a;
        else {
            uint32_t hi, lo;
            split2(prev, a, hi, lo);
            int kk = m*taps + u - 1;
            int stp = kk >> 4;
            int kp = (kk >> 1) & 7;
            LL widx = wp + (LL)stp*1024 + n*8 + kp;
            wch[widx] = hi; wcl[widx] = lo;
        }
    }
    if (m == 0){
        float bcv = 0.f;
        #pragma unroll
        for (int j = 0; j < 3; ++j) bcv = fmaf(sw[j], cbs[base+j][n], bcv);
        bc[k*128+n] = bcv;
    }
}

// -------- pipelined mma.sync bf16 conv (ldmatrix fragments) ------------------
__global__ void __launch_bounds__(256)
convgemm_mma(const uint32_t* __restrict__ wch, const uint32_t* __restrict__ wcl,
             const float* __restrict__ bc, const uint32_t* __restrict__ xp2,
             float* __restrict__ xg)
{
    extern __shared__ uint32_t smc[];
    uint32_t* Ah = smc;            // [2][1536]
    uint32_t* Al = smc + 3072;
    uint32_t* Bh = smc + 6144;
    uint32_t* Bl = smc + 9216;
    int z = (int)((blockIdx.y * 49u) % 120u);
    int b = z / 30, k = z - b*30;
    int taps, shift; LL woff;
    band_cfg(k, taps, shift, woff);
    const int NC = taps << 3;
    const int half = taps >> 1;
    const int mask = taps - 1;
    const uint32_t* Abh = wch + (woff >> 1);
    const uint32_t* Abl = wcl + (woff >> 1);
    const uint32_t* xpz = xp2 + (LL)z*65536;
    int t0 = blockIdx.x * 128;
    int tid = threadIdx.x;
    int lane = tid & 31, wid = tid >> 5;
    int m0w = (wid >> 2) * 64, n0w = (wid & 3) * 32;
    int lr = lane >> 2, lc = lane & 3;

    float acc[4][4][4];
    #pragma unroll
    for (int i=0;i<4;i++)
        #pragma unroll
        for (int j=0;j<4;j++)
            #pragma unroll
            for (int q=0;q<4;q++) acc[i][j][q]=0.f;

    int am = tid >> 1, akp = (tid & 1) * 4;
    int bkp = tid & 7, btq = tid >> 3;

    int arow = (lane & 7) + ((lane >> 3) & 1) * 8;
    int akh = lane >> 4;
    uint32_t aAh[4], aAl[4];
    #pragma unroll
    for (int mf = 0; mf < 4; ++mf){
        int row = m0w + mf*16 + arow;
        aAh[mf] = s2u(Ah) + (uint32_t)((row*12 + akh*4)*4);
        aAl[mf] = s2u(Al) + (uint32_t)((row*12 + akh*4)*4);
    }
    int brow = n0w + (lane >> 4)*8 + (lane & 7);
    int bkh = (lane >> 3) & 1;
    uint32_t aBh = s2u(Bh) + (uint32_t)((brow*12 + bkh*4)*4);
    uint32_t aBl = s2u(Bl) + (uint32_t)((brow*12 + bkh*4)*4);

    uint4 a4h, a4l;
    uint32_t bhv[4], blv[4];
    {
        a4h = *(const uint4*)(Abh + tid*4);
        a4l = *(const uint4*)(Abl + tid*4);
        int kk = bkp*2;
        int mi = kk >> shift, u0 = kk & mask;
        const uint32_t* src = xpz + (LL)mi*512;
        int off = u0 - half;
        #pragma unroll
        for (int i = 0; i < 4; ++i){
            int t = btq*4 + i;
            int p0 = t0 + t + off;
            uint32_t w0 = ((unsigned)p0 < 512u) ? src[p0] : 0u;
            uint32_t w1 = ((unsigned)(p0+1) < 512u) ? src[p0+1] : 0u;
            bhv[i] = __byte_perm(w0, w1, 0x5410);
            blv[i] = __byte_perm(w0, w1, 0x7632);
        }
    }
    for (int st = 0; st < NC; ++st){
        int buf = (st & 1) * 1536;
        uint32_t bufb = (uint32_t)(st & 1) * 6144u;
        *(uint4*)&Ah[buf + am*12 + akp] = a4h;
        *(uint4*)&Al[buf + am*12 + akp] = a4l;
        #pragma unroll
        for (int i = 0; i < 4; ++i){
            int t = btq*4 + i;
            Bh[buf + t*12 + bkp] = bhv[i];
            Bl[buf + t*12 + bkp] = blv[i];
        }
        __syncthreads();
        if (st + 1 < NC){
            int stn = st + 1;
            a4h = *(const uint4*)(Abh + (LL)stn*1024 + tid*4);
            a4l = *(const uint4*)(Abl + (LL)stn*1024 + tid*4);
            int kk = (stn << 4) + bkp*2;
            int mi = kk >> shift, u0 = kk & mask;
            const uint32_t* src = xpz + (LL)mi*512;
            int off = u0 - half;
            #pragma unroll
            for (int i = 0; i < 4; ++i){
                int t = btq*4 + i;
                int p0 = t0 + t + off;
                uint32_t w0 = ((unsigned)p0 < 512u) ? src[p0] : 0u;
                uint32_t w1 = ((unsigned)(p0+1) < 512u) ? src[p0+1] : 0u;
                bhv[i] = __byte_perm(w0, w1, 0x5410);
                blv[i] = __byte_perm(w0, w1, 0x7632);
            }
        }
        uint32_t bh[4][2], bl[4][2];
        ldsm4(bh[0][0], bh[0][1], bh[1][0], bh[1][1], aBh + bufb);
        ldsm4(bh[2][0], bh[2][1], bh[3][0], bh[3][1], aBh + 768u + bufb);
        ldsm4(bl[0][0], bl[0][1], bl[1][0], bl[1][1], aBl + bufb);
        ldsm4(bl[2][0], bl[2][1], bl[3][0], bl[3][1], aBl + 768u + bufb);
        #pragma unroll
        for (int mf = 0; mf < 4; ++mf){
            uint32_t ah0,ah1,ah2,ah3, al0,al1,al2,al3;
            ldsm4(ah0,ah1,ah2,ah3, aAh[mf] + bufb);
            ldsm4(al0,al1,al2,al3, aAl[mf] + bufb);
            #pragma unroll
            for (int nf = 0; nf < 4; ++nf){
                MMA_BF16(acc[mf][nf], ah0,ah1,ah2,ah3, bh[nf][0], bh[nf][1]);
                MMA_BF16(acc[mf][nf], ah0,ah1,ah2,ah3, bl[nf][0], bl[nf][1]);
                MMA_BF16(acc[mf][nf], al0,al1,al2,al3, bh[nf][0], bh[nf][1]);
            }
        }
    }
    #pragma unroll
    for (int mf = 0; mf < 4; ++mf){
        int m = m0w + mf*16 + lr;
        float bc0 = bc[k*128 + m];
        float bc1 = bc[k*128 + m + 8];
        #pragma unroll
        for (int nf = 0; nf < 4; ++nf){
            int t = t0 + n0w + nf*8 + lc*2;
            LL base = ((LL)((b*512 + t)*30 + k)) * 128;
            xg[base + m]          = acc[mf][nf][0] + bc0;
            xg[base + 3840 + m]   = acc[mf][nf][1] + bc0;
            xg[base + m + 8]      = acc[mf][nf][2] + bc1;
            xg[base + 3840 + m+8] = acc[mf][nf][3] + bc1;
        }
    }
}

// ------------------------------- adjacency ----------------------------------
__global__ void adj_kernel(const float* __restrict__ be, float* __restrict__ adj){
    __shared__ float e[30][64];
    __shared__ float sim[30][30];
    __shared__ float Ar[30][30];
    int tid = threadIdx.x;
    for (int i = tid; i < 30; i += 256){
        float s = 0.f;
        for (int d = 0; d < 64; ++d){ float v = be[i*64+d]; s += v*v; }
        float inv = 1.f/(sqrtf(s)+1e-8f);
        for (int d = 0; d < 64; ++d) e[i][d] = be[i*64+d]*inv;
    }
    __syncthreads();
    for (int p = tid; p < 900; p += 256){
        int i = p/30, j = p - (p/30)*30;
        float s = 0.f;
        for (int d = 0; d < 64; ++d) s = fmaf(e[i][d], e[j][d], s);
        sim[i][j] = s; Ar[i][j] = 0.f;
    }
    __syncthreads();
    if (tid < 30){
        bool taken[30];
        for (int j = 0; j < 30; ++j) taken[j] = false;
        for (int r = 0; r < 5; ++r){
            int bi = 0; float bvv = -1e30f;
            for (int j = 0; j < 30; ++j)
                if (!taken[j] && sim[tid][j] > bvv){ bvv = sim[tid][j]; bi = j; }
            taken[bi] = true;
            Ar[tid][bi] = bvv;
        }
    }
    __syncthreads();
    for (int p = tid; p < 900; p += 256){
        int i = p/30, j = p - (p/30)*30;
        adj[p] = 0.5f*(Ar[i][j] + Ar[j][i]);
    }
}

// --------------------------- graph attention core ---------------------------
__global__ void gattn_kernel(const float* __restrict__ qg, const float* __restrict__ kg,
                             const float* __restrict__ vg, const float* __restrict__ adj,
                             float* __restrict__ outp){
    __shared__ float sq[4][30][32];
    __shared__ float sv[4][30][32];
    __shared__ float sadj[30][30];
    __shared__ float sat[4][32];
    LL m = blockIdx.x;
    int tid = threadIdx.x, h = tid >> 5, lane = tid & 31;
    for (int i = tid; i < 3840; i += 128){
        int r = i >> 7, c = i & 127;
        sq[c>>5][r][c&31] = qg[m*3840 + i];
        sv[c>>5][r][c&31] = vg[m*3840 + i];
    }
    for (int i = tid; i < 900; i += 128) sadj[i/30][i - (i/30)*30] = adj[i];
    float kreg[32];
    if (lane < 30){
        #pragma unroll
        for (int d = 0; d < 32; ++d) kreg[d] = kg[m*3840 + lane*128 + h*32 + d];
    } else {
        #pragma unroll
        for (int d = 0; d < 32; ++d) kreg[d] = 0.f;
    }
    __syncthreads();
    const float invs = 0.17677669529663687f;
    float* orow = outp + m*3840;
    for (int i = 0; i < 30; ++i){
        float qv = sq[h][i][lane];
        float d = 0.f;
        #pragma unroll
        for (int dd = 0; dd < 32; ++dd)
            d = fmaf(__shfl_sync(0xffffffffu, qv, dd), kreg[dd], d);
        bool valid = (lane < 30) && (sadj[i][lane] != 0.f);
        float sc = valid ? d*invs : -1e30f;
        float mx = sc;
        #pragma unroll
        for (int o=16;o;o>>=1) mx = fmaxf(mx, __shfl_xor_sync(0xffffffffu, mx, o));
        float e = valid ? expf(sc - mx) : 0.f;
        float s = e;
        #pragma unroll
        for (int o=16;o;o>>=1) s += __shfl_xor_sync(0xffffffffu, s, o);
        float at = (s > 0.f) ? e/s : 0.f;
        sat[h][lane] = at;
        __syncwarp();
        float o = 0.f;
        for (int j = 0; j < 30; ++j) o = fmaf(sat[h][j], sv[h][j][lane], o);
        orow[i*128 + h*32 + lane] = o;
        __syncwarp();
    }
}

// ------------------------------ output transpose -----------------------------
__global__ void transpose_out_kernel(const float* __restrict__ og, float* __restrict__ out){
    __shared__ float s[30*129 + 32];
    int t = blockIdx.x, b = blockIdx.y;
    const float* src = og + (LL)(b*512 + t)*3840;
    for (int i = threadIdx.x; i < 3840; i += 256){
        int k = i >> 7, n = i & 127;
        s[k*129 + n] = src[i];
    }
    __syncthreads();
    float* dst = out + (LL)b*1966080 + (LL)t*30;
    for (int i = threadIdx.x; i < 3840; i += 256){
        int n = i / 30, k = i - n*30;
        dst[(LL)n*15360 + k] = s[k*129 + n];
    }
}

// ----------------------------------- launch ----------------------------------
extern "C" void kernel_launch(void* const* d_in, const int* in_sizes, int n_in,
                              void* d_out, int out_size) {
    const float* x   = (const float*)d_in[0];
    const float* Wq  = (const float*)d_in[1];
    const float* Wk  = (const float*)d_in[2];
    const float* Wv  = (const float*)d_in[3];
    const float* Wo  = (const float*)d_in[4];
    const float* bo  = (const float*)d_in[5];
    const float* lw1 = (const float*)d_in[6];
    const float* lb1 = (const float*)d_in[7];
    const float* lw2 = (const float*)d_in[8];
    const float* lb2 = (const float*)d_in[9];
    const float* cw2 = (const float*)d_in[10];
    const float* cb2 = (const float*)d_in[11];
    const float* cw4 = (const float*)d_in[12];
    const float* cb4 = (const float*)d_in[13];
    const float* cw8 = (const float*)d_in[14];
    const float* cb8 = (const float*)d_in[15];
    const float* cw16= (const float*)d_in[16];
    const float* cb16= (const float*)d_in[17];
    const float* cw32= (const float*)d_in[18];
    const float* cb32= (const float*)d_in[19];
    const float* fw  = (const float*)d_in[20];
    const float* be  = (const float*)d_in[21];
    const float* gWq = (const float*)d_in[22];
    const float* gbq = (const float*)d_in[23];
    const float* gWk = (const float*)d_in[24];
    const float* gbk = (const float*)d_in[25];
    const float* gWv = (const float*)d_in[26];
    const float* gbv = (const float*)d_in[27];
    const float* gWo = (const float*)d_in[28];
    const float* gbo = (const float*)d_in[29];
    float* out = (float*)d_out;

    void *xb,*q,*k_,*v,*S,*rs,*st,*lam,*xm,*wch,*wcl,*xp2,*bc,*xg,*adj;
    cudaGetSymbolAddress(&xb, g_xb);  cudaGetSymbolAddress(&q,  g_q);
    cudaGetSymbolAddress(&k_, g_k);   cudaGetSymbolAddress(&v,  g_v);
    cudaGetSymbolAddress(&S,  g_S);   cudaGetSymbolAddress(&rs, g_rs);
    cudaGetSymbolAddress(&st, g_st);  cudaGetSymbolAddress(&lam,g_lam);
    cudaGetSymbolAddress(&xm, g_xm);
    cudaGetSymbolAddress(&wch,g_wch); cudaGetSymbolAddress(&wcl,g_wcl);
    cudaGetSymbolAddress(&xp2,g_xp2); cudaGetSymbolAddress(&bc, g_bc);
    cudaGetSymbolAddress(&xg, g_xg);  cudaGetSymbolAddress(&adj,g_adj);

    float* o1 = (float*)S;
    float* o2 = (float*)S + 3932160;

    cudaFuncSetAttribute(flash_kernel, cudaFuncAttributeMaxDynamicSharedMemorySize, 57344);
    cudaFuncSetAttribute(proj3_kernel, cudaFuncAttributeMaxDynamicSharedMemorySize, 87040);
    cudaFuncSetAttribute(mgemm_p, cudaFuncAttributeMaxDynamicSharedMemorySize, 49152);
    cudaFuncSetAttribute(convgemm_mma, cudaFuncAttributeMaxDynamicSharedMemorySize, 49152);

    transpose_x_kernel<<<dim3(512,4), 256>>>(x, (float*)xb);
    combine_wc_kernel<<<1920, 256>>>(fw, cw2,cw4,cw8,cw16,cw32,
                                     cb2,cb4,cb8,cb16,cb32,
                                     (uint32_t*)wch, (uint32_t*)wcl, (float*)bc);
    adj_kernel<<<1, 256>>>(be, (float*)adj);

    proj3_kernel<<<dim3(4,120), 256, 87040>>>((const float*)xb, 65536LL,
        Wq, 16384LL, Wk, 16384LL, Wv, 8192LL, 4,
        nullptr, nullptr, nullptr,
        (float*)q, 65536LL, (float*)k_, 65536LL, (float*)v, 32768LL, 64);

    flash_kernel<<<dim3(4,120,2), 128, 57344>>>((const float*)q, (const float*)k_,
                                                (const float*)v, o1, o2, (float*)rs);

    stats_finalize_kernel<<<240,128>>>((const float*)rs, (float*)st);
    lambda_kernel<<<1,128>>>((const float*)st, lw1, lb1, lw2, lb2, (float*)lam);

    mgemm_p<<<dim3(1,4,120),256,41984>>>(o1, o2, (const float*)lam, Wo, bo,
        (float*)xm, (uint32_t*)xp2, 64, 4, 131072LL, 32768LL, 64,
        8192LL, 0LL, 128, 65536LL, 1966080LL, 1, 512, 128, 1.f);

    convgemm_mma<<<dim3(4,120), 256, 49152>>>((const uint32_t*)wch, (const uint32_t*)wcl,
                                              (const float*)bc, (const uint32_t*)xp2, (float*)xg);

    proj3_kernel<<<dim3(480,1), 256, 87040>>>((const float*)xg, 0LL,
        gWq, 0LL, gWk, 0LL, gWv, 0LL, 1,
        gbq, gbk, gbv,
        (float*)q, 0LL, (float*)k_, 0LL, (float*)xb, 0LL, 128);

    gattn_kernel<<<2048,128>>>((const float*)q, (const float*)k_, (const float*)xb,
                               (const float*)adj, (float*)xg);

    mgemm_p<<<dim3(1,480,1),256,41984>>>((const float*)xg, nullptr, nullptr, gWo, gbo,
        (float*)xm, nullptr, 128, 1, 0LL, 0LL, 128,
        0LL, 0LL, 128, 0LL, 0LL, 128, 1, 0, 1.f);

    transpose_out_kernel<<<dim3(512,4),256>>>((const float*)xm, out);
}